// round 5
// baseline (speedup 1.0000x reference)
#include <cuda_runtime.h>
#include <cuda_fp16.h>
#include <math.h>

// ---------------- problem constants ----------------
#define BB   16
#define SS   512
#define DD   512
#define LL   4
#define HH   8
#define QKD  256      // D/2
#define VV   512
#define FF   1408
#define RR   (BB*SS)      // 8192 rows
#define DQK  32
#define DV   64
#define EPS_RMS 1e-6f
#define EPS_BN  1e-5f
#define CAPV 15.0f

// weight half-buffer offsets (element counts, all layers concatenated)
#define OFF_WQ   0L
#define OFF_WK   524288L
#define OFF_WV   1048576L
#define OFF_WOG  2097152L
#define OFF_WOUT 3145728L
#define OFF_WG   4194304L
#define OFF_WU   7077888L
#define OFF_WD   9961472L
#define TOTW     12845056L

// ---------------- device scratch ----------------
__device__ float g_xn [RR*DD];
__device__ float g_h  [RR*DD];
__device__ float g_q  [RR*QKD];
__device__ float g_k  [RR*QKD];
__device__ float g_v  [RR*VV];
__device__ float g_og [RR*VV];
__device__ float g_ht [RR*VV];
__device__ float g_ig [BB*HH*SS];
__device__ float g_fg [BB*HH*SS];
__device__ float g_bc [BB*HH*SS];
__device__ float g_mv [BB*HH*SS];
__device__ float g_gu1[RR*FF];
__device__ float g_part[64*1024];
__device__ float g_stats[1024];
__device__ float g_last[BB*DD];
__device__ float g_o1 [BB*256];
__device__ float g_o2 [BB];

__device__ __half g_wh  [TOTW];      // fp16 weights
__device__ __half g_yh  [RR*DD];     // fp16 rms-normed activations
__device__ __half g_hth [RR*VV];     // fp16 headnorm output
__device__ __half g_g1h [RR*FF];     // fp16 silu(g)*u

__device__ __forceinline__ float softcapf(float x){ return CAPV * tanhf(x * (1.0f/CAPV)); }
__device__ __forceinline__ float logsigf(float x){ return fminf(x,0.f) - log1pf(expf(-fabsf(x))); }

__device__ __forceinline__ void cp16(void* smem_dst, const void* gsrc){
    unsigned s = (unsigned)__cvta_generic_to_shared(smem_dst);
    asm volatile("cp.async.cg.shared.global [%0], [%1], 16;" :: "r"(s), "l"(gsrc));
}
__device__ __forceinline__ void cp_commit(){ asm volatile("cp.async.commit_group;" ::: "memory"); }
template<int NN> __device__ __forceinline__ void cp_wait(){ asm volatile("cp.async.wait_group %0;" :: "n"(NN) : "memory"); }

__device__ __forceinline__ void mma_f16(float* c, const unsigned* a, const unsigned* b){
    asm volatile("mma.sync.aligned.m16n8k16.row.col.f32.f16.f16.f32 "
        "{%0,%1,%2,%3}, {%4,%5,%6,%7}, {%8,%9}, {%0,%1,%2,%3};"
        : "+f"(c[0]), "+f"(c[1]), "+f"(c[2]), "+f"(c[3])
        : "r"(a[0]), "r"(a[1]), "r"(a[2]), "r"(a[3]), "r"(b[0]), "r"(b[1]));
}
__device__ __forceinline__ void ldsm4(unsigned& r0, unsigned& r1, unsigned& r2, unsigned& r3, unsigned addr){
    asm volatile("ldmatrix.sync.aligned.m8n8.x4.shared.b16 {%0,%1,%2,%3}, [%4];"
        : "=r"(r0), "=r"(r1), "=r"(r2), "=r"(r3) : "r"(addr));
}
__device__ __forceinline__ void ldsm4t(unsigned& r0, unsigned& r1, unsigned& r2, unsigned& r3, unsigned addr){
    asm volatile("ldmatrix.sync.aligned.m8n8.x4.trans.shared.b16 {%0,%1,%2,%3}, [%4];"
        : "=r"(r0), "=r"(r1), "=r"(r2), "=r"(r3) : "r"(addr));
}

// ---------------- bn partial + weight fp32->fp16 conversion (fused launch) ----
__global__ void bnpart_conv_kernel(const float* __restrict__ x,
        const float* __restrict__ Wq, const float* __restrict__ Wk,
        const float* __restrict__ Wv, const float* __restrict__ Wog,
        const float* __restrict__ Wout, const float* __restrict__ Wg,
        const float* __restrict__ Wu, const float* __restrict__ Wd){
    if (blockIdx.x < 64){
        int c0 = threadIdx.x, c1 = threadIdx.x + 256;
        float s0=0,s1=0,q0=0,q1=0;
        const float* base = x + (size_t)blockIdx.x * 128 * DD;
        for (int r=0;r<128;r++){
            float v0 = base[(size_t)r*DD + c0];
            float v1 = base[(size_t)r*DD + c1];
            s0+=v0; q0+=v0*v0; s1+=v1; q1+=v1*v1;
        }
        float* p = g_part + blockIdx.x*1024;
        p[c0]=s0; p[c1]=s1; p[512+c0]=q0; p[512+c1]=q1;
    } else {
        long e = (long)(blockIdx.x - 64)*1024 + (long)threadIdx.x*4;
        if (e >= TOTW) return;
        const float* src; long base;
        if      (e < OFF_WK)   { src = Wq;   base = OFF_WQ;  }
        else if (e < OFF_WV)   { src = Wk;   base = OFF_WK;  }
        else if (e < OFF_WOG)  { src = Wv;   base = OFF_WV;  }
        else if (e < OFF_WOUT) { src = Wog;  base = OFF_WOG; }
        else if (e < OFF_WG)   { src = Wout; base = OFF_WOUT;}
        else if (e < OFF_WU)   { src = Wg;   base = OFF_WG;  }
        else if (e < OFF_WD)   { src = Wu;   base = OFF_WU;  }
        else                   { src = Wd;   base = OFF_WD;  }
        float4 v = *reinterpret_cast<const float4*>(src + (e - base));
        __half2* d = reinterpret_cast<__half2*>(g_wh + e);
        d[0] = __floats2half2_rn(v.x, v.y);
        d[1] = __floats2half2_rn(v.z, v.w);
    }
}
__global__ void bn_final_kernel(){
    int c = threadIdx.x; // 512
    float s=0,q=0;
    for (int i=0;i<64;i++){ s += g_part[i*1024+c]; q += g_part[i*1024+512+c]; }
    float mu = s * (1.0f/RR);
    float var = q * (1.0f/RR) - mu*mu;
    g_stats[c] = mu;
    g_stats[512+c] = rsqrtf(var + EPS_BN);
}
// bn apply + rmsnorm(norm1_w[0]) fused
__global__ void bnapply_rms_kernel(const float* __restrict__ x,
                                   const float* __restrict__ gamma,
                                   const float* __restrict__ beta,
                                   const float* __restrict__ w){
    __shared__ float red[8];
    int r = blockIdx.x, t = threadIdx.x;
    int c0 = t, c1 = t + 256;
    const float* xr = x + (size_t)r*DD;
    float a = (xr[c0]-g_stats[c0])*g_stats[512+c0]*gamma[c0] + beta[c0];
    float b = (xr[c1]-g_stats[c1])*g_stats[512+c1]*gamma[c1] + beta[c1];
    g_xn[(size_t)r*DD+c0] = a; g_xn[(size_t)r*DD+c1] = b;
    g_h [(size_t)r*DD+c0] = a; g_h [(size_t)r*DD+c1] = b;
    float s = a*a + b*b;
    #pragma unroll
    for (int o=16;o;o>>=1) s += __shfl_xor_sync(~0u, s, o);
    if ((t&31)==0) red[t>>5]=s;
    __syncthreads();
    float tot = 0;
    #pragma unroll
    for (int i=0;i<8;i++) tot += red[i];
    float rs = rsqrtf(tot*(1.0f/DD) + EPS_RMS);
    g_yh[(size_t)r*DD+c0] = __float2half(a*rs*w[c0]);
    g_yh[(size_t)r*DD+c1] = __float2half(b*rs*w[c1]);
}

// ---------------- rms norm variants ----------------
__global__ void rmsnorm_h_kernel(const float* __restrict__ x, const float* __restrict__ w,
                                 __half* __restrict__ y){
    __shared__ float red[8];
    int r = blockIdx.x, t = threadIdx.x;
    const float* xr = x + (size_t)r*DD;
    float a = xr[t], b = xr[t+256];
    float s = a*a + b*b;
    #pragma unroll
    for (int o=16;o;o>>=1) s += __shfl_xor_sync(~0u, s, o);
    if ((t&31)==0) red[t>>5]=s;
    __syncthreads();
    float tot = 0;
    #pragma unroll
    for (int i=0;i<8;i++) tot += red[i];
    float rs = rsqrtf(tot*(1.0f/DD) + EPS_RMS);
    __half* yr = y + (size_t)r*DD;
    yr[t]     = __float2half(a*rs*w[t]);
    yr[t+256] = __float2half(b*rs*w[t+256]);
}
__global__ void rmsnorm_f_kernel(const float* __restrict__ x, const float* __restrict__ w,
                                 float* __restrict__ y, long xs){
    __shared__ float red[8];
    int r = blockIdx.x, t = threadIdx.x;
    const float* xr = x + (size_t)r*xs;
    float a = xr[t], b = xr[t+256];
    float s = a*a + b*b;
    #pragma unroll
    for (int o=16;o;o>>=1) s += __shfl_xor_sync(~0u, s, o);
    if ((t&31)==0) red[t>>5]=s;
    __syncthreads();
    float tot = 0;
    #pragma unroll
    for (int i=0;i<8;i++) tot += red[i];
    float rs = rsqrtf(tot*(1.0f/DD) + EPS_RMS);
    float* yr = y + (size_t)r*DD;
    yr[t]     = a*rs*w[t];
    yr[t+256] = b*rs*w[t+256];
}

// ---------------- fp16 tensor-core GEMM v2 ----------------
// C[M,N] = A[M,K] @ B[K,N]; block 128x128, 8 warps of 32x64, K-tile 32,
// 3-stage cp.async pipeline, ldmatrix fragments, fp32 accum.
// EPI: 0 store fp32, 1 C+=, 2 sigmoid, 3 CH = silu(C)*acc (half out)
#define AP 40          // A row pitch (halves)
#define BP 136         // B row pitch (halves)
#define AS_SZ (128*AP) // 5120
#define BS_SZ (32*BP)  // 4352
#define NSTG 3
#define HG_SMEM (NSTG*(AS_SZ+BS_SZ)*2)

template<int EPI>
__global__ __launch_bounds__(256) void hgemm_kernel(
        const __half* __restrict__ A,
        const __half* __restrict__ B0, float* __restrict__ C0,
        const __half* __restrict__ B1, float* __restrict__ C1,
        __half* __restrict__ CH,
        int N, int K){
    extern __shared__ __half sm[];
    __half* As = sm;                    // [NSTG][AS_SZ]
    __half* Bs = sm + NSTG*AS_SZ;       // [NSTG][BS_SZ]
    const __half* Bm = (blockIdx.z == 0) ? B0 : B1;
    float* C = (blockIdx.z == 0) ? C0 : C1;
    const int tid = threadIdx.x;
    const int lane = tid & 31;
    const int wid = tid >> 5;
    const int g = lane >> 2, t = lane & 3;
    const int mw = (wid >> 1) * 32;   // 4 m-warps
    const int nw = (wid & 1) * 64;    // 2 n-warps
    const __half* Ab = A + (size_t)blockIdx.y * 128 * K;
    const __half* Bb = Bm + (size_t)blockIdx.x * 128;

    const int lrow = (lane & 7) + ((lane >> 3) & 1) * 8;
    const int lcol = ((lane >> 3) & 2) * 4;
    const unsigned smA = (unsigned)__cvta_generic_to_shared(As);
    const unsigned smB = (unsigned)__cvta_generic_to_shared(Bs);

    float acc[2][8][4];
    #pragma unroll
    for (int i=0;i<2;i++)
        #pragma unroll
        for (int j=0;j<8;j++)
            #pragma unroll
            for (int c=0;c<4;c++) acc[i][j][c]=0.f;

    const int KT = K / 32;

    #define LOAD_TILE(kt, buf) do {                                            \
        __half* Ad = As + (buf)*AS_SZ;                                         \
        __half* Bd = Bs + (buf)*BS_SZ;                                         \
        _Pragma("unroll")                                                      \
        for (int ii=0; ii<2; ii++){                                            \
            int idx = tid + ii*256;                                            \
            int m = idx >> 2, c = idx & 3;                                     \
            cp16(Ad + m*AP + c*8, Ab + (size_t)m*K + (kt)*32 + c*8);           \
        }                                                                      \
        _Pragma("unroll")                                                      \
        for (int ii=0; ii<2; ii++){                                            \
            int idx = tid + ii*256;                                            \
            int kr = idx >> 4, c = idx & 15;                                   \
            cp16(Bd + kr*BP + c*8, Bb + (size_t)((kt)*32+kr)*N + c*8);         \
        }                                                                      \
    } while(0)

    LOAD_TILE(0, 0);
    cp_commit();
    if (KT > 1){ LOAD_TILE(1, 1); cp_commit(); }

    for (int kt=0; kt<KT; kt++){
        int buf = kt % NSTG;
        if (kt+2 < KT){
            LOAD_TILE(kt+2, (kt+2)%NSTG);
            cp_commit();
            cp_wait<2>();
        } else if (kt+1 < KT){
            cp_wait<1>();
        } else {
            cp_wait<0>();
        }
        __syncthreads();
        unsigned baseA = smA + buf*AS_SZ*2;
        unsigned baseB = smB + buf*BS_SZ*2;
        #pragma unroll
        for (int ks=0; ks<2; ks++){
            int k0 = ks*16;
            unsigned af[2][4], bf[4][4];
            #pragma unroll
            for (int i=0;i<2;i++){
                int m0 = mw + i*16;
                unsigned addr = baseA + ((unsigned)(m0 + lrow)*AP + (k0 + lcol))*2;
                ldsm4(af[i][0], af[i][1], af[i][2], af[i][3], addr);
            }
            #pragma unroll
            for (int j2=0;j2<4;j2++){
                int n0 = nw + j2*16;
                unsigned addr = baseB + ((unsigned)(k0 + lrow)*BP + (n0 + lcol))*2;
                ldsm4t(bf[j2][0], bf[j2][1], bf[j2][2], bf[j2][3], addr);
            }
            #pragma unroll
            for (int i=0;i<2;i++){
                #pragma unroll
                for (int j=0;j<8;j++){
                    unsigned b2[2];
                    b2[0] = bf[j>>1][(j&1)*2+0];
                    b2[1] = bf[j>>1][(j&1)*2+1];
                    mma_f16(acc[i][j], af[i], b2);
                }
            }
        }
        __syncthreads();
    }

    // epilogue
    #pragma unroll
    for (int i=0;i<2;i++){
        #pragma unroll
        for (int j=0;j<8;j++){
            size_t row = (size_t)blockIdx.y*128 + mw + i*16 + g;
            size_t col = (size_t)blockIdx.x*128 + nw + j*8 + t*2;
            #pragma unroll
            for (int h2=0; h2<2; h2++){
                size_t rr = row + h2*8;
                float v0 = acc[i][j][h2*2+0];
                float v1 = acc[i][j][h2*2+1];
                if (EPI==0){
                    float* p = C + rr*N + col;
                    p[0]=v0; p[1]=v1;
                } else if (EPI==1){
                    float* p = C + rr*N + col;
                    p[0]+=v0; p[1]+=v1;
                } else if (EPI==2){
                    float* p = C + rr*N + col;
                    p[0] = 1.0f/(1.0f+expf(-v0));
                    p[1] = 1.0f/(1.0f+expf(-v1));
                } else {
                    const float* p = C + rr*N + col;
                    float g0=p[0], g1v=p[1];
                    __half* q = CH + rr*N + col;
                    q[0] = __float2half(g0*(1.0f/(1.0f+expf(-g0)))*v0);
                    q[1] = __float2half(g1v*(1.0f/(1.0f+expf(-g1v)))*v1);
                }
            }
        }
    }
    #undef LOAD_TILE
}

// ---------------- gate projections (fp16 y input) ----------------
__global__ void gates_kernel(const __half* __restrict__ y,
                             const float* __restrict__ Wi, const float* __restrict__ bi,
                             const float* __restrict__ Wf, const float* __restrict__ bf){
    int warp = (blockIdx.x*blockDim.x + threadIdx.x) >> 5;
    int lane = threadIdx.x & 31;
    if (warp >= RR) return;
    const __half* yr = y + (size_t)warp*DD;
    float si[8]={0,0,0,0,0,0,0,0}, sf[8]={0,0,0,0,0,0,0,0};
    for (int d=lane; d<DD; d+=32){
        float yv = __half2float(yr[d]);
        #pragma unroll
        for (int hh=0; hh<8; hh++){
            si[hh] += yv * Wi[d*HH+hh];
            sf[hh] += yv * Wf[d*HH+hh];
        }
    }
    #pragma unroll
    for (int hh=0; hh<8; hh++){
        #pragma unroll
        for (int o=16;o;o>>=1){
            si[hh]+=__shfl_xor_sync(~0u,si[hh],o);
            sf[hh]+=__shfl_xor_sync(~0u,sf[hh],o);
        }
    }
    if (lane==0){
        int b = warp >> 9, s = warp & 511;
        #pragma unroll
        for (int hh=0;hh<8;hh++){
            g_ig[((b*HH+hh)*SS)+s] = softcapf(si[hh]+bi[hh]);
            g_fg[((b*HH+hh)*SS)+s] = softcapf(sf[hh]+bf[hh]);
        }
    }
}

// ---------------- per-(b,h) prefix scan ----------------
__global__ void scan_kernel(){
    if (threadIdx.x != 0) return;
    int bh = blockIdx.x;
    const float* ig = g_ig + bh*SS;
    const float* fg = g_fg + bh*SS;
    float bc=0.f, cm=-1e30f;
    for (int s=0;s<SS;s++){
        bc += logsigf(fg[s]);
        float c = ig[s] - bc;
        cm = fmaxf(cm, c);
        g_bc[bh*SS+s] = bc;
        g_mv[bh*SS+s] = bc + cm;   // m[t]
    }
}

// ---------------- mLSTM attention: 128 thr, 2 threads per t-row ----------------
__global__ __launch_bounds__(128) void attn_kernel(){
    __shared__ float4 Ks[64*8];   // 64 rows x 32 floats
    __shared__ float4 Vs[64*16];  // 64 rows x 64 floats
    __shared__ float bs_s[64], ig_s[64];
    int bh = blockIdx.y; int b = bh >> 3; int h = bh & 7;
    int tt = blockIdx.x;
    int tid = threadIdx.x;
    int row = tid & 63;
    int half = tid >> 6;          // 0: cols 0-31, 1: cols 32-63
    int t = tt*64 + row;
    const float4* qp = (const float4*)(g_q + ((size_t)(b*SS)+t)*QKD + h*DQK);
    float4 q4[8];
    #pragma unroll
    for (int d=0;d<8;d++) q4[d] = qp[d];
    float bt = g_bc[bh*SS + t];
    float mt = g_mv[bh*SS + t];
    float4 acc[8];
    #pragma unroll
    for (int j=0;j<8;j++) acc[j] = make_float4(0.f,0.f,0.f,0.f);
    float ssum = 0.f;
    const float scale = 0.17677669529663687f;  // 1/sqrt(32)
    for (int st=0; st<=tt; st++){
        int s0 = st*64;
        #pragma unroll
        for (int ii=0; ii<4; ii++){
            int idx = tid + ii*128;
            int rr = idx >> 3, cc = idx & 7;
            Ks[idx] = *(const float4*)(g_k + ((size_t)(b*SS)+s0+rr)*QKD + h*DQK + cc*4);
        }
        #pragma unroll
        for (int ii=0; ii<8; ii++){
            int idx = tid + ii*128;
            int rr = idx >> 4, cc = idx & 15;
            Vs[idx] = *(const float4*)(g_v + ((size_t)(b*SS)+s0+rr)*VV + h*DV + cc*4);
        }
        if (tid < 64){
            bs_s[tid] = g_bc[bh*SS + s0 + tid];
            ig_s[tid] = g_ig[bh*SS + s0 + tid];
        }
        __syncthreads();
        int smax = min(64, t - s0 + 1);
        for (int sl=0; sl<smax; sl++){
            const float4* kp = &Ks[sl*8];
            float dot=0.f;
            #pragma unroll
            for (int d=0;d<8;d++){
                float4 kv = kp[d];
                dot += q4[d].x*kv.x + q4[d].y*kv.y + q4[d].z*kv.z + q4[d].w*kv.w;
            }
            float w = dot * scale * __expf(bt - bs_s[sl] + ig_s[sl] - mt);
            ssum += w;
            const float4* vp = &Vs[sl*16 + half*8];
            #pragma unroll
            for (int j=0;j<8;j++){
                float4 vv = vp[j];
                acc[j].x += w*vv.x; acc[j].y += w*vv.y;
                acc[j].z += w*vv.z; acc[j].w += w*vv.w;
            }
        }
        __syncthreads();
    }
    float nrm = fmaxf(fabsf(ssum), __expf(-mt));
    float inv = 1.0f/(nrm + EPS_RMS);
    float4* o = (float4*)(g_ht + ((size_t)(b*SS)+t)*VV + h*DV) + half*8;
    #pragma unroll
    for (int j=0;j<8;j++){
        float4 a = acc[j];
        o[j] = make_float4(a.x*inv, a.y*inv, a.z*inv, a.w*inv);
    }
}

// ---------------- per-head layer norm * mhn_w * og -> fp16 ----------------
__global__ void headnorm_kernel(const float* __restrict__ mhn){
    int r = blockIdx.x;
    int w = threadIdx.x >> 5;      // head
    int lane = threadIdx.x & 31;
    const float* base = g_ht + (size_t)r*VV + w*DV;
    float e0 = base[lane], e1 = base[lane+32];
    float s = e0 + e1;
    #pragma unroll
    for (int o=16;o;o>>=1) s += __shfl_xor_sync(~0u,s,o);
    float mu = s * (1.0f/DV);
    float d0 = e0-mu, d1 = e1-mu;
    float v = d0*d0 + d1*d1;
    #pragma unroll
    for (int o=16;o;o>>=1) v += __shfl_xor_sync(~0u,v,o);
    float rs = rsqrtf(v*(1.0f/DV) + EPS_RMS);
    const float* ogb = g_og + (size_t)r*VV + w*DV;
    __half* dst = g_hth + (size_t)r*VV + w*DV;
    dst[lane]    = __float2half(d0*rs*mhn[w*DV+lane]   * ogb[lane]);
    dst[lane+32] = __float2half(d1*rs*mhn[w*DV+lane+32]* ogb[lane+32]);
}

// ---------------- final heads ----------------
__global__ void bn1_kernel(const float* __restrict__ gamma, const float* __restrict__ beta){
    int c = threadIdx.x; // 512
    float v[16]; float mu=0.f;
    #pragma unroll
    for (int b=0;b<16;b++){ v[b]=g_last[b*DD+c]; mu+=v[b]; }
    mu *= (1.0f/16.0f);
    float var=0.f;
    #pragma unroll
    for (int b=0;b<16;b++){ float d=v[b]-mu; var+=d*d; }
    var *= (1.0f/16.0f);
    float rs = rsqrtf(var + EPS_BN);
    #pragma unroll
    for (int b=0;b<16;b++) g_last[b*DD+c] = (v[b]-mu)*rs*gamma[c] + beta[c];
}
__global__ void fc1_kernel(const float* __restrict__ W, const float* __restrict__ bias){
    __shared__ float xr[512];
    int b = blockIdx.x; int j = threadIdx.x; // 256
    xr[j]     = g_last[b*DD + j];
    xr[j+256] = g_last[b*DD + j + 256];
    __syncthreads();
    float s=0.f;
    #pragma unroll 8
    for (int k=0;k<512;k++) s += xr[k]*W[k*256+j];
    g_o1[b*256+j] = s + bias[j];
}
__global__ void bn2gelu_kernel(const float* __restrict__ gamma, const float* __restrict__ beta){
    int j = threadIdx.x; // 256
    float v[16]; float mu=0.f;
    #pragma unroll
    for (int b=0;b<16;b++){ v[b]=g_o1[b*256+j]; mu+=v[b]; }
    mu *= (1.0f/16.0f);
    float var=0.f;
    #pragma unroll
    for (int b=0;b<16;b++){ float d=v[b]-mu; var+=d*d; }
    var *= (1.0f/16.0f);
    float rs = rsqrtf(var + EPS_BN);
    #pragma unroll
    for (int b=0;b<16;b++){
        float t = (v[b]-mu)*rs*gamma[j] + beta[j];
        g_o1[b*256+j] = 0.5f*t*(1.0f + erff(t*0.7071067811865475f));
    }
}
__global__ void fc2_kernel(const float* __restrict__ W, const float* __restrict__ bias){
    __shared__ float red[256];
    int b = blockIdx.x; int j = threadIdx.x;
    red[j] = g_o1[b*256+j]*W[j];
    __syncthreads();
    for (int o=128;o;o>>=1){ if(j<o) red[j]+=red[j+o]; __syncthreads(); }
    if (j==0) g_o2[b] = red[0] + bias[0];
}
__global__ void res_out_kernel(const float* __restrict__ resW, const float* __restrict__ resb,
                               float* __restrict__ out){
    int warp = (blockIdx.x*blockDim.x + threadIdx.x) >> 5;
    int lane = threadIdx.x & 31;
    if (warp >= RR) return;
    const float* xr = g_xn + (size_t)warp*DD;
    float s=0.f;
    for (int d=lane; d<DD; d+=32) s += xr[d]*resW[d];
    #pragma unroll
    for (int o=16;o;o>>=1) s += __shfl_xor_sync(~0u,s,o);
    if (lane==0){
        float v = s + resb[0] + g_o2[warp>>9];
        out[warp] = fmaxf(v, 0.f);
    }
}

// ---------------- host driver ----------------
extern "C" void kernel_launch(void* const* d_in, const int* in_sizes, int n_in,
                              void* d_out, int out_size){
    const float* x        = (const float*)d_in[0];
    const float* bng      = (const float*)d_in[1];
    const float* bnb      = (const float*)d_in[2];
    const float* norm1_w  = (const float*)d_in[3];
    const float* norm2_w  = (const float*)d_in[4];
    const float* Wq       = (const float*)d_in[5];
    const float* Wk       = (const float*)d_in[6];
    const float* Wv       = (const float*)d_in[7];
    const float* Wog      = (const float*)d_in[8];
    const float* Wi       = (const float*)d_in[9];
    const float* bi       = (const float*)d_in[10];
    const float* Wf       = (const float*)d_in[11];
    const float* bf       = (const float*)d_in[12];
    const float* mhn_w    = (const float*)d_in[13];
    const float* Wout     = (const float*)d_in[14];
    const float* Wg       = (const float*)d_in[15];
    const float* Wu       = (const float*)d_in[16];
    const float* Wd       = (const float*)d_in[17];
    const float* fnorm_w  = (const float*)d_in[18];
    const float* bn1_g    = (const float*)d_in[19];
    const float* bn1_b    = (const float*)d_in[20];
    const float* fc1_W    = (const float*)d_in[21];
    const float* fc1_b    = (const float*)d_in[22];
    const float* bn2_g    = (const float*)d_in[23];
    const float* bn2_b    = (const float*)d_in[24];
    const float* fc2_W    = (const float*)d_in[25];
    const float* fc2_b    = (const float*)d_in[26];
    const float* res_W    = (const float*)d_in[27];
    const float* res_b    = (const float*)d_in[28];
    float* out = (float*)d_out;

    float *p_q,*p_k,*p_v,*p_og,*p_ht,*p_h,*p_g1,*p_last;
    __half *p_wh,*p_yh,*p_hth,*p_g1h;
    cudaGetSymbolAddress((void**)&p_q,  g_q);
    cudaGetSymbolAddress((void**)&p_k,  g_k);
    cudaGetSymbolAddress((void**)&p_v,  g_v);
    cudaGetSymbolAddress((void**)&p_og, g_og);
    cudaGetSymbolAddress((void**)&p_ht, g_ht);
    cudaGetSymbolAddress((void**)&p_h,  g_h);
    cudaGetSymbolAddress((void**)&p_g1, g_gu1);
    cudaGetSymbolAddress((void**)&p_last, g_last);
    cudaGetSymbolAddress((void**)&p_wh,  g_wh);
    cudaGetSymbolAddress((void**)&p_yh,  g_yh);
    cudaGetSymbolAddress((void**)&p_hth, g_hth);
    cudaGetSymbolAddress((void**)&p_g1h, g_g1h);

    cudaFuncSetAttribute(hgemm_kernel<0>, cudaFuncAttributeMaxDynamicSharedMemorySize, HG_SMEM);
    cudaFuncSetAttribute(hgemm_kernel<1>, cudaFuncAttributeMaxDynamicSharedMemorySize, HG_SMEM);
    cudaFuncSetAttribute(hgemm_kernel<2>, cudaFuncAttributeMaxDynamicSharedMemorySize, HG_SMEM);
    cudaFuncSetAttribute(hgemm_kernel<3>, cudaFuncAttributeMaxDynamicSharedMemorySize, HG_SMEM);

    bnpart_conv_kernel<<<64 + (int)((TOTW + 1023)/1024), 256>>>(x, Wq, Wk, Wv, Wog, Wout, Wg, Wu, Wd);
    bn_final_kernel<<<1,512>>>();
    bnapply_rms_kernel<<<RR,256>>>(x, bng, bnb, norm1_w);

    for (int l=0;l<LL;l++){
        const __half* Wq_h  = p_wh + OFF_WQ  + (size_t)l*DD*QKD;
        const __half* Wk_h  = p_wh + OFF_WK  + (size_t)l*DD*QKD;
        const __half* Wv_h  = p_wh + OFF_WV  + (size_t)l*DD*VV;
        const __half* Wog_h = p_wh + OFF_WOG + (size_t)l*DD*VV;
        const __half* Wout_h= p_wh + OFF_WOUT+ (size_t)l*VV*DD;
        const __half* Wg_h  = p_wh + OFF_WG  + (size_t)l*DD*FF;
        const __half* Wu_h  = p_wh + OFF_WU  + (size_t)l*DD*FF;
        const __half* Wd_h  = p_wh + OFF_WD  + (size_t)l*FF*DD;
        const float* Wi_l = Wi + (size_t)l*DD*HH;
        const float* Wf_l = Wf + (size_t)l*DD*HH;

        if (l > 0)
            rmsnorm_h_kernel<<<RR,256>>>(p_h, norm1_w + l*DD, p_yh);

        hgemm_kernel<0><<<dim3(QKD/128, RR/128, 2),256,HG_SMEM>>>(p_yh, Wq_h, p_q, Wk_h, p_k, nullptr, QKD, DD);
        hgemm_kernel<0><<<dim3(VV/128,  RR/128, 1),256,HG_SMEM>>>(p_yh, Wv_h, p_v, Wv_h, p_v, nullptr, VV, DD);
        hgemm_kernel<2><<<dim3(VV/128,  RR/128, 1),256,HG_SMEM>>>(p_yh, Wog_h,p_og,Wog_h,p_og,nullptr, VV, DD);
        gates_kernel<<<RR/8,256>>>(p_yh, Wi_l, bi + l*HH, Wf_l, bf + l*HH);
        scan_kernel<<<BB*HH,32>>>();

        attn_kernel<<<dim3(SS/64, BB*HH),128>>>();

        headnorm_kernel<<<RR,256>>>(mhn_w + l*VV);
        hgemm_kernel<1><<<dim3(DD/128, RR/128, 1),256,HG_SMEM>>>(p_hth, Wout_h, p_h, Wout_h, p_h, nullptr, DD, VV);

        rmsnorm_h_kernel<<<RR,256>>>(p_h, norm2_w + l*DD, p_yh);
        hgemm_kernel<0><<<dim3(FF/128, RR/128, 1),256,HG_SMEM>>>(p_yh, Wg_h, p_g1, Wg_h, p_g1, nullptr, FF, DD);
        hgemm_kernel<3><<<dim3(FF/128, RR/128, 1),256,HG_SMEM>>>(p_yh, Wu_h, p_g1, Wu_h, p_g1, p_g1h, FF, DD);
        hgemm_kernel<1><<<dim3(DD/128, RR/128, 1),256,HG_SMEM>>>(p_g1h, Wd_h, p_h, Wd_h, p_h, nullptr, DD, FF);
    }

    rmsnorm_f_kernel<<<BB,256>>>(p_h + (size_t)(SS-1)*DD, fnorm_w, p_last, (long)SS*DD);

    bn1_kernel<<<1,512>>>(bn1_g, bn1_b);
    fc1_kernel<<<BB,256>>>(fc1_W, fc1_b);
    bn2gelu_kernel<<<1,256>>>(bn2_g, bn2_b);
    fc2_kernel<<<BB,256>>>(fc2_W, fc2_b);
    res_out_kernel<<<RR/8,256>>>(res_W, res_b, out);
    (void)in_sizes; (void)n_in; (void)out_size;
}

// round 6
// speedup vs baseline: 1.1935x; 1.1935x over previous
#include <cuda_runtime.h>
#include <cuda_fp16.h>
#include <math.h>

// ---------------- problem constants ----------------
#define BB   16
#define SS   512
#define DD   512
#define LL   4
#define HH   8
#define QKD  256      // D/2
#define VV   512
#define FF   1408
#define RR   (BB*SS)      // 8192 rows
#define DQK  32
#define DV   64
#define EPS_RMS 1e-6f
#define EPS_BN  1e-5f
#define CAPV 15.0f

// weight half-buffer offsets (element counts, all layers concatenated)
#define OFF_WQ   0L
#define OFF_WK   524288L
#define OFF_WV   1048576L
#define OFF_WOG  2097152L
#define OFF_WOUT 3145728L
#define OFF_WG   4194304L
#define OFF_WU   7077888L
#define OFF_WD   9961472L
#define TOTW     12845056L

// ---------------- device scratch ----------------
__device__ float g_xn [RR*DD];
__device__ float g_h  [RR*DD];
__device__ float g_q  [RR*QKD];
__device__ float g_k  [RR*QKD];
__device__ float g_v  [RR*VV];
__device__ float g_og [RR*VV];
__device__ float g_ig [BB*HH*SS];
__device__ float g_fg [BB*HH*SS];
__device__ float g_bc [BB*HH*SS];
__device__ float g_mv [BB*HH*SS];
__device__ float g_part[64*1024];
__device__ float g_stats[1024];
__device__ float g_last[BB*DD];
__device__ float g_o1 [BB*256];
__device__ float g_o2 [BB];

__device__ __half g_wh  [TOTW];      // fp16 weights
__device__ __half g_yh  [RR*DD];     // fp16 rms-normed activations
__device__ __half g_hth [RR*VV];     // fp16 headnorm output
__device__ __half g_g1h [RR*FF];     // fp16 silu(g)*u

__device__ __forceinline__ float softcapf(float x){ return CAPV * tanhf(x * (1.0f/CAPV)); }
__device__ __forceinline__ float logsigf(float x){ return fminf(x,0.f) - log1pf(expf(-fabsf(x))); }

__device__ __forceinline__ void cp16(void* smem_dst, const void* gsrc){
    unsigned s = (unsigned)__cvta_generic_to_shared(smem_dst);
    asm volatile("cp.async.cg.shared.global [%0], [%1], 16;" :: "r"(s), "l"(gsrc));
}
__device__ __forceinline__ void cp_commit(){ asm volatile("cp.async.commit_group;" ::: "memory"); }
template<int NN> __device__ __forceinline__ void cp_wait(){ asm volatile("cp.async.wait_group %0;" :: "n"(NN) : "memory"); }

__device__ __forceinline__ void mma_f16(float* c, const unsigned* a, const unsigned* b){
    asm volatile("mma.sync.aligned.m16n8k16.row.col.f32.f16.f16.f32 "
        "{%0,%1,%2,%3}, {%4,%5,%6,%7}, {%8,%9}, {%0,%1,%2,%3};"
        : "+f"(c[0]), "+f"(c[1]), "+f"(c[2]), "+f"(c[3])
        : "r"(a[0]), "r"(a[1]), "r"(a[2]), "r"(a[3]), "r"(b[0]), "r"(b[1]));
}
__device__ __forceinline__ void ldsm4(unsigned& r0, unsigned& r1, unsigned& r2, unsigned& r3, unsigned addr){
    asm volatile("ldmatrix.sync.aligned.m8n8.x4.shared.b16 {%0,%1,%2,%3}, [%4];"
        : "=r"(r0), "=r"(r1), "=r"(r2), "=r"(r3) : "r"(addr));
}
__device__ __forceinline__ void ldsm4t(unsigned& r0, unsigned& r1, unsigned& r2, unsigned& r3, unsigned addr){
    asm volatile("ldmatrix.sync.aligned.m8n8.x4.trans.shared.b16 {%0,%1,%2,%3}, [%4];"
        : "=r"(r0), "=r"(r1), "=r"(r2), "=r"(r3) : "r"(addr));
}

// ---------------- bn partial + weight fp32->fp16 conversion (fused launch) ----
__global__ void bnpart_conv_kernel(const float* __restrict__ x,
        const float* __restrict__ Wq, const float* __restrict__ Wk,
        const float* __restrict__ Wv, const float* __restrict__ Wog,
        const float* __restrict__ Wout, const float* __restrict__ Wg,
        const float* __restrict__ Wu, const float* __restrict__ Wd){
    if (blockIdx.x < 64){
        int c0 = threadIdx.x, c1 = threadIdx.x + 256;
        float s0=0,s1=0,q0=0,q1=0;
        const float* base = x + (size_t)blockIdx.x * 128 * DD;
        for (int r=0;r<128;r++){
            float v0 = base[(size_t)r*DD + c0];
            float v1 = base[(size_t)r*DD + c1];
            s0+=v0; q0+=v0*v0; s1+=v1; q1+=v1*v1;
        }
        float* p = g_part + blockIdx.x*1024;
        p[c0]=s0; p[c1]=s1; p[512+c0]=q0; p[512+c1]=q1;
    } else {
        long e = (long)(blockIdx.x - 64)*1024 + (long)threadIdx.x*4;
        if (e >= TOTW) return;
        const float* src; long base;
        if      (e < OFF_WK)   { src = Wq;   base = OFF_WQ;  }
        else if (e < OFF_WV)   { src = Wk;   base = OFF_WK;  }
        else if (e < OFF_WOG)  { src = Wv;   base = OFF_WV;  }
        else if (e < OFF_WOUT) { src = Wog;  base = OFF_WOG; }
        else if (e < OFF_WG)   { src = Wout; base = OFF_WOUT;}
        else if (e < OFF_WU)   { src = Wg;   base = OFF_WG;  }
        else if (e < OFF_WD)   { src = Wu;   base = OFF_WU;  }
        else                   { src = Wd;   base = OFF_WD;  }
        float4 v = *reinterpret_cast<const float4*>(src + (e - base));
        __half2* d = reinterpret_cast<__half2*>(g_wh + e);
        d[0] = __floats2half2_rn(v.x, v.y);
        d[1] = __floats2half2_rn(v.z, v.w);
    }
}
__global__ void bn_final_kernel(){
    int c = threadIdx.x; // 512
    float s=0,q=0;
    for (int i=0;i<64;i++){ s += g_part[i*1024+c]; q += g_part[i*1024+512+c]; }
    float mu = s * (1.0f/RR);
    float var = q * (1.0f/RR) - mu*mu;
    g_stats[c] = mu;
    g_stats[512+c] = rsqrtf(var + EPS_BN);
}
// bn apply + rmsnorm(norm1_w[0]) fused
__global__ void bnapply_rms_kernel(const float* __restrict__ x,
                                   const float* __restrict__ gamma,
                                   const float* __restrict__ beta,
                                   const float* __restrict__ w){
    __shared__ float red[8];
    int r = blockIdx.x, t = threadIdx.x;
    int c0 = t, c1 = t + 256;
    const float* xr = x + (size_t)r*DD;
    float a = (xr[c0]-g_stats[c0])*g_stats[512+c0]*gamma[c0] + beta[c0];
    float b = (xr[c1]-g_stats[c1])*g_stats[512+c1]*gamma[c1] + beta[c1];
    g_xn[(size_t)r*DD+c0] = a; g_xn[(size_t)r*DD+c1] = b;
    g_h [(size_t)r*DD+c0] = a; g_h [(size_t)r*DD+c1] = b;
    float s = a*a + b*b;
    #pragma unroll
    for (int o=16;o;o>>=1) s += __shfl_xor_sync(~0u, s, o);
    if ((t&31)==0) red[t>>5]=s;
    __syncthreads();
    float tot = 0;
    #pragma unroll
    for (int i=0;i<8;i++) tot += red[i];
    float rs = rsqrtf(tot*(1.0f/DD) + EPS_RMS);
    g_yh[(size_t)r*DD+c0] = __float2half(a*rs*w[c0]);
    g_yh[(size_t)r*DD+c1] = __float2half(b*rs*w[c1]);
}

// ---------------- rms norm variants ----------------
__global__ void rmsnorm_h_kernel(const float* __restrict__ x, const float* __restrict__ w,
                                 __half* __restrict__ y){
    __shared__ float red[8];
    int r = blockIdx.x, t = threadIdx.x;
    const float* xr = x + (size_t)r*DD;
    float a = xr[t], b = xr[t+256];
    float s = a*a + b*b;
    #pragma unroll
    for (int o=16;o;o>>=1) s += __shfl_xor_sync(~0u, s, o);
    if ((t&31)==0) red[t>>5]=s;
    __syncthreads();
    float tot = 0;
    #pragma unroll
    for (int i=0;i<8;i++) tot += red[i];
    float rs = rsqrtf(tot*(1.0f/DD) + EPS_RMS);
    __half* yr = y + (size_t)r*DD;
    yr[t]     = __float2half(a*rs*w[t]);
    yr[t+256] = __float2half(b*rs*w[t+256]);
}
__global__ void rmsnorm_f_kernel(const float* __restrict__ x, const float* __restrict__ w,
                                 float* __restrict__ y, long xs){
    __shared__ float red[8];
    int r = blockIdx.x, t = threadIdx.x;
    const float* xr = x + (size_t)r*xs;
    float a = xr[t], b = xr[t+256];
    float s = a*a + b*b;
    #pragma unroll
    for (int o=16;o;o>>=1) s += __shfl_xor_sync(~0u, s, o);
    if ((t&31)==0) red[t>>5]=s;
    __syncthreads();
    float tot = 0;
    #pragma unroll
    for (int i=0;i<8;i++) tot += red[i];
    float rs = rsqrtf(tot*(1.0f/DD) + EPS_RMS);
    float* yr = y + (size_t)r*DD;
    yr[t]     = a*rs*w[t];
    yr[t+256] = b*rs*w[t+256];
}

// ---------------- fp16 tensor-core GEMM v4 ----------------
// block 128x128, 8 warps of 32x64, K-tile 32, 4-stage cp.async,
// ONE __syncthreads per K-tile. EPI per blockIdx.z:
// 0 store fp32, 1 C+=, 2 sigmoid
#define AP 40
#define BP 136
#define AS_SZ (128*AP)
#define BS_SZ (32*BP)
#define NSTG 4
#define HG_SMEM (NSTG*(AS_SZ+BS_SZ)*2)

template<int EPI0, int EPI1>
__global__ __launch_bounds__(256) void hgemm_kernel(
        const __half* __restrict__ A,
        const __half* __restrict__ B0, float* __restrict__ C0,
        const __half* __restrict__ B1, float* __restrict__ C1,
        int N, int K){
    extern __shared__ __half sm[];
    __half* As = sm;
    __half* Bs = sm + NSTG*AS_SZ;
    const int z = blockIdx.z;
    const __half* Bm = z ? B1 : B0;
    float* C = z ? C1 : C0;
    const int tid = threadIdx.x;
    const int lane = tid & 31;
    const int wid = tid >> 5;
    const int g = lane >> 2, t = lane & 3;
    const int mw = (wid >> 1) * 32;
    const int nw = (wid & 1) * 64;
    const __half* Ab = A + (size_t)blockIdx.y * 128 * K;
    const __half* Bb = Bm + (size_t)blockIdx.x * 128;

    const int lrow = (lane & 7) + ((lane >> 3) & 1) * 8;
    const int lcol = ((lane >> 3) & 2) * 4;
    const unsigned smA = (unsigned)__cvta_generic_to_shared(As);
    const unsigned smB = (unsigned)__cvta_generic_to_shared(Bs);

    float acc[2][8][4];
    #pragma unroll
    for (int i=0;i<2;i++)
        #pragma unroll
        for (int j=0;j<8;j++)
            #pragma unroll
            for (int c=0;c<4;c++) acc[i][j][c]=0.f;

    const int KT = K / 32;

    #define LOAD_TILE(kt, buf) do {                                            \
        __half* Ad = As + (buf)*AS_SZ;                                         \
        __half* Bd = Bs + (buf)*BS_SZ;                                         \
        _Pragma("unroll")                                                      \
        for (int ii=0; ii<2; ii++){                                            \
            int idx = tid + ii*256;                                            \
            int m = idx >> 2, c = idx & 3;                                     \
            cp16(Ad + m*AP + c*8, Ab + (size_t)m*K + (kt)*32 + c*8);           \
        }                                                                      \
        _Pragma("unroll")                                                      \
        for (int ii=0; ii<2; ii++){                                            \
            int idx = tid + ii*256;                                            \
            int kr = idx >> 4, c = idx & 15;                                   \
            cp16(Bd + kr*BP + c*8, Bb + (size_t)((kt)*32+kr)*N + c*8);         \
        }                                                                      \
    } while(0)

    LOAD_TILE(0, 0); cp_commit();
    LOAD_TILE(1, 1); cp_commit();
    LOAD_TILE(2, 2); cp_commit();

    for (int kt=0; kt<KT; kt++){
        if (kt <= KT-3)      cp_wait<2>();
        else if (kt == KT-2) cp_wait<1>();
        else                 cp_wait<0>();
        __syncthreads();
        if (kt+3 < KT){ LOAD_TILE(kt+3, (kt+3)&3); cp_commit(); }

        int buf = kt & 3;
        unsigned baseA = smA + buf*AS_SZ*2;
        unsigned baseB = smB + buf*BS_SZ*2;
        #pragma unroll
        for (int ks=0; ks<2; ks++){
            int k0 = ks*16;
            unsigned af[2][4], bf[4][4];
            #pragma unroll
            for (int i=0;i<2;i++){
                int m0 = mw + i*16;
                ldsm4(af[i][0], af[i][1], af[i][2], af[i][3],
                      baseA + ((unsigned)(m0 + lrow)*AP + (k0 + lcol))*2);
            }
            #pragma unroll
            for (int j2=0;j2<4;j2++){
                int n0 = nw + j2*16;
                ldsm4t(bf[j2][0], bf[j2][1], bf[j2][2], bf[j2][3],
                       baseB + ((unsigned)(k0 + lrow)*BP + (n0 + lcol))*2);
            }
            #pragma unroll
            for (int i=0;i<2;i++){
                #pragma unroll
                for (int j=0;j<8;j++){
                    unsigned b2[2];
                    b2[0] = bf[j>>1][(j&1)*2+0];
                    b2[1] = bf[j>>1][(j&1)*2+1];
                    mma_f16(acc[i][j], af[i], b2);
                }
            }
        }
    }

    const int EPI = z ? EPI1 : EPI0;
    #pragma unroll
    for (int i=0;i<2;i++){
        #pragma unroll
        for (int j=0;j<8;j++){
            size_t row = (size_t)blockIdx.y*128 + mw + i*16 + g;
            size_t col = (size_t)blockIdx.x*128 + nw + j*8 + t*2;
            #pragma unroll
            for (int h2=0; h2<2; h2++){
                size_t rr = row + h2*8;
                float v0 = acc[i][j][h2*2+0];
                float v1 = acc[i][j][h2*2+1];
                float* p = C + rr*N + col;
                if (EPI==0){ p[0]=v0; p[1]=v1; }
                else if (EPI==1){ p[0]+=v0; p[1]+=v1; }
                else {
                    p[0] = 1.0f/(1.0f+expf(-v0));
                    p[1] = 1.0f/(1.0f+expf(-v1));
                }
            }
        }
    }
    #undef LOAD_TILE
}

// ---------------- fused G+U GEMM: out = silu(y@Wg) * (y@Wu), fp16 out -------
#define GU_SMEM (NSTG*(AS_SZ+2*BS_SZ)*2)
__global__ __launch_bounds__(256) void hgemm_gu_kernel(
        const __half* __restrict__ A,
        const __half* __restrict__ Bg, const __half* __restrict__ Bu,
        __half* __restrict__ CH, int N, int K){
    extern __shared__ __half sm[];
    __half* As  = sm;
    __half* Bgs = sm + NSTG*AS_SZ;
    __half* Bus = Bgs + NSTG*BS_SZ;
    const int tid = threadIdx.x;
    const int lane = tid & 31;
    const int wid = tid >> 5;
    const int g = lane >> 2, t = lane & 3;
    const int mw = (wid >> 1) * 32;
    const int nw = (wid & 1) * 64;
    const __half* Ab  = A + (size_t)blockIdx.y * 128 * K;
    const __half* Bgb = Bg + (size_t)blockIdx.x * 128;
    const __half* Bub = Bu + (size_t)blockIdx.x * 128;

    const int lrow = (lane & 7) + ((lane >> 3) & 1) * 8;
    const int lcol = ((lane >> 3) & 2) * 4;
    const unsigned smA = (unsigned)__cvta_generic_to_shared(As);
    const unsigned smG = (unsigned)__cvta_generic_to_shared(Bgs);
    const unsigned smU = (unsigned)__cvta_generic_to_shared(Bus);

    float accg[2][8][4], accu[2][8][4];
    #pragma unroll
    for (int i=0;i<2;i++)
        #pragma unroll
        for (int j=0;j<8;j++)
            #pragma unroll
            for (int c=0;c<4;c++){ accg[i][j][c]=0.f; accu[i][j][c]=0.f; }

    const int KT = K / 32;

    #define LOAD_TILE_GU(kt, buf) do {                                         \
        __half* Ad = As  + (buf)*AS_SZ;                                        \
        __half* Gd = Bgs + (buf)*BS_SZ;                                        \
        __half* Ud = Bus + (buf)*BS_SZ;                                        \
        _Pragma("unroll")                                                      \
        for (int ii=0; ii<2; ii++){                                            \
            int idx = tid + ii*256;                                            \
            int m = idx >> 2, c = idx & 3;                                     \
            cp16(Ad + m*AP + c*8, Ab + (size_t)m*K + (kt)*32 + c*8);           \
        }                                                                      \
        _Pragma("unroll")                                                      \
        for (int ii=0; ii<2; ii++){                                            \
            int idx = tid + ii*256;                                            \
            int kr = idx >> 4, c = idx & 15;                                   \
            cp16(Gd + kr*BP + c*8, Bgb + (size_t)((kt)*32+kr)*N + c*8);        \
            cp16(Ud + kr*BP + c*8, Bub + (size_t)((kt)*32+kr)*N + c*8);        \
        }                                                                      \
    } while(0)

    LOAD_TILE_GU(0, 0); cp_commit();
    LOAD_TILE_GU(1, 1); cp_commit();
    LOAD_TILE_GU(2, 2); cp_commit();

    for (int kt=0; kt<KT; kt++){
        if (kt <= KT-3)      cp_wait<2>();
        else if (kt == KT-2) cp_wait<1>();
        else                 cp_wait<0>();
        __syncthreads();
        if (kt+3 < KT){ LOAD_TILE_GU(kt+3, (kt+3)&3); cp_commit(); }

        int buf = kt & 3;
        unsigned baseA = smA + buf*AS_SZ*2;
        unsigned baseG = smG + buf*BS_SZ*2;
        unsigned baseU = smU + buf*BS_SZ*2;
        #pragma unroll
        for (int ks=0; ks<2; ks++){
            int k0 = ks*16;
            unsigned af[2][4], bg[4][4], bu[4][4];
            #pragma unroll
            for (int i=0;i<2;i++){
                int m0 = mw + i*16;
                ldsm4(af[i][0], af[i][1], af[i][2], af[i][3],
                      baseA + ((unsigned)(m0 + lrow)*AP + (k0 + lcol))*2);
            }
            #pragma unroll
            for (int j2=0;j2<4;j2++){
                int n0 = nw + j2*16;
                ldsm4t(bg[j2][0], bg[j2][1], bg[j2][2], bg[j2][3],
                       baseG + ((unsigned)(k0 + lrow)*BP + (n0 + lcol))*2);
                ldsm4t(bu[j2][0], bu[j2][1], bu[j2][2], bu[j2][3],
                       baseU + ((unsigned)(k0 + lrow)*BP + (n0 + lcol))*2);
            }
            #pragma unroll
            for (int i=0;i<2;i++){
                #pragma unroll
                for (int j=0;j<8;j++){
                    unsigned b2g[2], b2u[2];
                    b2g[0] = bg[j>>1][(j&1)*2+0]; b2g[1] = bg[j>>1][(j&1)*2+1];
                    b2u[0] = bu[j>>1][(j&1)*2+0]; b2u[1] = bu[j>>1][(j&1)*2+1];
                    mma_f16(accg[i][j], af[i], b2g);
                    mma_f16(accu[i][j], af[i], b2u);
                }
            }
        }
    }

    #pragma unroll
    for (int i=0;i<2;i++){
        #pragma unroll
        for (int j=0;j<8;j++){
            size_t row = (size_t)blockIdx.y*128 + mw + i*16 + g;
            size_t col = (size_t)blockIdx.x*128 + nw + j*8 + t*2;
            #pragma unroll
            for (int h2=0; h2<2; h2++){
                size_t rr = row + h2*8;
                float g0 = accg[i][j][h2*2+0], g1v = accg[i][j][h2*2+1];
                float u0 = accu[i][j][h2*2+0], u1 = accu[i][j][h2*2+1];
                __half* q = CH + rr*N + col;
                q[0] = __float2half(g0*(1.0f/(1.0f+expf(-g0)))*u0);
                q[1] = __float2half(g1v*(1.0f/(1.0f+expf(-g1v)))*u1);
            }
        }
    }
    #undef LOAD_TILE_GU
}

// ---------------- gate projections (fp16 y input) ----------------
__global__ void gates_kernel(const __half* __restrict__ y,
                             const float* __restrict__ Wi, const float* __restrict__ bi,
                             const float* __restrict__ Wf, const float* __restrict__ bf){
    int warp = (blockIdx.x*blockDim.x + threadIdx.x) >> 5;
    int lane = threadIdx.x & 31;
    if (warp >= RR) return;
    const __half* yr = y + (size_t)warp*DD;
    float si[8]={0,0,0,0,0,0,0,0}, sf[8]={0,0,0,0,0,0,0,0};
    for (int d=lane; d<DD; d+=32){
        float yv = __half2float(yr[d]);
        #pragma unroll
        for (int hh=0; hh<8; hh++){
            si[hh] += yv * Wi[d*HH+hh];
            sf[hh] += yv * Wf[d*HH+hh];
        }
    }
    #pragma unroll
    for (int hh=0; hh<8; hh++){
        #pragma unroll
        for (int o=16;o;o>>=1){
            si[hh]+=__shfl_xor_sync(~0u,si[hh],o);
            sf[hh]+=__shfl_xor_sync(~0u,sf[hh],o);
        }
    }
    if (lane==0){
        int b = warp >> 9, s = warp & 511;
        #pragma unroll
        for (int hh=0;hh<8;hh++){
            g_ig[((b*HH+hh)*SS)+s] = softcapf(si[hh]+bi[hh]);
            g_fg[((b*HH+hh)*SS)+s] = softcapf(sf[hh]+bf[hh]);
        }
    }
}

// ---------------- per-(b,h) prefix scan (warp-parallel) ----------------
__global__ void scan_kernel(){
    int bh = blockIdx.x;
    int lane = threadIdx.x;
    const float* ig = g_ig + bh*SS;
    const float* fg = g_fg + bh*SS;
    float bcv[16];
    float carry = 0.f;
    #pragma unroll
    for (int c=0;c<16;c++){
        int s = c*32 + lane;
        float lf = logsigf(fg[s]);
        #pragma unroll
        for (int o=1;o<32;o<<=1){
            float n = __shfl_up_sync(~0u, lf, o);
            if (lane >= o) lf += n;
        }
        float bc = carry + lf;
        bcv[c] = bc;
        g_bc[bh*SS+s] = bc;
        carry = __shfl_sync(~0u, bc, 31);
    }
    float carrym = -1e30f;
    #pragma unroll
    for (int c=0;c<16;c++){
        int s = c*32 + lane;
        float cv = ig[s] - bcv[c];
        #pragma unroll
        for (int o=1;o<32;o<<=1){
            float n = __shfl_up_sync(~0u, cv, o);
            if (lane >= o) cv = fmaxf(cv, n);
        }
        float cm = fmaxf(carrym, cv);
        g_mv[bh*SS+s] = bcv[c] + cm;
        carrym = __shfl_sync(~0u, cm, 31);
    }
}

// ---------------- mLSTM attention + fused per-head LN * mhn * og -> fp16 ----
__global__ __launch_bounds__(64) void attn_kernel(const float* __restrict__ mhn){
    __shared__ float4 Ks[64*8];   // 64 rows x 32 floats
    __shared__ float4 Vs[64*16];  // 64 rows x 64 floats
    __shared__ float bs_s[64], ig_s[64];
    int bh = blockIdx.y; int b = bh >> 3; int h = bh & 7;
    int tt = blockIdx.x;
    int tid = threadIdx.x;
    int t = tt*64 + tid;
    const float4* qp = (const float4*)(g_q + ((size_t)(b*SS)+t)*QKD + h*DQK);
    float4 q4[8];
    #pragma unroll
    for (int d=0;d<8;d++) q4[d] = qp[d];
    float bt = g_bc[bh*SS + t];
    float mt = g_mv[bh*SS + t];
    float4 acc[16];
    #pragma unroll
    for (int j=0;j<16;j++) acc[j] = make_float4(0.f,0.f,0.f,0.f);
    float ssum = 0.f;
    const float scale = 0.17677669529663687f;  // 1/sqrt(32)
    for (int st=0; st<=tt; st++){
        int s0 = st*64;
        #pragma unroll
        for (int ii=0; ii<8; ii++){
            int idx = tid + ii*64;
            int rr = idx >> 3, cc = idx & 7;
            Ks[idx] = *(const float4*)(g_k + ((size_t)(b*SS)+s0+rr)*QKD + h*DQK + cc*4);
        }
        #pragma unroll
        for (int ii=0; ii<16; ii++){
            int idx = tid + ii*64;
            int rr = idx >> 4, cc = idx & 15;
            Vs[idx] = *(const float4*)(g_v + ((size_t)(b*SS)+s0+rr)*VV + h*DV + cc*4);
        }
        bs_s[tid] = g_bc[bh*SS + s0 + tid];
        ig_s[tid] = g_ig[bh*SS + s0 + tid];
        __syncthreads();
        int smax = min(64, t - s0 + 1);
        for (int sl=0; sl<smax; sl++){
            const float4* kp = &Ks[sl*8];
            float dot=0.f;
            #pragma unroll
            for (int d=0;d<8;d++){
                float4 kv = kp[d];
                dot += q4[d].x*kv.x + q4[d].y*kv.y + q4[d].z*kv.z + q4[d].w*kv.w;
            }
            float w = dot * scale * __expf(bt - bs_s[sl] + ig_s[sl] - mt);
            ssum += w;
            const float4* vp = &Vs[sl*16];
            #pragma unroll
            for (int j=0;j<16;j++){
                float4 vv = vp[j];
                acc[j].x += w*vv.x; acc[j].y += w*vv.y;
                acc[j].z += w*vv.z; acc[j].w += w*vv.w;
            }
        }
        __syncthreads();
    }
    float nrm = fmaxf(fabsf(ssum), __expf(-mt));
    float inv = 1.0f/(nrm + EPS_RMS);
    // fused per-head layer norm over the 64 values this thread owns
    float mu = 0.f;
    #pragma unroll
    for (int j=0;j<16;j++) mu += acc[j].x + acc[j].y + acc[j].z + acc[j].w;
    mu = mu * inv * (1.0f/DV);
    float var = 0.f;
    #pragma unroll
    for (int j=0;j<16;j++){
        float4 a = acc[j];
        float d0=a.x*inv-mu, d1=a.y*inv-mu, d2=a.z*inv-mu, d3=a.w*inv-mu;
        var += d0*d0 + d1*d1 + d2*d2 + d3*d3;
    }
    float rs = rsqrtf(var*(1.0f/DV) + EPS_RMS);
    const float4* ogb = (const float4*)(g_og + ((size_t)(b*SS)+t)*VV + h*DV);
    const float4* mw4 = (const float4*)(mhn + h*DV);
    __half2* o2 = (__half2*)(g_hth + ((size_t)(b*SS)+t)*VV + h*DV);
    #pragma unroll
    for (int j=0;j<16;j++){
        float4 a = acc[j];
        float4 og4 = ogb[j];
        float4 w4 = mw4[j];
        float r0 = (a.x*inv-mu)*rs*w4.x*og4.x;
        float r1 = (a.y*inv-mu)*rs*w4.y*og4.y;
        float r2 = (a.z*inv-mu)*rs*w4.z*og4.z;
        float r3 = (a.w*inv-mu)*rs*w4.w*og4.w;
        o2[j*2+0] = __floats2half2_rn(r0, r1);
        o2[j*2+1] = __floats2half2_rn(r2, r3);
    }
}

// ---------------- final heads ----------------
__global__ void bn1_kernel(const float* __restrict__ gamma, const float* __restrict__ beta){
    int c = threadIdx.x; // 512
    float v[16]; float mu=0.f;
    #pragma unroll
    for (int b=0;b<16;b++){ v[b]=g_last[b*DD+c]; mu+=v[b]; }
    mu *= (1.0f/16.0f);
    float var=0.f;
    #pragma unroll
    for (int b=0;b<16;b++){ float d=v[b]-mu; var+=d*d; }
    var *= (1.0f/16.0f);
    float rs = rsqrtf(var + EPS_BN);
    #pragma unroll
    for (int b=0;b<16;b++) g_last[b*DD+c] = (v[b]-mu)*rs*gamma[c] + beta[c];
}
__global__ void fc1_kernel(const float* __restrict__ W, const float* __restrict__ bias){
    __shared__ float xr[512];
    int b = blockIdx.x; int j = threadIdx.x; // 256
    xr[j]     = g_last[b*DD + j];
    xr[j+256] = g_last[b*DD + j + 256];
    __syncthreads();
    float s=0.f;
    #pragma unroll 8
    for (int k=0;k<512;k++) s += xr[k]*W[k*256+j];
    g_o1[b*256+j] = s + bias[j];
}
__global__ void bn2gelu_kernel(const float* __restrict__ gamma, const float* __restrict__ beta){
    int j = threadIdx.x; // 256
    float v[16]; float mu=0.f;
    #pragma unroll
    for (int b=0;b<16;b++){ v[b]=g_o1[b*256+j]; mu+=v[b]; }
    mu *= (1.0f/16.0f);
    float var=0.f;
    #pragma unroll
    for (int b=0;b<16;b++){ float d=v[b]-mu; var+=d*d; }
    var *= (1.0f/16.0f);
    float rs = rsqrtf(var + EPS_BN);
    #pragma unroll
    for (int b=0;b<16;b++){
        float t = (v[b]-mu)*rs*gamma[j] + beta[j];
        g_o1[b*256+j] = 0.5f*t*(1.0f + erff(t*0.7071067811865475f));
    }
}
__global__ void fc2_kernel(const float* __restrict__ W, const float* __restrict__ bias){
    __shared__ float red[256];
    int b = blockIdx.x; int j = threadIdx.x;
    red[j] = g_o1[b*256+j]*W[j];
    __syncthreads();
    for (int o=128;o;o>>=1){ if(j<o) red[j]+=red[j+o]; __syncthreads(); }
    if (j==0) g_o2[b] = red[0] + bias[0];
}
__global__ void res_out_kernel(const float* __restrict__ resW, const float* __restrict__ resb,
                               float* __restrict__ out){
    int warp = (blockIdx.x*blockDim.x + threadIdx.x) >> 5;
    int lane = threadIdx.x & 31;
    if (warp >= RR) return;
    const float* xr = g_xn + (size_t)warp*DD;
    float s=0.f;
    for (int d=lane; d<DD; d+=32) s += xr[d]*resW[d];
    #pragma unroll
    for (int o=16;o;o>>=1) s += __shfl_xor_sync(~0u,s,o);
    if (lane==0){
        float v = s + resb[0] + g_o2[warp>>9];
        out[warp] = fmaxf(v, 0.f);
    }
}

// ---------------- host driver ----------------
extern "C" void kernel_launch(void* const* d_in, const int* in_sizes, int n_in,
                              void* d_out, int out_size){
    const float* x        = (const float*)d_in[0];
    const float* bng      = (const float*)d_in[1];
    const float* bnb      = (const float*)d_in[2];
    const float* norm1_w  = (const float*)d_in[3];
    const float* norm2_w  = (const float*)d_in[4];
    const float* Wq       = (const float*)d_in[5];
    const float* Wk       = (const float*)d_in[6];
    const float* Wv       = (const float*)d_in[7];
    const float* Wog      = (const float*)d_in[8];
    const float* Wi       = (const float*)d_in[9];
    const float* bi       = (const float*)d_in[10];
    const float* Wf       = (const float*)d_in[11];
    const float* bf       = (const float*)d_in[12];
    const float* mhn_w    = (const float*)d_in[13];
    const float* Wout     = (const float*)d_in[14];
    const float* Wg       = (const float*)d_in[15];
    const float* Wu       = (const float*)d_in[16];
    const float* Wd       = (const float*)d_in[17];
    const float* fnorm_w  = (const float*)d_in[18];
    const float* bn1_g    = (const float*)d_in[19];
    const float* bn1_b    = (const float*)d_in[20];
    const float* fc1_W    = (const float*)d_in[21];
    const float* fc1_b    = (const float*)d_in[22];
    const float* bn2_g    = (const float*)d_in[23];
    const float* bn2_b    = (const float*)d_in[24];
    const float* fc2_W    = (const float*)d_in[25];
    const float* fc2_b    = (const float*)d_in[26];
    const float* res_W    = (const float*)d_in[27];
    const float* res_b    = (const float*)d_in[28];
    float* out = (float*)d_out;

    float *p_q,*p_k,*p_v,*p_og,*p_h,*p_last;
    __half *p_wh,*p_yh,*p_hth,*p_g1h;
    cudaGetSymbolAddress((void**)&p_q,  g_q);
    cudaGetSymbolAddress((void**)&p_k,  g_k);
    cudaGetSymbolAddress((void**)&p_v,  g_v);
    cudaGetSymbolAddress((void**)&p_og, g_og);
    cudaGetSymbolAddress((void**)&p_h,  g_h);
    cudaGetSymbolAddress((void**)&p_last, g_last);
    cudaGetSymbolAddress((void**)&p_wh,  g_wh);
    cudaGetSymbolAddress((void**)&p_yh,  g_yh);
    cudaGetSymbolAddress((void**)&p_hth, g_hth);
    cudaGetSymbolAddress((void**)&p_g1h, g_g1h);

    cudaFuncSetAttribute((const void*)hgemm_kernel<0,0>, cudaFuncAttributeMaxDynamicSharedMemorySize, HG_SMEM);
    cudaFuncSetAttribute((const void*)hgemm_kernel<0,2>, cudaFuncAttributeMaxDynamicSharedMemorySize, HG_SMEM);
    cudaFuncSetAttribute((const void*)hgemm_kernel<1,1>, cudaFuncAttributeMaxDynamicSharedMemorySize, HG_SMEM);
    cudaFuncSetAttribute((const void*)hgemm_gu_kernel,   cudaFuncAttributeMaxDynamicSharedMemorySize, GU_SMEM);

    bnpart_conv_kernel<<<64 + (int)((TOTW + 1023)/1024), 256>>>(x, Wq, Wk, Wv, Wog, Wout, Wg, Wu, Wd);
    bn_final_kernel<<<1,512>>>();
    bnapply_rms_kernel<<<RR,256>>>(x, bng, bnb, norm1_w);

    for (int l=0;l<LL;l++){
        const __half* Wq_h  = p_wh + OFF_WQ  + (size_t)l*DD*QKD;
        const __half* Wk_h  = p_wh + OFF_WK  + (size_t)l*DD*QKD;
        const __half* Wv_h  = p_wh + OFF_WV  + (size_t)l*DD*VV;
        const __half* Wog_h = p_wh + OFF_WOG + (size_t)l*DD*VV;
        const __half* Wout_h= p_wh + OFF_WOUT+ (size_t)l*VV*DD;
        const __half* Wg_h  = p_wh + OFF_WG  + (size_t)l*DD*FF;
        const __half* Wu_h  = p_wh + OFF_WU  + (size_t)l*DD*FF;
        const __half* Wd_h  = p_wh + OFF_WD  + (size_t)l*FF*DD;
        const float* Wi_l = Wi + (size_t)l*DD*HH;
        const float* Wf_l = Wf + (size_t)l*DD*HH;

        if (l > 0)
            rmsnorm_h_kernel<<<RR,256>>>(p_h, norm1_w + l*DD, p_yh);

        // q & k (dual)
        hgemm_kernel<0,0><<<dim3(QKD/128, RR/128, 2),256,HG_SMEM>>>(p_yh, Wq_h, p_q, Wk_h, p_k, QKD, DD);
        // v (store) & og (sigmoid) (dual)
        hgemm_kernel<0,2><<<dim3(VV/128,  RR/128, 2),256,HG_SMEM>>>(p_yh, Wv_h, p_v, Wog_h, p_og, VV, DD);
        gates_kernel<<<RR/8,256>>>(p_yh, Wi_l, bi + l*HH, Wf_l, bf + l*HH);
        scan_kernel<<<BB*HH,32>>>();

        attn_kernel<<<dim3(SS/64, BB*HH),64>>>(mhn_w + l*VV);

        hgemm_kernel<1,1><<<dim3(DD/128, RR/128, 1),256,HG_SMEM>>>(p_hth, Wout_h, p_h, Wout_h, p_h, DD, VV);

        rmsnorm_h_kernel<<<RR,256>>>(p_h, norm2_w + l*DD, p_yh);
        hgemm_gu_kernel<<<dim3(FF/128, RR/128, 1),256,GU_SMEM>>>(p_yh, Wg_h, Wu_h, p_g1h, FF, DD);
        hgemm_kernel<1,1><<<dim3(DD/128, RR/128, 1),256,HG_SMEM>>>(p_g1h, Wd_h, p_h, Wd_h, p_h, DD, FF);
    }

    rmsnorm_f_kernel<<<BB,256>>>(p_h + (size_t)(SS-1)*DD, fnorm_w, p_last, (long)SS*DD);

    bn1_kernel<<<1,512>>>(bn1_g, bn1_b);
    fc1_kernel<<<BB,256>>>(fc1_W, fc1_b);
    bn2gelu_kernel<<<1,256>>>(bn2_g, bn2_b);
    fc2_kernel<<<BB,256>>>(fc2_W, fc2_b);
    res_out_kernel<<<RR/8,256>>>(res_W, res_b, out);
    (void)in_sizes; (void)n_in; (void)out_size;
}

// round 7
// speedup vs baseline: 1.2289x; 1.0297x over previous
#include <cuda_runtime.h>
#include <cuda_fp16.h>
#include <math.h>

// ---------------- problem constants ----------------
#define BB   16
#define SS   512
#define DD   512
#define LL   4
#define HH   8
#define QKD  256      // D/2
#define VV   512
#define FF   1408
#define RR   (BB*SS)      // 8192 rows
#define DQK  32
#define DV   64
#define EPS_RMS 1e-6f
#define EPS_BN  1e-5f
#define CAPV 15.0f

// weight half-buffer offsets (element counts, all layers concatenated)
#define OFF_WQ   0L
#define OFF_WK   524288L
#define OFF_WV   1048576L
#define OFF_WOG  2097152L
#define OFF_WOUT 3145728L
#define OFF_WG   4194304L
#define OFF_WU   7077888L
#define OFF_WD   9961472L
#define TOTW     12845056L

// ---------------- device scratch ----------------
__device__ float g_xn [RR*DD];
__device__ float g_h  [RR*DD];
__device__ float g_q  [RR*QKD];
__device__ float g_k  [RR*QKD];
__device__ float g_v  [RR*VV];
__device__ float g_og [RR*VV];
__device__ float g_ig [BB*HH*SS];
__device__ float g_fg [BB*HH*SS];
__device__ float g_bc [BB*HH*SS];
__device__ float g_mv [BB*HH*SS];
__device__ float g_part[64*1024];
__device__ float g_stats[1024];
__device__ float g_last[BB*DD];
__device__ float g_o1 [BB*256];
__device__ float g_o2 [BB];

__device__ __half g_wh  [TOTW];      // fp16 weights
__device__ __half g_yh  [RR*DD];     // fp16 rms-normed activations
__device__ __half g_hth [RR*VV];     // fp16 headnorm output
__device__ __half g_g1h [RR*FF];     // fp16 silu(g)*u

__device__ __forceinline__ float softcapf(float x){ return CAPV * tanhf(x * (1.0f/CAPV)); }
__device__ __forceinline__ float logsigf(float x){ return fminf(x,0.f) - log1pf(expf(-fabsf(x))); }

__device__ __forceinline__ void cp16(void* smem_dst, const void* gsrc){
    unsigned s = (unsigned)__cvta_generic_to_shared(smem_dst);
    asm volatile("cp.async.cg.shared.global [%0], [%1], 16;" :: "r"(s), "l"(gsrc));
}
__device__ __forceinline__ void cp_commit(){ asm volatile("cp.async.commit_group;" ::: "memory"); }
template<int NN> __device__ __forceinline__ void cp_wait(){ asm volatile("cp.async.wait_group %0;" :: "n"(NN) : "memory"); }

__device__ __forceinline__ void mma_f16(float* c, const unsigned* a, const unsigned* b){
    asm volatile("mma.sync.aligned.m16n8k16.row.col.f32.f16.f16.f32 "
        "{%0,%1,%2,%3}, {%4,%5,%6,%7}, {%8,%9}, {%0,%1,%2,%3};"
        : "+f"(c[0]), "+f"(c[1]), "+f"(c[2]), "+f"(c[3])
        : "r"(a[0]), "r"(a[1]), "r"(a[2]), "r"(a[3]), "r"(b[0]), "r"(b[1]));
}
__device__ __forceinline__ void ldsm4(unsigned& r0, unsigned& r1, unsigned& r2, unsigned& r3, unsigned addr){
    asm volatile("ldmatrix.sync.aligned.m8n8.x4.shared.b16 {%0,%1,%2,%3}, [%4];"
        : "=r"(r0), "=r"(r1), "=r"(r2), "=r"(r3) : "r"(addr));
}
__device__ __forceinline__ void ldsm4t(unsigned& r0, unsigned& r1, unsigned& r2, unsigned& r3, unsigned addr){
    asm volatile("ldmatrix.sync.aligned.m8n8.x4.trans.shared.b16 {%0,%1,%2,%3}, [%4];"
        : "=r"(r0), "=r"(r1), "=r"(r2), "=r"(r3) : "r"(addr));
}

// ---------------- bn partial + weight fp32->fp16 conversion (fused launch) ----
__global__ void bnpart_conv_kernel(const float* __restrict__ x,
        const float* __restrict__ Wq, const float* __restrict__ Wk,
        const float* __restrict__ Wv, const float* __restrict__ Wog,
        const float* __restrict__ Wout, const float* __restrict__ Wg,
        const float* __restrict__ Wu, const float* __restrict__ Wd){
    if (blockIdx.x < 64){
        int c0 = threadIdx.x, c1 = threadIdx.x + 256;
        float s0=0,s1=0,q0=0,q1=0;
        const float* base = x + (size_t)blockIdx.x * 128 * DD;
        for (int r=0;r<128;r++){
            float v0 = base[(size_t)r*DD + c0];
            float v1 = base[(size_t)r*DD + c1];
            s0+=v0; q0+=v0*v0; s1+=v1; q1+=v1*v1;
        }
        float* p = g_part + blockIdx.x*1024;
        p[c0]=s0; p[c1]=s1; p[512+c0]=q0; p[512+c1]=q1;
    } else {
        long e = (long)(blockIdx.x - 64)*1024 + (long)threadIdx.x*4;
        if (e >= TOTW) return;
        const float* src; long base;
        if      (e < OFF_WK)   { src = Wq;   base = OFF_WQ;  }
        else if (e < OFF_WV)   { src = Wk;   base = OFF_WK;  }
        else if (e < OFF_WOG)  { src = Wv;   base = OFF_WV;  }
        else if (e < OFF_WOUT) { src = Wog;  base = OFF_WOG; }
        else if (e < OFF_WG)   { src = Wout; base = OFF_WOUT;}
        else if (e < OFF_WU)   { src = Wg;   base = OFF_WG;  }
        else if (e < OFF_WD)   { src = Wu;   base = OFF_WU;  }
        else                   { src = Wd;   base = OFF_WD;  }
        float4 v = *reinterpret_cast<const float4*>(src + (e - base));
        __half2* d = reinterpret_cast<__half2*>(g_wh + e);
        d[0] = __floats2half2_rn(v.x, v.y);
        d[1] = __floats2half2_rn(v.z, v.w);
    }
}
__global__ void bn_final_kernel(){
    int c = threadIdx.x; // 512
    float s=0,q=0;
    for (int i=0;i<64;i++){ s += g_part[i*1024+c]; q += g_part[i*1024+512+c]; }
    float mu = s * (1.0f/RR);
    float var = q * (1.0f/RR) - mu*mu;
    g_stats[c] = mu;
    g_stats[512+c] = rsqrtf(var + EPS_BN);
}
// bn apply + rmsnorm(norm1_w[0]) fused
__global__ void bnapply_rms_kernel(const float* __restrict__ x,
                                   const float* __restrict__ gamma,
                                   const float* __restrict__ beta,
                                   const float* __restrict__ w){
    __shared__ float red[8];
    int r = blockIdx.x, t = threadIdx.x;
    int c0 = t, c1 = t + 256;
    const float* xr = x + (size_t)r*DD;
    float a = (xr[c0]-g_stats[c0])*g_stats[512+c0]*gamma[c0] + beta[c0];
    float b = (xr[c1]-g_stats[c1])*g_stats[512+c1]*gamma[c1] + beta[c1];
    g_xn[(size_t)r*DD+c0] = a; g_xn[(size_t)r*DD+c1] = b;
    g_h [(size_t)r*DD+c0] = a; g_h [(size_t)r*DD+c1] = b;
    float s = a*a + b*b;
    #pragma unroll
    for (int o=16;o;o>>=1) s += __shfl_xor_sync(~0u, s, o);
    if ((t&31)==0) red[t>>5]=s;
    __syncthreads();
    float tot = 0;
    #pragma unroll
    for (int i=0;i<8;i++) tot += red[i];
    float rs = rsqrtf(tot*(1.0f/DD) + EPS_RMS);
    g_yh[(size_t)r*DD+c0] = __float2half(a*rs*w[c0]);
    g_yh[(size_t)r*DD+c1] = __float2half(b*rs*w[c1]);
}

// ---------------- rms norm variants ----------------
__global__ void rmsnorm_h_kernel(const float* __restrict__ x, const float* __restrict__ w,
                                 __half* __restrict__ y){
    __shared__ float red[8];
    int r = blockIdx.x, t = threadIdx.x;
    const float* xr = x + (size_t)r*DD;
    float a = xr[t], b = xr[t+256];
    float s = a*a + b*b;
    #pragma unroll
    for (int o=16;o;o>>=1) s += __shfl_xor_sync(~0u, s, o);
    if ((t&31)==0) red[t>>5]=s;
    __syncthreads();
    float tot = 0;
    #pragma unroll
    for (int i=0;i<8;i++) tot += red[i];
    float rs = rsqrtf(tot*(1.0f/DD) + EPS_RMS);
    __half* yr = y + (size_t)r*DD;
    yr[t]     = __float2half(a*rs*w[t]);
    yr[t+256] = __float2half(b*rs*w[t+256]);
}
__global__ void rmsnorm_f_kernel(const float* __restrict__ x, const float* __restrict__ w,
                                 float* __restrict__ y, long xs){
    __shared__ float red[8];
    int r = blockIdx.x, t = threadIdx.x;
    const float* xr = x + (size_t)r*xs;
    float a = xr[t], b = xr[t+256];
    float s = a*a + b*b;
    #pragma unroll
    for (int o=16;o;o>>=1) s += __shfl_xor_sync(~0u, s, o);
    if ((t&31)==0) red[t>>5]=s;
    __syncthreads();
    float tot = 0;
    #pragma unroll
    for (int i=0;i<8;i++) tot += red[i];
    float rs = rsqrtf(tot*(1.0f/DD) + EPS_RMS);
    float* yr = y + (size_t)r*DD;
    yr[t]     = a*rs*w[t];
    yr[t+256] = b*rs*w[t+256];
}

// ---------------- fp16 tensor-core GEMM, BM=64 x BN=128 ----------------
// 4 warps of 32x64, 128 threads, K-tile 32, 3-stage cp.async.
#define AP 40
#define BP 136
#define AS_SZ (64*AP)    // 2560 halves
#define BS_SZ (32*BP)    // 4352 halves
#define NSTG 3
#define HG_SMEM (NSTG*(AS_SZ+BS_SZ)*2)   // 41472 B
#define GU_SMEM (NSTG*(AS_SZ+2*BS_SZ)*2) // 67584 B

// shared mainloop body pieces as macros
#define GEMM_PRE()                                                             \
    const int tid = threadIdx.x;                                               \
    const int lane = tid & 31;                                                 \
    const int wid = tid >> 5;                                                  \
    const int g = lane >> 2, t = lane & 3;                                     \
    const int mw = (wid >> 1) * 32;                                            \
    const int nw = (wid & 1) * 64;                                             \
    const int lrow = (lane & 7) + ((lane >> 3) & 1) * 8;                       \
    const int lcol = ((lane >> 3) & 2) * 4;

#define LOAD_A(kt, buf) do {                                                   \
    __half* Ad = As + (buf)*AS_SZ;                                             \
    _Pragma("unroll")                                                          \
    for (int ii=0; ii<2; ii++){                                                \
        int idx = tid + ii*128;                                                \
        int m = idx >> 2, c = idx & 3;                                         \
        cp16(Ad + m*AP + c*8, Ab + (size_t)m*K + (kt)*32 + c*8);               \
    }                                                                          \
} while(0)

#define LOAD_B(kt, buf, Bsb, Bb, N) do {                                       \
    __half* Bd = (Bsb) + (buf)*BS_SZ;                                          \
    _Pragma("unroll")                                                          \
    for (int ii=0; ii<4; ii++){                                                \
        int idx = tid + ii*128;                                                \
        int kr = idx >> 4, c = idx & 15;                                       \
        cp16(Bd + kr*BP + c*8, (Bb) + (size_t)((kt)*32+kr)*(N) + c*8);         \
    }                                                                          \
} while(0)

#define COMPUTE_TILE(buf, accA, smAbase, smBbase)                              \
    {                                                                          \
        unsigned baseA = (smAbase) + (buf)*AS_SZ*2;                            \
        unsigned baseB = (smBbase) + (buf)*BS_SZ*2;                            \
        _Pragma("unroll")                                                      \
        for (int ks=0; ks<2; ks++){                                            \
            int k0 = ks*16;                                                    \
            unsigned af[2][4], bf[4][4];                                       \
            _Pragma("unroll")                                                  \
            for (int i=0;i<2;i++){                                             \
                int m0 = mw + i*16;                                            \
                ldsm4(af[i][0], af[i][1], af[i][2], af[i][3],                  \
                      baseA + ((unsigned)(m0 + lrow)*AP + (k0 + lcol))*2);     \
            }                                                                  \
            _Pragma("unroll")                                                  \
            for (int j2=0;j2<4;j2++){                                          \
                int n0 = nw + j2*16;                                           \
                ldsm4t(bf[j2][0], bf[j2][1], bf[j2][2], bf[j2][3],             \
                       baseB + ((unsigned)(k0 + lrow)*BP + (n0 + lcol))*2);    \
            }                                                                  \
            _Pragma("unroll")                                                  \
            for (int i=0;i<2;i++){                                             \
                _Pragma("unroll")                                              \
                for (int j=0;j<8;j++){                                         \
                    unsigned b2[2];                                            \
                    b2[0] = bf[j>>1][(j&1)*2+0];                               \
                    b2[1] = bf[j>>1][(j&1)*2+1];                               \
                    mma_f16(accA[i][j], af[i], b2);                            \
                }                                                              \
            }                                                                  \
        }                                                                      \
    }

// merged projection GEMM: x-tile 0-1:q, 2-3:k, 4-7:v (store), 8-11:og (sigmoid)
__global__ __launch_bounds__(128) void proj_gemm_kernel(
        const __half* __restrict__ A,
        const __half* __restrict__ Wq_h, const __half* __restrict__ Wk_h,
        const __half* __restrict__ Wv_h, const __half* __restrict__ Wog_h){
    extern __shared__ __half sm[];
    __half* As = sm;
    __half* Bs = sm + NSTG*AS_SZ;
    const int K = DD;
    int xt = blockIdx.x;
    const __half* Bsrc; float* C; int NC, xl, epi;
    if (xt < 2)      { Bsrc = Wq_h;  C = g_q;  NC = QKD; xl = xt;   epi = 0; }
    else if (xt < 4) { Bsrc = Wk_h;  C = g_k;  NC = QKD; xl = xt-2; epi = 0; }
    else if (xt < 8) { Bsrc = Wv_h;  C = g_v;  NC = VV;  xl = xt-4; epi = 0; }
    else             { Bsrc = Wog_h; C = g_og; NC = VV;  xl = xt-8; epi = 2; }
    GEMM_PRE();
    const __half* Ab = A + (size_t)blockIdx.y * 64 * K;
    const __half* Bb = Bsrc + (size_t)xl * 128;
    const unsigned smA = (unsigned)__cvta_generic_to_shared(As);
    const unsigned smB = (unsigned)__cvta_generic_to_shared(Bs);

    float acc[2][8][4];
    #pragma unroll
    for (int i=0;i<2;i++)
        #pragma unroll
        for (int j=0;j<8;j++)
            #pragma unroll
            for (int c=0;c<4;c++) acc[i][j][c]=0.f;

    const int KT = K/32;
    LOAD_A(0,0); LOAD_B(0,0,Bs,Bb,NC); cp_commit();
    LOAD_A(1,1); LOAD_B(1,1,Bs,Bb,NC); cp_commit();
    for (int kt=0; kt<KT; kt++){
        if (kt+1 < KT) cp_wait<1>(); else cp_wait<0>();
        __syncthreads();
        if (kt+2 < KT){
            int nb = (kt+2)%NSTG;
            LOAD_A(kt+2, nb); LOAD_B(kt+2, nb, Bs, Bb, NC); cp_commit();
        }
        COMPUTE_TILE(kt%NSTG, acc, smA, smB);
        __syncthreads();
    }
    #pragma unroll
    for (int i=0;i<2;i++){
        #pragma unroll
        for (int j=0;j<8;j++){
            size_t row = (size_t)blockIdx.y*64 + mw + i*16 + g;
            size_t col = (size_t)xl*128 + nw + j*8 + t*2;
            #pragma unroll
            for (int h2=0; h2<2; h2++){
                size_t rr = row + h2*8;
                float v0 = acc[i][j][h2*2+0];
                float v1 = acc[i][j][h2*2+1];
                float* p = C + rr*NC + col;
                if (epi==0){ p[0]=v0; p[1]=v1; }
                else { p[0]=1.0f/(1.0f+expf(-v0)); p[1]=1.0f/(1.0f+expf(-v1)); }
            }
        }
    }
}

// generic GEMM: EPI 0 store fp32, 1 C+=
template<int EPI>
__global__ __launch_bounds__(128) void hgemm64_kernel(
        const __half* __restrict__ A,
        const __half* __restrict__ B, float* __restrict__ C,
        int N, int K){
    extern __shared__ __half sm[];
    __half* As = sm;
    __half* Bs = sm + NSTG*AS_SZ;
    GEMM_PRE();
    const __half* Ab = A + (size_t)blockIdx.y * 64 * K;
    const __half* Bb = B + (size_t)blockIdx.x * 128;
    const unsigned smA = (unsigned)__cvta_generic_to_shared(As);
    const unsigned smB = (unsigned)__cvta_generic_to_shared(Bs);

    float acc[2][8][4];
    #pragma unroll
    for (int i=0;i<2;i++)
        #pragma unroll
        for (int j=0;j<8;j++)
            #pragma unroll
            for (int c=0;c<4;c++) acc[i][j][c]=0.f;

    const int KT = K/32;
    LOAD_A(0,0); LOAD_B(0,0,Bs,Bb,N); cp_commit();
    LOAD_A(1,1); LOAD_B(1,1,Bs,Bb,N); cp_commit();
    for (int kt=0; kt<KT; kt++){
        if (kt+1 < KT) cp_wait<1>(); else cp_wait<0>();
        __syncthreads();
        if (kt+2 < KT){
            int nb = (kt+2)%NSTG;
            LOAD_A(kt+2, nb); LOAD_B(kt+2, nb, Bs, Bb, N); cp_commit();
        }
        COMPUTE_TILE(kt%NSTG, acc, smA, smB);
        __syncthreads();
    }
    #pragma unroll
    for (int i=0;i<2;i++){
        #pragma unroll
        for (int j=0;j<8;j++){
            size_t row = (size_t)blockIdx.y*64 + mw + i*16 + g;
            size_t col = (size_t)blockIdx.x*128 + nw + j*8 + t*2;
            #pragma unroll
            for (int h2=0; h2<2; h2++){
                size_t rr = row + h2*8;
                float v0 = acc[i][j][h2*2+0];
                float v1 = acc[i][j][h2*2+1];
                float* p = C + rr*N + col;
                if (EPI==0){ p[0]=v0; p[1]=v1; }
                else { p[0]+=v0; p[1]+=v1; }
            }
        }
    }
}

// fused G+U GEMM: out = silu(y@Wg) * (y@Wu), fp16 out
__global__ __launch_bounds__(128) void hgemm_gu_kernel(
        const __half* __restrict__ A,
        const __half* __restrict__ Bg, const __half* __restrict__ Bu,
        __half* __restrict__ CH, int N, int K){
    extern __shared__ __half sm[];
    __half* As  = sm;
    __half* Bgs = sm + NSTG*AS_SZ;
    __half* Bus = Bgs + NSTG*BS_SZ;
    GEMM_PRE();
    const __half* Ab  = A + (size_t)blockIdx.y * 64 * K;
    const __half* Bgb = Bg + (size_t)blockIdx.x * 128;
    const __half* Bub = Bu + (size_t)blockIdx.x * 128;
    const unsigned smA = (unsigned)__cvta_generic_to_shared(As);
    const unsigned smG = (unsigned)__cvta_generic_to_shared(Bgs);
    const unsigned smU = (unsigned)__cvta_generic_to_shared(Bus);

    float accg[2][8][4], accu[2][8][4];
    #pragma unroll
    for (int i=0;i<2;i++)
        #pragma unroll
        for (int j=0;j<8;j++)
            #pragma unroll
            for (int c=0;c<4;c++){ accg[i][j][c]=0.f; accu[i][j][c]=0.f; }

    const int KT = K/32;
    LOAD_A(0,0); LOAD_B(0,0,Bgs,Bgb,N); LOAD_B(0,0,Bus,Bub,N); cp_commit();
    LOAD_A(1,1); LOAD_B(1,1,Bgs,Bgb,N); LOAD_B(1,1,Bus,Bub,N); cp_commit();
    for (int kt=0; kt<KT; kt++){
        if (kt+1 < KT) cp_wait<1>(); else cp_wait<0>();
        __syncthreads();
        if (kt+2 < KT){
            int nb = (kt+2)%NSTG;
            LOAD_A(kt+2, nb);
            LOAD_B(kt+2, nb, Bgs, Bgb, N);
            LOAD_B(kt+2, nb, Bus, Bub, N);
            cp_commit();
        }
        COMPUTE_TILE(kt%NSTG, accg, smA, smG);
        COMPUTE_TILE(kt%NSTG, accu, smA, smU);
        __syncthreads();
    }
    #pragma unroll
    for (int i=0;i<2;i++){
        #pragma unroll
        for (int j=0;j<8;j++){
            size_t row = (size_t)blockIdx.y*64 + mw + i*16 + g;
            size_t col = (size_t)blockIdx.x*128 + nw + j*8 + t*2;
            #pragma unroll
            for (int h2=0; h2<2; h2++){
                size_t rr = row + h2*8;
                float g0 = accg[i][j][h2*2+0], g1v = accg[i][j][h2*2+1];
                float u0 = accu[i][j][h2*2+0], u1 = accu[i][j][h2*2+1];
                __half* q = CH + rr*N + col;
                q[0] = __float2half(g0*(1.0f/(1.0f+expf(-g0)))*u0);
                q[1] = __float2half(g1v*(1.0f/(1.0f+expf(-g1v)))*u1);
            }
        }
    }
}

// ---------------- gate projections (fp16 y input) ----------------
__global__ void gates_kernel(const __half* __restrict__ y,
                             const float* __restrict__ Wi, const float* __restrict__ bi,
                             const float* __restrict__ Wf, const float* __restrict__ bf){
    int warp = (blockIdx.x*blockDim.x + threadIdx.x) >> 5;
    int lane = threadIdx.x & 31;
    if (warp >= RR) return;
    const __half* yr = y + (size_t)warp*DD;
    float si[8]={0,0,0,0,0,0,0,0}, sf[8]={0,0,0,0,0,0,0,0};
    for (int d=lane; d<DD; d+=32){
        float yv = __half2float(yr[d]);
        #pragma unroll
        for (int hh=0; hh<8; hh++){
            si[hh] += yv * Wi[d*HH+hh];
            sf[hh] += yv * Wf[d*HH+hh];
        }
    }
    #pragma unroll
    for (int hh=0; hh<8; hh++){
        #pragma unroll
        for (int o=16;o;o>>=1){
            si[hh]+=__shfl_xor_sync(~0u,si[hh],o);
            sf[hh]+=__shfl_xor_sync(~0u,sf[hh],o);
        }
    }
    if (lane==0){
        int b = warp >> 9, s = warp & 511;
        #pragma unroll
        for (int hh=0;hh<8;hh++){
            g_ig[((b*HH+hh)*SS)+s] = softcapf(si[hh]+bi[hh]);
            g_fg[((b*HH+hh)*SS)+s] = softcapf(sf[hh]+bf[hh]);
        }
    }
}

// ---------------- per-(b,h) prefix scan (warp-parallel) ----------------
__global__ void scan_kernel(){
    int bh = blockIdx.x;
    int lane = threadIdx.x;
    const float* ig = g_ig + bh*SS;
    const float* fg = g_fg + bh*SS;
    float bcv[16];
    float carry = 0.f;
    #pragma unroll
    for (int c=0;c<16;c++){
        int s = c*32 + lane;
        float lf = logsigf(fg[s]);
        #pragma unroll
        for (int o=1;o<32;o<<=1){
            float n = __shfl_up_sync(~0u, lf, o);
            if (lane >= o) lf += n;
        }
        float bc = carry + lf;
        bcv[c] = bc;
        g_bc[bh*SS+s] = bc;
        carry = __shfl_sync(~0u, bc, 31);
    }
    float carrym = -1e30f;
    #pragma unroll
    for (int c=0;c<16;c++){
        int s = c*32 + lane;
        float cv = ig[s] - bcv[c];
        #pragma unroll
        for (int o=1;o<32;o<<=1){
            float n = __shfl_up_sync(~0u, cv, o);
            if (lane >= o) cv = fmaxf(cv, n);
        }
        float cm = fmaxf(carrym, cv);
        g_mv[bh*SS+s] = bcv[c] + cm;
        carrym = __shfl_sync(~0u, cm, 31);
    }
}

// ---------------- mLSTM attention + fused per-head LN * mhn * og -> fp16 ----
__global__ __launch_bounds__(64) void attn_kernel(const float* __restrict__ mhn){
    __shared__ float4 Ks[64*8];
    __shared__ float4 Vs[64*16];
    __shared__ float bs_s[64], ig_s[64];
    int bh = blockIdx.y; int b = bh >> 3; int h = bh & 7;
    int tt = blockIdx.x;
    int tid = threadIdx.x;
    int t = tt*64 + tid;
    const float4* qp = (const float4*)(g_q + ((size_t)(b*SS)+t)*QKD + h*DQK);
    float4 q4[8];
    #pragma unroll
    for (int d=0;d<8;d++) q4[d] = qp[d];
    float bt = g_bc[bh*SS + t];
    float mt = g_mv[bh*SS + t];
    float4 acc[16];
    #pragma unroll
    for (int j=0;j<16;j++) acc[j] = make_float4(0.f,0.f,0.f,0.f);
    float ssum = 0.f;
    const float scale = 0.17677669529663687f;
    for (int st=0; st<=tt; st++){
        int s0 = st*64;
        #pragma unroll
        for (int ii=0; ii<8; ii++){
            int idx = tid + ii*64;
            int rr = idx >> 3, cc = idx & 7;
            Ks[idx] = *(const float4*)(g_k + ((size_t)(b*SS)+s0+rr)*QKD + h*DQK + cc*4);
        }
        #pragma unroll
        for (int ii=0; ii<16; ii++){
            int idx = tid + ii*64;
            int rr = idx >> 4, cc = idx & 15;
            Vs[idx] = *(const float4*)(g_v + ((size_t)(b*SS)+s0+rr)*VV + h*DV + cc*4);
        }
        bs_s[tid] = g_bc[bh*SS + s0 + tid];
        ig_s[tid] = g_ig[bh*SS + s0 + tid];
        __syncthreads();
        int smax = min(64, t - s0 + 1);
        for (int sl=0; sl<smax; sl++){
            const float4* kp = &Ks[sl*8];
            float dot=0.f;
            #pragma unroll
            for (int d=0;d<8;d++){
                float4 kv = kp[d];
                dot += q4[d].x*kv.x + q4[d].y*kv.y + q4[d].z*kv.z + q4[d].w*kv.w;
            }
            float w = dot * scale * __expf(bt - bs_s[sl] + ig_s[sl] - mt);
            ssum += w;
            const float4* vp = &Vs[sl*16];
            #pragma unroll
            for (int j=0;j<16;j++){
                float4 vv = vp[j];
                acc[j].x += w*vv.x; acc[j].y += w*vv.y;
                acc[j].z += w*vv.z; acc[j].w += w*vv.w;
            }
        }
        __syncthreads();
    }
    float nrm = fmaxf(fabsf(ssum), __expf(-mt));
    float inv = 1.0f/(nrm + EPS_RMS);
    float mu = 0.f;
    #pragma unroll
    for (int j=0;j<16;j++) mu += acc[j].x + acc[j].y + acc[j].z + acc[j].w;
    mu = mu * inv * (1.0f/DV);
    float var = 0.f;
    #pragma unroll
    for (int j=0;j<16;j++){
        float4 a = acc[j];
        float d0=a.x*inv-mu, d1=a.y*inv-mu, d2=a.z*inv-mu, d3=a.w*inv-mu;
        var += d0*d0 + d1*d1 + d2*d2 + d3*d3;
    }
    float rs = rsqrtf(var*(1.0f/DV) + EPS_RMS);
    const float4* ogb = (const float4*)(g_og + ((size_t)(b*SS)+t)*VV + h*DV);
    const float4* mw4 = (const float4*)(mhn + h*DV);
    __half2* o2 = (__half2*)(g_hth + ((size_t)(b*SS)+t)*VV + h*DV);
    #pragma unroll
    for (int j=0;j<16;j++){
        float4 a = acc[j];
        float4 og4 = ogb[j];
        float4 w4 = mw4[j];
        float r0 = (a.x*inv-mu)*rs*w4.x*og4.x;
        float r1 = (a.y*inv-mu)*rs*w4.y*og4.y;
        float r2 = (a.z*inv-mu)*rs*w4.z*og4.z;
        float r3 = (a.w*inv-mu)*rs*w4.w*og4.w;
        o2[j*2+0] = __floats2half2_rn(r0, r1);
        o2[j*2+1] = __floats2half2_rn(r2, r3);
    }
}

// ---------------- final heads ----------------
__global__ void bn1_kernel(const float* __restrict__ gamma, const float* __restrict__ beta){
    int c = threadIdx.x;
    float v[16]; float mu=0.f;
    #pragma unroll
    for (int b=0;b<16;b++){ v[b]=g_last[b*DD+c]; mu+=v[b]; }
    mu *= (1.0f/16.0f);
    float var=0.f;
    #pragma unroll
    for (int b=0;b<16;b++){ float d=v[b]-mu; var+=d*d; }
    var *= (1.0f/16.0f);
    float rs = rsqrtf(var + EPS_BN);
    #pragma unroll
    for (int b=0;b<16;b++) g_last[b*DD+c] = (v[b]-mu)*rs*gamma[c] + beta[c];
}
__global__ void fc1_kernel(const float* __restrict__ W, const float* __restrict__ bias){
    __shared__ float xr[512];
    int b = blockIdx.x; int j = threadIdx.x;
    xr[j]     = g_last[b*DD + j];
    xr[j+256] = g_last[b*DD + j + 256];
    __syncthreads();
    float s=0.f;
    #pragma unroll 8
    for (int k=0;k<512;k++) s += xr[k]*W[k*256+j];
    g_o1[b*256+j] = s + bias[j];
}
__global__ void bn2gelu_kernel(const float* __restrict__ gamma, const float* __restrict__ beta){
    int j = threadIdx.x;
    float v[16]; float mu=0.f;
    #pragma unroll
    for (int b=0;b<16;b++){ v[b]=g_o1[b*256+j]; mu+=v[b]; }
    mu *= (1.0f/16.0f);
    float var=0.f;
    #pragma unroll
    for (int b=0;b<16;b++){ float d=v[b]-mu; var+=d*d; }
    var *= (1.0f/16.0f);
    float rs = rsqrtf(var + EPS_BN);
    #pragma unroll
    for (int b=0;b<16;b++){
        float t = (v[b]-mu)*rs*gamma[j] + beta[j];
        g_o1[b*256+j] = 0.5f*t*(1.0f + erff(t*0.7071067811865475f));
    }
}
__global__ void fc2_kernel(const float* __restrict__ W, const float* __restrict__ bias){
    __shared__ float red[256];
    int b = blockIdx.x; int j = threadIdx.x;
    red[j] = g_o1[b*256+j]*W[j];
    __syncthreads();
    for (int o=128;o;o>>=1){ if(j<o) red[j]+=red[j+o]; __syncthreads(); }
    if (j==0) g_o2[b] = red[0] + bias[0];
}
__global__ void res_out_kernel(const float* __restrict__ resW, const float* __restrict__ resb,
                               float* __restrict__ out){
    int warp = (blockIdx.x*blockDim.x + threadIdx.x) >> 5;
    int lane = threadIdx.x & 31;
    if (warp >= RR) return;
    const float* xr = g_xn + (size_t)warp*DD;
    float s=0.f;
    for (int d=lane; d<DD; d+=32) s += xr[d]*resW[d];
    #pragma unroll
    for (int o=16;o;o>>=1) s += __shfl_xor_sync(~0u,s,o);
    if (lane==0){
        float v = s + resb[0] + g_o2[warp>>9];
        out[warp] = fmaxf(v, 0.f);
    }
}

// ---------------- host driver ----------------
extern "C" void kernel_launch(void* const* d_in, const int* in_sizes, int n_in,
                              void* d_out, int out_size){
    const float* x        = (const float*)d_in[0];
    const float* bng      = (const float*)d_in[1];
    const float* bnb      = (const float*)d_in[2];
    const float* norm1_w  = (const float*)d_in[3];
    const float* norm2_w  = (const float*)d_in[4];
    const float* Wq       = (const float*)d_in[5];
    const float* Wk       = (const float*)d_in[6];
    const float* Wv       = (const float*)d_in[7];
    const float* Wog      = (const float*)d_in[8];
    const float* Wi       = (const float*)d_in[9];
    const float* bi       = (const float*)d_in[10];
    const float* Wf       = (const float*)d_in[11];
    const float* bf       = (const float*)d_in[12];
    const float* mhn_w    = (const float*)d_in[13];
    const float* Wout     = (const float*)d_in[14];
    const float* Wg       = (const float*)d_in[15];
    const float* Wu       = (const float*)d_in[16];
    const float* Wd       = (const float*)d_in[17];
    const float* fnorm_w  = (const float*)d_in[18];
    const float* bn1_g    = (const float*)d_in[19];
    const float* bn1_b    = (const float*)d_in[20];
    const float* fc1_W    = (const float*)d_in[21];
    const float* fc1_b    = (const float*)d_in[22];
    const float* bn2_g    = (const float*)d_in[23];
    const float* bn2_b    = (const float*)d_in[24];
    const float* fc2_W    = (const float*)d_in[25];
    const float* fc2_b    = (const float*)d_in[26];
    const float* res_W    = (const float*)d_in[27];
    const float* res_b    = (const float*)d_in[28];
    float* out = (float*)d_out;

    float *p_h,*p_last;
    __half *p_wh,*p_yh,*p_hth,*p_g1h;
    cudaGetSymbolAddress((void**)&p_h,  g_h);
    cudaGetSymbolAddress((void**)&p_last, g_last);
    cudaGetSymbolAddress((void**)&p_wh,  g_wh);
    cudaGetSymbolAddress((void**)&p_yh,  g_yh);
    cudaGetSymbolAddress((void**)&p_hth, g_hth);
    cudaGetSymbolAddress((void**)&p_g1h, g_g1h);

    cudaFuncSetAttribute((const void*)proj_gemm_kernel,  cudaFuncAttributeMaxDynamicSharedMemorySize, HG_SMEM);
    cudaFuncSetAttribute((const void*)hgemm64_kernel<1>, cudaFuncAttributeMaxDynamicSharedMemorySize, HG_SMEM);
    cudaFuncSetAttribute((const void*)hgemm_gu_kernel,   cudaFuncAttributeMaxDynamicSharedMemorySize, GU_SMEM);

    bnpart_conv_kernel<<<64 + (int)((TOTW + 1023)/1024), 256>>>(x, Wq, Wk, Wv, Wog, Wout, Wg, Wu, Wd);
    bn_final_kernel<<<1,512>>>();
    bnapply_rms_kernel<<<RR,256>>>(x, bng, bnb, norm1_w);

    for (int l=0;l<LL;l++){
        const __half* Wq_h  = p_wh + OFF_WQ  + (size_t)l*DD*QKD;
        const __half* Wk_h  = p_wh + OFF_WK  + (size_t)l*DD*QKD;
        const __half* Wv_h  = p_wh + OFF_WV  + (size_t)l*DD*VV;
        const __half* Wog_h = p_wh + OFF_WOG + (size_t)l*DD*VV;
        const __half* Wout_h= p_wh + OFF_WOUT+ (size_t)l*VV*DD;
        const __half* Wg_h  = p_wh + OFF_WG  + (size_t)l*DD*FF;
        const __half* Wu_h  = p_wh + OFF_WU  + (size_t)l*DD*FF;
        const __half* Wd_h  = p_wh + OFF_WD  + (size_t)l*FF*DD;
        const float* Wi_l = Wi + (size_t)l*DD*HH;
        const float* Wf_l = Wf + (size_t)l*DD*HH;

        if (l > 0)
            rmsnorm_h_kernel<<<RR,256>>>(p_h, norm1_w + l*DD, p_yh);

        // all four projections in ONE launch (1536 blocks)
        proj_gemm_kernel<<<dim3(12, RR/64), 128, HG_SMEM>>>(p_yh, Wq_h, Wk_h, Wv_h, Wog_h);
        gates_kernel<<<RR/8,256>>>(p_yh, Wi_l, bi + l*HH, Wf_l, bf + l*HH);
        scan_kernel<<<BB*HH,32>>>();

        attn_kernel<<<dim3(SS/64, BB*HH),64>>>(mhn_w + l*VV);

        hgemm64_kernel<1><<<dim3(DD/128, RR/64), 128, HG_SMEM>>>(p_hth, Wout_h, p_h, DD, VV);

        rmsnorm_h_kernel<<<RR,256>>>(p_h, norm2_w + l*DD, p_yh);
        hgemm_gu_kernel<<<dim3(FF/128, RR/64), 128, GU_SMEM>>>(p_yh, Wg_h, Wu_h, p_g1h, FF, DD);
        hgemm64_kernel<1><<<dim3(DD/128, RR/64), 128, HG_SMEM>>>(p_g1h, Wd_h, p_h, DD, FF);
    }

    rmsnorm_f_kernel<<<BB,256>>>(p_h + (size_t)(SS-1)*DD, fnorm_w, p_last, (long)SS*DD);

    bn1_kernel<<<1,512>>>(bn1_g, bn1_b);
    fc1_kernel<<<BB,256>>>(fc1_W, fc1_b);
    bn2gelu_kernel<<<1,256>>>(bn2_g, bn2_b);
    fc2_kernel<<<BB,256>>>(fc2_W, fc2_b);
    res_out_kernel<<<RR/8,256>>>(res_W, res_b, out);
    (void)in_sizes; (void)n_in; (void)out_size;
}

// round 8
// speedup vs baseline: 1.7888x; 1.4556x over previous
#include <cuda_runtime.h>
#include <cuda_fp16.h>
#include <math.h>

// ---------------- problem constants ----------------
#define BB   16
#define SS   512
#define DD   512
#define LL   4
#define HH   8
#define QKD  256      // D/2
#define VV   512
#define FF   1408
#define RR   (BB*SS)      // 8192 rows
#define DQK  32
#define DV   64
#define EPS_RMS 1e-6f
#define EPS_BN  1e-5f
#define CAPV 15.0f

// weight half-buffer offsets (element counts, all layers concatenated)
#define OFF_WQ   0L
#define OFF_WK   524288L
#define OFF_WV   1048576L
#define OFF_WOG  2097152L
#define OFF_WOUT 3145728L
#define OFF_WG   4194304L
#define OFF_WU   7077888L
#define OFF_WD   9961472L
#define TOTW     12845056L

// ---------------- device scratch ----------------
__device__ float g_xn [RR*DD];
__device__ float g_h  [RR*DD];
__device__ float g_og [RR*VV];
__device__ float g_ig [BB*HH*SS];
__device__ float g_fg [BB*HH*SS];
__device__ float g_bc [BB*HH*SS];
__device__ float g_mv [BB*HH*SS];
__device__ float g_part[64*1024];
__device__ float g_stats[1024];
__device__ float g_last[BB*DD];
__device__ float g_o1 [BB*256];
__device__ float g_o2 [BB];

__device__ __half g_wh  [TOTW];      // fp16 weights
__device__ __half g_yh  [RR*DD];     // fp16 rms-normed activations
__device__ __half g_hth [RR*VV];     // fp16 headnorm output
__device__ __half g_g1h [RR*FF];     // fp16 silu(g)*u
__device__ __half g_qh  [RR*QKD];
__device__ __half g_kh  [RR*QKD];
__device__ __half g_vh  [RR*VV];

__device__ __forceinline__ float softcapf(float x){ return CAPV * tanhf(x * (1.0f/CAPV)); }
__device__ __forceinline__ float logsigf(float x){ return fminf(x,0.f) - log1pf(expf(-fabsf(x))); }

__device__ __forceinline__ void cp16(void* smem_dst, const void* gsrc){
    unsigned s = (unsigned)__cvta_generic_to_shared(smem_dst);
    asm volatile("cp.async.cg.shared.global [%0], [%1], 16;" :: "r"(s), "l"(gsrc));
}
__device__ __forceinline__ void cp_commit(){ asm volatile("cp.async.commit_group;" ::: "memory"); }
template<int NN> __device__ __forceinline__ void cp_wait(){ asm volatile("cp.async.wait_group %0;" :: "n"(NN) : "memory"); }

__device__ __forceinline__ void mma_f16(float* c, const unsigned* a, const unsigned* b){
    asm volatile("mma.sync.aligned.m16n8k16.row.col.f32.f16.f16.f32 "
        "{%0,%1,%2,%3}, {%4,%5,%6,%7}, {%8,%9}, {%0,%1,%2,%3};"
        : "+f"(c[0]), "+f"(c[1]), "+f"(c[2]), "+f"(c[3])
        : "r"(a[0]), "r"(a[1]), "r"(a[2]), "r"(a[3]), "r"(b[0]), "r"(b[1]));
}
__device__ __forceinline__ void ldsm4(unsigned& r0, unsigned& r1, unsigned& r2, unsigned& r3, unsigned addr){
    asm volatile("ldmatrix.sync.aligned.m8n8.x4.shared.b16 {%0,%1,%2,%3}, [%4];"
        : "=r"(r0), "=r"(r1), "=r"(r2), "=r"(r3) : "r"(addr));
}
__device__ __forceinline__ void ldsm4t(unsigned& r0, unsigned& r1, unsigned& r2, unsigned& r3, unsigned addr){
    asm volatile("ldmatrix.sync.aligned.m8n8.x4.trans.shared.b16 {%0,%1,%2,%3}, [%4];"
        : "=r"(r0), "=r"(r1), "=r"(r2), "=r"(r3) : "r"(addr));
}
__device__ __forceinline__ unsigned f22h(float a, float b){
    __half2 h = __floats2half2_rn(a, b);
    return *reinterpret_cast<unsigned*>(&h);
}

// ---------------- bn partial + weight fp32->fp16 conversion (fused launch) ----
__global__ void bnpart_conv_kernel(const float* __restrict__ x,
        const float* __restrict__ Wq, const float* __restrict__ Wk,
        const float* __restrict__ Wv, const float* __restrict__ Wog,
        const float* __restrict__ Wout, const float* __restrict__ Wg,
        const float* __restrict__ Wu, const float* __restrict__ Wd){
    if (blockIdx.x < 64){
        int c0 = threadIdx.x, c1 = threadIdx.x + 256;
        float s0=0,s1=0,q0=0,q1=0;
        const float* base = x + (size_t)blockIdx.x * 128 * DD;
        for (int r=0;r<128;r++){
            float v0 = base[(size_t)r*DD + c0];
            float v1 = base[(size_t)r*DD + c1];
            s0+=v0; q0+=v0*v0; s1+=v1; q1+=v1*v1;
        }
        float* p = g_part + blockIdx.x*1024;
        p[c0]=s0; p[c1]=s1; p[512+c0]=q0; p[512+c1]=q1;
    } else {
        long e = (long)(blockIdx.x - 64)*1024 + (long)threadIdx.x*4;
        if (e >= TOTW) return;
        const float* src; long base;
        if      (e < OFF_WK)   { src = Wq;   base = OFF_WQ;  }
        else if (e < OFF_WV)   { src = Wk;   base = OFF_WK;  }
        else if (e < OFF_WOG)  { src = Wv;   base = OFF_WV;  }
        else if (e < OFF_WOUT) { src = Wog;  base = OFF_WOG; }
        else if (e < OFF_WG)   { src = Wout; base = OFF_WOUT;}
        else if (e < OFF_WU)   { src = Wg;   base = OFF_WG;  }
        else if (e < OFF_WD)   { src = Wu;   base = OFF_WU;  }
        else                   { src = Wd;   base = OFF_WD;  }
        float4 v = *reinterpret_cast<const float4*>(src + (e - base));
        __half2* d = reinterpret_cast<__half2*>(g_wh + e);
        d[0] = __floats2half2_rn(v.x, v.y);
        d[1] = __floats2half2_rn(v.z, v.w);
    }
}
__global__ void bn_final_kernel(){
    int c = threadIdx.x; // 512
    float s=0,q=0;
    for (int i=0;i<64;i++){ s += g_part[i*1024+c]; q += g_part[i*1024+512+c]; }
    float mu = s * (1.0f/RR);
    float var = q * (1.0f/RR) - mu*mu;
    g_stats[c] = mu;
    g_stats[512+c] = rsqrtf(var + EPS_BN);
}
// bn apply + rmsnorm(norm1_w[0]) fused
__global__ void bnapply_rms_kernel(const float* __restrict__ x,
                                   const float* __restrict__ gamma,
                                   const float* __restrict__ beta,
                                   const float* __restrict__ w){
    __shared__ float red[8];
    int r = blockIdx.x, t = threadIdx.x;
    int c0 = t, c1 = t + 256;
    const float* xr = x + (size_t)r*DD;
    float a = (xr[c0]-g_stats[c0])*g_stats[512+c0]*gamma[c0] + beta[c0];
    float b = (xr[c1]-g_stats[c1])*g_stats[512+c1]*gamma[c1] + beta[c1];
    g_xn[(size_t)r*DD+c0] = a; g_xn[(size_t)r*DD+c1] = b;
    g_h [(size_t)r*DD+c0] = a; g_h [(size_t)r*DD+c1] = b;
    float s = a*a + b*b;
    #pragma unroll
    for (int o=16;o;o>>=1) s += __shfl_xor_sync(~0u, s, o);
    if ((t&31)==0) red[t>>5]=s;
    __syncthreads();
    float tot = 0;
    #pragma unroll
    for (int i=0;i<8;i++) tot += red[i];
    float rs = rsqrtf(tot*(1.0f/DD) + EPS_RMS);
    g_yh[(size_t)r*DD+c0] = __float2half(a*rs*w[c0]);
    g_yh[(size_t)r*DD+c1] = __float2half(b*rs*w[c1]);
}

// ---------------- rms norm variants ----------------
__global__ void rmsnorm_h_kernel(const float* __restrict__ x, const float* __restrict__ w,
                                 __half* __restrict__ y){
    __shared__ float red[8];
    int r = blockIdx.x, t = threadIdx.x;
    const float* xr = x + (size_t)r*DD;
    float a = xr[t], b = xr[t+256];
    float s = a*a + b*b;
    #pragma unroll
    for (int o=16;o;o>>=1) s += __shfl_xor_sync(~0u, s, o);
    if ((t&31)==0) red[t>>5]=s;
    __syncthreads();
    float tot = 0;
    #pragma unroll
    for (int i=0;i<8;i++) tot += red[i];
    float rs = rsqrtf(tot*(1.0f/DD) + EPS_RMS);
    __half* yr = y + (size_t)r*DD;
    yr[t]     = __float2half(a*rs*w[t]);
    yr[t+256] = __float2half(b*rs*w[t+256]);
}
__global__ void rmsnorm_f_kernel(const float* __restrict__ x, const float* __restrict__ w,
                                 float* __restrict__ y, long xs){
    __shared__ float red[8];
    int r = blockIdx.x, t = threadIdx.x;
    const float* xr = x + (size_t)r*xs;
    float a = xr[t], b = xr[t+256];
    float s = a*a + b*b;
    #pragma unroll
    for (int o=16;o;o>>=1) s += __shfl_xor_sync(~0u, s, o);
    if ((t&31)==0) red[t>>5]=s;
    __syncthreads();
    float tot = 0;
    #pragma unroll
    for (int i=0;i<8;i++) tot += red[i];
    float rs = rsqrtf(tot*(1.0f/DD) + EPS_RMS);
    float* yr = y + (size_t)r*DD;
    yr[t]     = a*rs*w[t];
    yr[t+256] = b*rs*w[t+256];
}

// ---------------- fp16 tensor-core GEMM, BM=64 x BN=128 ----------------
#define AP 40
#define BP 136
#define AS_SZ (64*AP)    // 2560 halves
#define BS_SZ (32*BP)    // 4352 halves
#define NSTG 3
#define HG_SMEM (NSTG*(AS_SZ+BS_SZ)*2)   // 41472 B
#define GU_SMEM (NSTG*(AS_SZ+2*BS_SZ)*2) // 67584 B

#define GEMM_PRE()                                                             \
    const int tid = threadIdx.x;                                               \
    const int lane = tid & 31;                                                 \
    const int wid = tid >> 5;                                                  \
    const int g = lane >> 2, t = lane & 3;                                     \
    const int mw = (wid >> 1) * 32;                                            \
    const int nw = (wid & 1) * 64;                                             \
    const int lrow = (lane & 7) + ((lane >> 3) & 1) * 8;                       \
    const int lcol = ((lane >> 3) & 2) * 4;

#define LOAD_A(kt, buf) do {                                                   \
    __half* Ad = As + (buf)*AS_SZ;                                             \
    _Pragma("unroll")                                                          \
    for (int ii=0; ii<2; ii++){                                                \
        int idx = tid + ii*128;                                                \
        int m = idx >> 2, c = idx & 3;                                         \
        cp16(Ad + m*AP + c*8, Ab + (size_t)m*K + (kt)*32 + c*8);               \
    }                                                                          \
} while(0)

#define LOAD_B(kt, buf, Bsb, Bb, N) do {                                       \
    __half* Bd = (Bsb) + (buf)*BS_SZ;                                          \
    _Pragma("unroll")                                                          \
    for (int ii=0; ii<4; ii++){                                                \
        int idx = tid + ii*128;                                                \
        int kr = idx >> 4, c = idx & 15;                                       \
        cp16(Bd + kr*BP + c*8, (Bb) + (size_t)((kt)*32+kr)*(N) + c*8);         \
    }                                                                          \
} while(0)

#define COMPUTE_TILE(buf, accA, smAbase, smBbase)                              \
    {                                                                          \
        unsigned baseA = (smAbase) + (buf)*AS_SZ*2;                            \
        unsigned baseB = (smBbase) + (buf)*BS_SZ*2;                            \
        _Pragma("unroll")                                                      \
        for (int ks=0; ks<2; ks++){                                            \
            int k0 = ks*16;                                                    \
            unsigned af[2][4], bf[4][4];                                       \
            _Pragma("unroll")                                                  \
            for (int i=0;i<2;i++){                                             \
                int m0 = mw + i*16;                                            \
                ldsm4(af[i][0], af[i][1], af[i][2], af[i][3],                  \
                      baseA + ((unsigned)(m0 + lrow)*AP + (k0 + lcol))*2);     \
            }                                                                  \
            _Pragma("unroll")                                                  \
            for (int j2=0;j2<4;j2++){                                          \
                int n0 = nw + j2*16;                                           \
                ldsm4t(bf[j2][0], bf[j2][1], bf[j2][2], bf[j2][3],             \
                       baseB + ((unsigned)(k0 + lrow)*BP + (n0 + lcol))*2);    \
            }                                                                  \
            _Pragma("unroll")                                                  \
            for (int i=0;i<2;i++){                                             \
                _Pragma("unroll")                                              \
                for (int j=0;j<8;j++){                                         \
                    unsigned b2[2];                                            \
                    b2[0] = bf[j>>1][(j&1)*2+0];                               \
                    b2[1] = bf[j>>1][(j&1)*2+1];                               \
                    mma_f16(accA[i][j], af[i], b2);                            \
                }                                                              \
            }                                                                  \
        }                                                                      \
    }

// merged projection GEMM: x-tile 0-1:q, 2-3:k, 4-7:v (fp16 out), 8-11:og (sigmoid fp32)
__global__ __launch_bounds__(128) void proj_gemm_kernel(
        const __half* __restrict__ A,
        const __half* __restrict__ Wq_h, const __half* __restrict__ Wk_h,
        const __half* __restrict__ Wv_h, const __half* __restrict__ Wog_h){
    extern __shared__ __half sm[];
    __half* As = sm;
    __half* Bs = sm + NSTG*AS_SZ;
    const int K = DD;
    int xt = blockIdx.x;
    const __half* Bsrc; __half* CH = nullptr; float* CF = nullptr; int NC, xl, epi;
    if (xt < 2)      { Bsrc = Wq_h;  CH = g_qh; NC = QKD; xl = xt;   epi = 0; }
    else if (xt < 4) { Bsrc = Wk_h;  CH = g_kh; NC = QKD; xl = xt-2; epi = 0; }
    else if (xt < 8) { Bsrc = Wv_h;  CH = g_vh; NC = VV;  xl = xt-4; epi = 0; }
    else             { Bsrc = Wog_h; CF = g_og; NC = VV;  xl = xt-8; epi = 2; }
    GEMM_PRE();
    const __half* Ab = A + (size_t)blockIdx.y * 64 * K;
    const __half* Bb = Bsrc + (size_t)xl * 128;
    const unsigned smA = (unsigned)__cvta_generic_to_shared(As);
    const unsigned smB = (unsigned)__cvta_generic_to_shared(Bs);

    float acc[2][8][4];
    #pragma unroll
    for (int i=0;i<2;i++)
        #pragma unroll
        for (int j=0;j<8;j++)
            #pragma unroll
            for (int c=0;c<4;c++) acc[i][j][c]=0.f;

    const int KT = K/32;
    LOAD_A(0,0); LOAD_B(0,0,Bs,Bb,NC); cp_commit();
    LOAD_A(1,1); LOAD_B(1,1,Bs,Bb,NC); cp_commit();
    for (int kt=0; kt<KT; kt++){
        if (kt+1 < KT) cp_wait<1>(); else cp_wait<0>();
        __syncthreads();
        if (kt+2 < KT){
            int nb = (kt+2)%NSTG;
            LOAD_A(kt+2, nb); LOAD_B(kt+2, nb, Bs, Bb, NC); cp_commit();
        }
        COMPUTE_TILE(kt%NSTG, acc, smA, smB);
        __syncthreads();
    }
    #pragma unroll
    for (int i=0;i<2;i++){
        #pragma unroll
        for (int j=0;j<8;j++){
            size_t row = (size_t)blockIdx.y*64 + mw + i*16 + g;
            size_t col = (size_t)xl*128 + nw + j*8 + t*2;
            #pragma unroll
            for (int h2=0; h2<2; h2++){
                size_t rr = row + h2*8;
                float v0 = acc[i][j][h2*2+0];
                float v1 = acc[i][j][h2*2+1];
                if (epi==0){
                    *reinterpret_cast<__half2*>(CH + rr*NC + col) = __floats2half2_rn(v0, v1);
                } else {
                    float* p = CF + rr*NC + col;
                    p[0]=1.0f/(1.0f+expf(-v0)); p[1]=1.0f/(1.0f+expf(-v1));
                }
            }
        }
    }
}

// generic GEMM: EPI 0 store fp32, 1 C+=
template<int EPI>
__global__ __launch_bounds__(128) void hgemm64_kernel(
        const __half* __restrict__ A,
        const __half* __restrict__ B, float* __restrict__ C,
        int N, int K){
    extern __shared__ __half sm[];
    __half* As = sm;
    __half* Bs = sm + NSTG*AS_SZ;
    GEMM_PRE();
    const __half* Ab = A + (size_t)blockIdx.y * 64 * K;
    const __half* Bb = B + (size_t)blockIdx.x * 128;
    const unsigned smA = (unsigned)__cvta_generic_to_shared(As);
    const unsigned smB = (unsigned)__cvta_generic_to_shared(Bs);

    float acc[2][8][4];
    #pragma unroll
    for (int i=0;i<2;i++)
        #pragma unroll
        for (int j=0;j<8;j++)
            #pragma unroll
            for (int c=0;c<4;c++) acc[i][j][c]=0.f;

    const int KT = K/32;
    LOAD_A(0,0); LOAD_B(0,0,Bs,Bb,N); cp_commit();
    LOAD_A(1,1); LOAD_B(1,1,Bs,Bb,N); cp_commit();
    for (int kt=0; kt<KT; kt++){
        if (kt+1 < KT) cp_wait<1>(); else cp_wait<0>();
        __syncthreads();
        if (kt+2 < KT){
            int nb = (kt+2)%NSTG;
            LOAD_A(kt+2, nb); LOAD_B(kt+2, nb, Bs, Bb, N); cp_commit();
        }
        COMPUTE_TILE(kt%NSTG, acc, smA, smB);
        __syncthreads();
    }
    #pragma unroll
    for (int i=0;i<2;i++){
        #pragma unroll
        for (int j=0;j<8;j++){
            size_t row = (size_t)blockIdx.y*64 + mw + i*16 + g;
            size_t col = (size_t)blockIdx.x*128 + nw + j*8 + t*2;
            #pragma unroll
            for (int h2=0; h2<2; h2++){
                size_t rr = row + h2*8;
                float v0 = acc[i][j][h2*2+0];
                float v1 = acc[i][j][h2*2+1];
                float* p = C + rr*N + col;
                if (EPI==0){ p[0]=v0; p[1]=v1; }
                else { p[0]+=v0; p[1]+=v1; }
            }
        }
    }
}

// fused G+U GEMM: out = silu(y@Wg) * (y@Wu), fp16 out
__global__ __launch_bounds__(128) void hgemm_gu_kernel(
        const __half* __restrict__ A,
        const __half* __restrict__ Bg, const __half* __restrict__ Bu,
        __half* __restrict__ CH, int N, int K){
    extern __shared__ __half sm[];
    __half* As  = sm;
    __half* Bgs = sm + NSTG*AS_SZ;
    __half* Bus = Bgs + NSTG*BS_SZ;
    GEMM_PRE();
    const __half* Ab  = A + (size_t)blockIdx.y * 64 * K;
    const __half* Bgb = Bg + (size_t)blockIdx.x * 128;
    const __half* Bub = Bu + (size_t)blockIdx.x * 128;
    const unsigned smA = (unsigned)__cvta_generic_to_shared(As);
    const unsigned smG = (unsigned)__cvta_generic_to_shared(Bgs);
    const unsigned smU = (unsigned)__cvta_generic_to_shared(Bus);

    float accg[2][8][4], accu[2][8][4];
    #pragma unroll
    for (int i=0;i<2;i++)
        #pragma unroll
        for (int j=0;j<8;j++)
            #pragma unroll
            for (int c=0;c<4;c++){ accg[i][j][c]=0.f; accu[i][j][c]=0.f; }

    const int KT = K/32;
    LOAD_A(0,0); LOAD_B(0,0,Bgs,Bgb,N); LOAD_B(0,0,Bus,Bub,N); cp_commit();
    LOAD_A(1,1); LOAD_B(1,1,Bgs,Bgb,N); LOAD_B(1,1,Bus,Bub,N); cp_commit();
    for (int kt=0; kt<KT; kt++){
        if (kt+1 < KT) cp_wait<1>(); else cp_wait<0>();
        __syncthreads();
        if (kt+2 < KT){
            int nb = (kt+2)%NSTG;
            LOAD_A(kt+2, nb);
            LOAD_B(kt+2, nb, Bgs, Bgb, N);
            LOAD_B(kt+2, nb, Bus, Bub, N);
            cp_commit();
        }
        COMPUTE_TILE(kt%NSTG, accg, smA, smG);
        COMPUTE_TILE(kt%NSTG, accu, smA, smU);
        __syncthreads();
    }
    #pragma unroll
    for (int i=0;i<2;i++){
        #pragma unroll
        for (int j=0;j<8;j++){
            size_t row = (size_t)blockIdx.y*64 + mw + i*16 + g;
            size_t col = (size_t)blockIdx.x*128 + nw + j*8 + t*2;
            #pragma unroll
            for (int h2=0; h2<2; h2++){
                size_t rr = row + h2*8;
                float g0 = accg[i][j][h2*2+0], g1v = accg[i][j][h2*2+1];
                float u0 = accu[i][j][h2*2+0], u1 = accu[i][j][h2*2+1];
                __half* q = CH + rr*N + col;
                q[0] = __float2half(g0*(1.0f/(1.0f+expf(-g0)))*u0);
                q[1] = __float2half(g1v*(1.0f/(1.0f+expf(-g1v)))*u1);
            }
        }
    }
}

// ---------------- gate projections (fp16 y input) ----------------
__global__ void gates_kernel(const __half* __restrict__ y,
                             const float* __restrict__ Wi, const float* __restrict__ bi,
                             const float* __restrict__ Wf, const float* __restrict__ bf){
    int warp = (blockIdx.x*blockDim.x + threadIdx.x) >> 5;
    int lane = threadIdx.x & 31;
    if (warp >= RR) return;
    const __half* yr = y + (size_t)warp*DD;
    float si[8]={0,0,0,0,0,0,0,0}, sf[8]={0,0,0,0,0,0,0,0};
    for (int d=lane; d<DD; d+=32){
        float yv = __half2float(yr[d]);
        #pragma unroll
        for (int hh=0; hh<8; hh++){
            si[hh] += yv * Wi[d*HH+hh];
            sf[hh] += yv * Wf[d*HH+hh];
        }
    }
    #pragma unroll
    for (int hh=0; hh<8; hh++){
        #pragma unroll
        for (int o=16;o;o>>=1){
            si[hh]+=__shfl_xor_sync(~0u,si[hh],o);
            sf[hh]+=__shfl_xor_sync(~0u,sf[hh],o);
        }
    }
    if (lane==0){
        int b = warp >> 9, s = warp & 511;
        #pragma unroll
        for (int hh=0;hh<8;hh++){
            g_ig[((b*HH+hh)*SS)+s] = softcapf(si[hh]+bi[hh]);
            g_fg[((b*HH+hh)*SS)+s] = softcapf(sf[hh]+bf[hh]);
        }
    }
}

// ---------------- per-(b,h) prefix scan (warp-parallel) ----------------
__global__ void scan_kernel(){
    int bh = blockIdx.x;
    int lane = threadIdx.x;
    const float* ig = g_ig + bh*SS;
    const float* fg = g_fg + bh*SS;
    float bcv[16];
    float carry = 0.f;
    #pragma unroll
    for (int c=0;c<16;c++){
        int s = c*32 + lane;
        float lf = logsigf(fg[s]);
        #pragma unroll
        for (int o=1;o<32;o<<=1){
            float n = __shfl_up_sync(~0u, lf, o);
            if (lane >= o) lf += n;
        }
        float bc = carry + lf;
        bcv[c] = bc;
        g_bc[bh*SS+s] = bc;
        carry = __shfl_sync(~0u, bc, 31);
    }
    float carrym = -1e30f;
    #pragma unroll
    for (int c=0;c<16;c++){
        int s = c*32 + lane;
        float cv = ig[s] - bcv[c];
        #pragma unroll
        for (int o=1;o<32;o<<=1){
            float n = __shfl_up_sync(~0u, cv, o);
            if (lane >= o) cv = fmaxf(cv, n);
        }
        float cm = fmaxf(carrym, cv);
        g_mv[bh*SS+s] = bcv[c] + cm;
        carrym = __shfl_sync(~0u, cm, 31);
    }
}

// ---------------- tensor-core mLSTM attention + fused headnorm ----------------
// block: (t-tile tt, bh). 4 warps, warp handles 16 t-rows. fp16 q/k/v, fp32 S/O accum.
#define QKP 40   // Q/K smem pitch (halves)
#define VVP 72   // V smem pitch (halves)
__global__ __launch_bounds__(128) void attn_kernel(const float* __restrict__ mhn){
    __shared__ __half Qs[64*QKP];
    __shared__ __half Ks[64*QKP];
    __shared__ __half Vs[64*VVP];
    __shared__ float bs_s[64], ig_s[64];
    int bh = blockIdx.y; int b = bh >> 3; int h = bh & 7;
    int tt = blockIdx.x;
    int tid = threadIdx.x, lane = tid & 31, wid = tid >> 5;
    int g = lane >> 2, t = lane & 3;
    int mw = wid * 16;
    const int lrow = (lane & 7) + ((lane >> 3) & 1) * 8;
    const int lcol = ((lane >> 3) & 2) * 4;
    const unsigned sQ = (unsigned)__cvta_generic_to_shared(Qs);
    const unsigned sK = (unsigned)__cvta_generic_to_shared(Ks);
    const unsigned sV = (unsigned)__cvta_generic_to_shared(Vs);
    const float scale = 0.17677669529663687f;  // 1/sqrt(32)

    // load Q tile: 64 rows x 32 halves
    #pragma unroll
    for (int ii=0; ii<2; ii++){
        int idx = tid + ii*128;
        int r = idx >> 2, c = (idx & 3) * 8;
        cp16(Qs + r*QKP + c, g_qh + ((size_t)(b*SS) + tt*64 + r)*QKD + h*DQK + c);
    }
    cp_commit();

    int r0 = tt*64 + mw + g, r1 = r0 + 8;
    float bt0 = g_bc[bh*SS + r0], bt1 = g_bc[bh*SS + r1];
    float mt0 = g_mv[bh*SS + r0], mt1 = g_mv[bh*SS + r1];

    float co[8][4];
    #pragma unroll
    for (int j=0;j<8;j++)
        #pragma unroll
        for (int c=0;c<4;c++) co[j][c]=0.f;
    float ssum0 = 0.f, ssum1 = 0.f;

    cp_wait<0>();
    __syncthreads();
    unsigned aq[2][4];
    #pragma unroll
    for (int ks=0; ks<2; ks++)
        ldsm4(aq[ks][0], aq[ks][1], aq[ks][2], aq[ks][3],
              sQ + ((unsigned)(mw + lrow)*QKP + ks*16 + lcol)*2);

    for (int st=0; st<=tt; st++){
        int s0 = st*64;
        #pragma unroll
        for (int ii=0; ii<2; ii++){
            int idx = tid + ii*128;
            int r = idx >> 2, c = (idx & 3) * 8;
            cp16(Ks + r*QKP + c, g_kh + ((size_t)(b*SS) + s0 + r)*QKD + h*DQK + c);
        }
        #pragma unroll
        for (int ii=0; ii<4; ii++){
            int idx = tid + ii*128;
            int r = idx >> 3, c = (idx & 7) * 8;
            cp16(Vs + r*VVP + c, g_vh + ((size_t)(b*SS) + s0 + r)*VV + h*DV + c);
        }
        if (tid < 64){
            bs_s[tid] = g_bc[bh*SS + s0 + tid];
            ig_s[tid] = g_ig[bh*SS + s0 + tid];
        }
        cp_commit(); cp_wait<0>();
        __syncthreads();

        // S = Q K^T  (m16 x n64, k32)
        float cs[8][4];
        #pragma unroll
        for (int j=0;j<8;j++)
            #pragma unroll
            for (int c=0;c<4;c++) cs[j][c]=0.f;
        #pragma unroll
        for (int ks=0; ks<2; ks++){
            unsigned bk[4][4];
            #pragma unroll
            for (int j2=0;j2<4;j2++)
                ldsm4(bk[j2][0], bk[j2][1], bk[j2][2], bk[j2][3],
                      sK + ((unsigned)(j2*16 + lrow)*QKP + ks*16 + lcol)*2);
            #pragma unroll
            for (int j=0;j<8;j++){
                unsigned b2[2];
                b2[0] = bk[j>>1][(j&1)];
                b2[1] = bk[j>>1][(j&1)+2];
                mma_f16(cs[j], aq[ks], b2);
            }
        }
        // decay, mask, ssum
        bool full = (st < tt);
        #pragma unroll
        for (int j=0;j<8;j++){
            int c0 = j*8 + 2*t, c1 = c0 + 1;
            float a0 = bs_s[c0] - ig_s[c0];   // subtractand
            float a1 = bs_s[c1] - ig_s[c1];
            float e00 = (full || (s0+c0 <= r0)) ? __expf(bt0 - a0 - mt0) : 0.f;
            float e10 = (full || (s0+c1 <= r0)) ? __expf(bt0 - a1 - mt0) : 0.f;
            float e01 = (full || (s0+c0 <= r1)) ? __expf(bt1 - a0 - mt1) : 0.f;
            float e11 = (full || (s0+c1 <= r1)) ? __expf(bt1 - a1 - mt1) : 0.f;
            cs[j][0] = cs[j][0]*scale*e00;  ssum0 += cs[j][0];
            cs[j][1] = cs[j][1]*scale*e10;  ssum0 += cs[j][1];
            cs[j][2] = cs[j][2]*scale*e01;  ssum1 += cs[j][2];
            cs[j][3] = cs[j][3]*scale*e11;  ssum1 += cs[j][3];
        }
        // O += P V  (k = s, 4 k16 steps)
        #pragma unroll
        for (int kk=0; kk<4; kk++){
            unsigned ap[4];
            ap[0] = f22h(cs[2*kk][0],   cs[2*kk][1]);
            ap[1] = f22h(cs[2*kk][2],   cs[2*kk][3]);
            ap[2] = f22h(cs[2*kk+1][0], cs[2*kk+1][1]);
            ap[3] = f22h(cs[2*kk+1][2], cs[2*kk+1][3]);
            unsigned bv[4][4];
            #pragma unroll
            for (int j2=0;j2<4;j2++)
                ldsm4t(bv[j2][0], bv[j2][1], bv[j2][2], bv[j2][3],
                       sV + ((unsigned)(kk*16 + lrow)*VVP + j2*16 + lcol)*2);
            #pragma unroll
            for (int j=0;j<8;j++){
                unsigned b2[2];
                b2[0] = bv[j>>1][(j&1)*2+0];
                b2[1] = bv[j>>1][(j&1)*2+1];
                mma_f16(co[j], ap, b2);
            }
        }
        __syncthreads();
    }

    // row norms: reduce ssum across quad (lanes 4g..4g+3)
    ssum0 += __shfl_xor_sync(~0u, ssum0, 1); ssum0 += __shfl_xor_sync(~0u, ssum0, 2);
    ssum1 += __shfl_xor_sync(~0u, ssum1, 1); ssum1 += __shfl_xor_sync(~0u, ssum1, 2);
    float inv0 = 1.0f/(fmaxf(fabsf(ssum0), __expf(-mt0)) + EPS_RMS);
    float inv1 = 1.0f/(fmaxf(fabsf(ssum1), __expf(-mt1)) + EPS_RMS);

    // fused per-head LN over 64 cols (quad reductions)
    float mu0=0.f, mu1=0.f;
    #pragma unroll
    for (int j=0;j<8;j++){ mu0 += co[j][0]+co[j][1]; mu1 += co[j][2]+co[j][3]; }
    mu0 += __shfl_xor_sync(~0u, mu0, 1); mu0 += __shfl_xor_sync(~0u, mu0, 2);
    mu1 += __shfl_xor_sync(~0u, mu1, 1); mu1 += __shfl_xor_sync(~0u, mu1, 2);
    mu0 *= inv0 * (1.0f/DV);
    mu1 *= inv1 * (1.0f/DV);
    float var0=0.f, var1=0.f;
    #pragma unroll
    for (int j=0;j<8;j++){
        float d0 = co[j][0]*inv0 - mu0, d1 = co[j][1]*inv0 - mu0;
        float d2 = co[j][2]*inv1 - mu1, d3 = co[j][3]*inv1 - mu1;
        var0 += d0*d0 + d1*d1; var1 += d2*d2 + d3*d3;
    }
    var0 += __shfl_xor_sync(~0u, var0, 1); var0 += __shfl_xor_sync(~0u, var0, 2);
    var1 += __shfl_xor_sync(~0u, var1, 1); var1 += __shfl_xor_sync(~0u, var1, 2);
    float rs0 = rsqrtf(var0*(1.0f/DV) + EPS_RMS);
    float rs1 = rsqrtf(var1*(1.0f/DV) + EPS_RMS);

    size_t rg0 = (size_t)(b*SS) + r0;
    size_t rg1 = (size_t)(b*SS) + r1;
    #pragma unroll
    for (int j=0;j<8;j++){
        int colh = h*DV + j*8 + 2*t;
        float2 w2 = *reinterpret_cast<const float2*>(mhn + colh);
        float2 og0 = *reinterpret_cast<const float2*>(g_og + rg0*VV + colh);
        float2 og1 = *reinterpret_cast<const float2*>(g_og + rg1*VV + colh);
        float o00 = (co[j][0]*inv0 - mu0)*rs0*w2.x*og0.x;
        float o01 = (co[j][1]*inv0 - mu0)*rs0*w2.y*og0.y;
        float o10 = (co[j][2]*inv1 - mu1)*rs1*w2.x*og1.x;
        float o11 = (co[j][3]*inv1 - mu1)*rs1*w2.y*og1.y;
        *reinterpret_cast<__half2*>(g_hth + rg0*VV + colh) = __floats2half2_rn(o00, o01);
        *reinterpret_cast<__half2*>(g_hth + rg1*VV + colh) = __floats2half2_rn(o10, o11);
    }
}

// ---------------- final heads ----------------
__global__ void bn1_kernel(const float* __restrict__ gamma, const float* __restrict__ beta){
    int c = threadIdx.x;
    float v[16]; float mu=0.f;
    #pragma unroll
    for (int b=0;b<16;b++){ v[b]=g_last[b*DD+c]; mu+=v[b]; }
    mu *= (1.0f/16.0f);
    float var=0.f;
    #pragma unroll
    for (int b=0;b<16;b++){ float d=v[b]-mu; var+=d*d; }
    var *= (1.0f/16.0f);
    float rs = rsqrtf(var + EPS_BN);
    #pragma unroll
    for (int b=0;b<16;b++) g_last[b*DD+c] = (v[b]-mu)*rs*gamma[c] + beta[c];
}
__global__ void fc1_kernel(const float* __restrict__ W, const float* __restrict__ bias){
    __shared__ float xr[512];
    int b = blockIdx.x; int j = threadIdx.x;
    xr[j]     = g_last[b*DD + j];
    xr[j+256] = g_last[b*DD + j + 256];
    __syncthreads();
    float s=0.f;
    #pragma unroll 8
    for (int k=0;k<512;k++) s += xr[k]*W[k*256+j];
    g_o1[b*256+j] = s + bias[j];
}
__global__ void bn2gelu_kernel(const float* __restrict__ gamma, const float* __restrict__ beta){
    int j = threadIdx.x;
    float v[16]; float mu=0.f;
    #pragma unroll
    for (int b=0;b<16;b++){ v[b]=g_o1[b*256+j]; mu+=v[b]; }
    mu *= (1.0f/16.0f);
    float var=0.f;
    #pragma unroll
    for (int b=0;b<16;b++){ float d=v[b]-mu; var+=d*d; }
    var *= (1.0f/16.0f);
    float rs = rsqrtf(var + EPS_BN);
    #pragma unroll
    for (int b=0;b<16;b++){
        float t = (v[b]-mu)*rs*gamma[j] + beta[j];
        g_o1[b*256+j] = 0.5f*t*(1.0f + erff(t*0.7071067811865475f));
    }
}
__global__ void fc2_kernel(const float* __restrict__ W, const float* __restrict__ bias){
    __shared__ float red[256];
    int b = blockIdx.x; int j = threadIdx.x;
    red[j] = g_o1[b*256+j]*W[j];
    __syncthreads();
    for (int o=128;o;o>>=1){ if(j<o) red[j]+=red[j+o]; __syncthreads(); }
    if (j==0) g_o2[b] = red[0] + bias[0];
}
__global__ void res_out_kernel(const float* __restrict__ resW, const float* __restrict__ resb,
                               float* __restrict__ out){
    int warp = (blockIdx.x*blockDim.x + threadIdx.x) >> 5;
    int lane = threadIdx.x & 31;
    if (warp >= RR) return;
    const float* xr = g_xn + (size_t)warp*DD;
    float s=0.f;
    for (int d=lane; d<DD; d+=32) s += xr[d]*resW[d];
    #pragma unroll
    for (int o=16;o;o>>=1) s += __shfl_xor_sync(~0u,s,o);
    if (lane==0){
        float v = s + resb[0] + g_o2[warp>>9];
        out[warp] = fmaxf(v, 0.f);
    }
}

// ---------------- host driver ----------------
extern "C" void kernel_launch(void* const* d_in, const int* in_sizes, int n_in,
                              void* d_out, int out_size){
    const float* x        = (const float*)d_in[0];
    const float* bng      = (const float*)d_in[1];
    const float* bnb      = (const float*)d_in[2];
    const float* norm1_w  = (const float*)d_in[3];
    const float* norm2_w  = (const float*)d_in[4];
    const float* Wq       = (const float*)d_in[5];
    const float* Wk       = (const float*)d_in[6];
    const float* Wv       = (const float*)d_in[7];
    const float* Wog      = (const float*)d_in[8];
    const float* Wi       = (const float*)d_in[9];
    const float* bi       = (const float*)d_in[10];
    const float* Wf       = (const float*)d_in[11];
    const float* bf       = (const float*)d_in[12];
    const float* mhn_w    = (const float*)d_in[13];
    const float* Wout     = (const float*)d_in[14];
    const float* Wg       = (const float*)d_in[15];
    const float* Wu       = (const float*)d_in[16];
    const float* Wd       = (const float*)d_in[17];
    const float* fnorm_w  = (const float*)d_in[18];
    const float* bn1_g    = (const float*)d_in[19];
    const float* bn1_b    = (const float*)d_in[20];
    const float* fc1_W    = (const float*)d_in[21];
    const float* fc1_b    = (const float*)d_in[22];
    const float* bn2_g    = (const float*)d_in[23];
    const float* bn2_b    = (const float*)d_in[24];
    const float* fc2_W    = (const float*)d_in[25];
    const float* fc2_b    = (const float*)d_in[26];
    const float* res_W    = (const float*)d_in[27];
    const float* res_b    = (const float*)d_in[28];
    float* out = (float*)d_out;

    float *p_h,*p_last;
    __half *p_wh,*p_yh,*p_hth,*p_g1h;
    cudaGetSymbolAddress((void**)&p_h,  g_h);
    cudaGetSymbolAddress((void**)&p_last, g_last);
    cudaGetSymbolAddress((void**)&p_wh,  g_wh);
    cudaGetSymbolAddress((void**)&p_yh,  g_yh);
    cudaGetSymbolAddress((void**)&p_hth, g_hth);
    cudaGetSymbolAddress((void**)&p_g1h, g_g1h);

    cudaFuncSetAttribute((const void*)proj_gemm_kernel,  cudaFuncAttributeMaxDynamicSharedMemorySize, HG_SMEM);
    cudaFuncSetAttribute((const void*)hgemm64_kernel<1>, cudaFuncAttributeMaxDynamicSharedMemorySize, HG_SMEM);
    cudaFuncSetAttribute((const void*)hgemm_gu_kernel,   cudaFuncAttributeMaxDynamicSharedMemorySize, GU_SMEM);

    bnpart_conv_kernel<<<64 + (int)((TOTW + 1023)/1024), 256>>>(x, Wq, Wk, Wv, Wog, Wout, Wg, Wu, Wd);
    bn_final_kernel<<<1,512>>>();
    bnapply_rms_kernel<<<RR,256>>>(x, bng, bnb, norm1_w);

    for (int l=0;l<LL;l++){
        const __half* Wq_h  = p_wh + OFF_WQ  + (size_t)l*DD*QKD;
        const __half* Wk_h  = p_wh + OFF_WK  + (size_t)l*DD*QKD;
        const __half* Wv_h  = p_wh + OFF_WV  + (size_t)l*DD*VV;
        const __half* Wog_h = p_wh + OFF_WOG + (size_t)l*DD*VV;
        const __half* Wout_h= p_wh + OFF_WOUT+ (size_t)l*VV*DD;
        const __half* Wg_h  = p_wh + OFF_WG  + (size_t)l*DD*FF;
        const __half* Wu_h  = p_wh + OFF_WU  + (size_t)l*DD*FF;
        const __half* Wd_h  = p_wh + OFF_WD  + (size_t)l*FF*DD;
        const float* Wi_l = Wi + (size_t)l*DD*HH;
        const float* Wf_l = Wf + (size_t)l*DD*HH;

        if (l > 0)
            rmsnorm_h_kernel<<<RR,256>>>(p_h, norm1_w + l*DD, p_yh);

        proj_gemm_kernel<<<dim3(12, RR/64), 128, HG_SMEM>>>(p_yh, Wq_h, Wk_h, Wv_h, Wog_h);
        gates_kernel<<<RR/8,256>>>(p_yh, Wi_l, bi + l*HH, Wf_l, bf + l*HH);
        scan_kernel<<<BB*HH,32>>>();

        attn_kernel<<<dim3(SS/64, BB*HH),128>>>(mhn_w + l*VV);

        hgemm64_kernel<1><<<dim3(DD/128, RR/64), 128, HG_SMEM>>>(p_hth, Wout_h, p_h, DD, VV);

        rmsnorm_h_kernel<<<RR,256>>>(p_h, norm2_w + l*DD, p_yh);
        hgemm_gu_kernel<<<dim3(FF/128, RR/64), 128, GU_SMEM>>>(p_yh, Wg_h, Wu_h, p_g1h, FF, DD);
        hgemm64_kernel<1><<<dim3(DD/128, RR/64), 128, HG_SMEM>>>(p_g1h, Wd_h, p_h, DD, FF);
    }

    rmsnorm_f_kernel<<<BB,256>>>(p_h + (size_t)(SS-1)*DD, fnorm_w, p_last, (long)SS*DD);

    bn1_kernel<<<1,512>>>(bn1_g, bn1_b);
    fc1_kernel<<<BB,256>>>(fc1_W, fc1_b);
    bn2gelu_kernel<<<1,256>>>(bn2_g, bn2_b);
    fc2_kernel<<<BB,256>>>(fc2_W, fc2_b);
    res_out_kernel<<<RR/8,256>>>(res_W, res_b, out);
    (void)in_sizes; (void)n_in; (void)out_size;
}

// round 9
// speedup vs baseline: 1.8037x; 1.0083x over previous
#include <cuda_runtime.h>
#include <cuda_fp16.h>
#include <math.h>

// ---------------- problem constants ----------------
#define BB   16
#define SS   512
#define DD   512
#define LL   4
#define HH   8
#define QKD  256      // D/2
#define VV   512
#define FF   1408
#define RR   (BB*SS)      // 8192 rows
#define DQK  32
#define DV   64
#define EPS_RMS 1e-6f
#define EPS_BN  1e-5f
#define CAPV 15.0f

// weight half-buffer offsets (element counts, all layers concatenated)
#define OFF_WQ   0L
#define OFF_WK   524288L
#define OFF_WV   1048576L
#define OFF_WOG  2097152L
#define OFF_WOUT 3145728L
#define OFF_WG   4194304L
#define OFF_WU   7077888L
#define OFF_WD   9961472L
#define TOTW     12845056L

// ---------------- device scratch ----------------
__device__ float g_xn [RR*DD];
__device__ float g_h  [RR*DD];
__device__ float g_og [RR*VV];
__device__ float g_ig [BB*HH*SS];
__device__ float g_fg [BB*HH*SS];
__device__ float g_bc [BB*HH*SS];
__device__ float g_mv [BB*HH*SS];
__device__ float g_part[64*1024];
__device__ float g_stats[1024];
__device__ float g_last[BB*DD];
__device__ float g_o1 [BB*256];
__device__ float g_o2 [BB];

__device__ __half g_wh  [TOTW];      // fp16 weights
__device__ __half g_yh  [RR*DD];     // fp16 rms-normed activations
__device__ __half g_hth [RR*VV];     // fp16 headnorm output
__device__ __half g_g1h [RR*FF];     // fp16 silu(g)*u
__device__ __half g_qh  [RR*QKD];
__device__ __half g_kh  [RR*QKD];
__device__ __half g_vh  [RR*VV];

__device__ __forceinline__ float softcapf(float x){ return CAPV * tanhf(x * (1.0f/CAPV)); }
__device__ __forceinline__ float logsigf(float x){ return fminf(x,0.f) - log1pf(expf(-fabsf(x))); }

__device__ __forceinline__ void cp16(void* smem_dst, const void* gsrc){
    unsigned s = (unsigned)__cvta_generic_to_shared(smem_dst);
    asm volatile("cp.async.cg.shared.global [%0], [%1], 16;" :: "r"(s), "l"(gsrc));
}
__device__ __forceinline__ void cp_commit(){ asm volatile("cp.async.commit_group;" ::: "memory"); }
template<int NN> __device__ __forceinline__ void cp_wait(){ asm volatile("cp.async.wait_group %0;" :: "n"(NN) : "memory"); }

__device__ __forceinline__ void mma_f16(float* c, const unsigned* a, const unsigned* b){
    asm volatile("mma.sync.aligned.m16n8k16.row.col.f32.f16.f16.f32 "
        "{%0,%1,%2,%3}, {%4,%5,%6,%7}, {%8,%9}, {%0,%1,%2,%3};"
        : "+f"(c[0]), "+f"(c[1]), "+f"(c[2]), "+f"(c[3])
        : "r"(a[0]), "r"(a[1]), "r"(a[2]), "r"(a[3]), "r"(b[0]), "r"(b[1]));
}
__device__ __forceinline__ void ldsm4(unsigned& r0, unsigned& r1, unsigned& r2, unsigned& r3, unsigned addr){
    asm volatile("ldmatrix.sync.aligned.m8n8.x4.shared.b16 {%0,%1,%2,%3}, [%4];"
        : "=r"(r0), "=r"(r1), "=r"(r2), "=r"(r3) : "r"(addr));
}
__device__ __forceinline__ void ldsm4t(unsigned& r0, unsigned& r1, unsigned& r2, unsigned& r3, unsigned addr){
    asm volatile("ldmatrix.sync.aligned.m8n8.x4.trans.shared.b16 {%0,%1,%2,%3}, [%4];"
        : "=r"(r0), "=r"(r1), "=r"(r2), "=r"(r3) : "r"(addr));
}
__device__ __forceinline__ unsigned f22h(float a, float b){
    __half2 h = __floats2half2_rn(a, b);
    return *reinterpret_cast<unsigned*>(&h);
}

// ---------------- bn partial + weight fp32->fp16 conversion (fused launch) ----
__global__ void bnpart_conv_kernel(const float* __restrict__ x,
        const float* __restrict__ Wq, const float* __restrict__ Wk,
        const float* __restrict__ Wv, const float* __restrict__ Wog,
        const float* __restrict__ Wout, const float* __restrict__ Wg,
        const float* __restrict__ Wu, const float* __restrict__ Wd){
    if (blockIdx.x < 64){
        int c0 = threadIdx.x, c1 = threadIdx.x + 256;
        float s0=0,s1=0,q0=0,q1=0;
        const float* base = x + (size_t)blockIdx.x * 128 * DD;
        for (int r=0;r<128;r++){
            float v0 = base[(size_t)r*DD + c0];
            float v1 = base[(size_t)r*DD + c1];
            s0+=v0; q0+=v0*v0; s1+=v1; q1+=v1*v1;
        }
        float* p = g_part + blockIdx.x*1024;
        p[c0]=s0; p[c1]=s1; p[512+c0]=q0; p[512+c1]=q1;
    } else {
        long e = (long)(blockIdx.x - 64)*1024 + (long)threadIdx.x*4;
        if (e >= TOTW) return;
        const float* src; long base;
        if      (e < OFF_WK)   { src = Wq;   base = OFF_WQ;  }
        else if (e < OFF_WV)   { src = Wk;   base = OFF_WK;  }
        else if (e < OFF_WOG)  { src = Wv;   base = OFF_WV;  }
        else if (e < OFF_WOUT) { src = Wog;  base = OFF_WOG; }
        else if (e < OFF_WG)   { src = Wout; base = OFF_WOUT;}
        else if (e < OFF_WU)   { src = Wg;   base = OFF_WG;  }
        else if (e < OFF_WD)   { src = Wu;   base = OFF_WU;  }
        else                   { src = Wd;   base = OFF_WD;  }
        float4 v = *reinterpret_cast<const float4*>(src + (e - base));
        __half2* d = reinterpret_cast<__half2*>(g_wh + e);
        d[0] = __floats2half2_rn(v.x, v.y);
        d[1] = __floats2half2_rn(v.z, v.w);
    }
}
__global__ void bn_final_kernel(){
    int c = threadIdx.x; // 512
    float s=0,q=0;
    for (int i=0;i<64;i++){ s += g_part[i*1024+c]; q += g_part[i*1024+512+c]; }
    float mu = s * (1.0f/RR);
    float var = q * (1.0f/RR) - mu*mu;
    g_stats[c] = mu;
    g_stats[512+c] = rsqrtf(var + EPS_BN);
}

// ---------------- gates tail (shared by rms kernels) ----------------
// ys: smem fp32 y row [512]; warps 0-7 compute head wid's ig/fg.
__device__ __forceinline__ void gates_tail(const float* ys, int r,
        const float* __restrict__ Wi, const float* __restrict__ bi,
        const float* __restrict__ Wf, const float* __restrict__ bf,
        int wid, int lane){
    float ai = 0.f, af = 0.f;
    int h = wid;
    #pragma unroll
    for (int k=0;k<16;k++){
        int d = lane + k*32;
        float yv = ys[d];
        ai += yv * Wi[d*HH + h];
        af += yv * Wf[d*HH + h];
    }
    #pragma unroll
    for (int o=16;o;o>>=1){
        ai += __shfl_xor_sync(~0u, ai, o);
        af += __shfl_xor_sync(~0u, af, o);
    }
    if (lane == 0){
        int b = r >> 9, s = r & 511;
        g_ig[((b*HH+h)*SS)+s] = softcapf(ai + bi[h]);
        g_fg[((b*HH+h)*SS)+s] = softcapf(af + bf[h]);
    }
}

// bn apply + rmsnorm(norm1_w[0]) + gates fused
__global__ void bnapply_rms_kernel(const float* __restrict__ x,
                                   const float* __restrict__ gamma,
                                   const float* __restrict__ beta,
                                   const float* __restrict__ w,
                                   const float* __restrict__ Wi, const float* __restrict__ bi,
                                   const float* __restrict__ Wf, const float* __restrict__ bf){
    __shared__ float red[8];
    __shared__ float ys[512];
    int r = blockIdx.x, t = threadIdx.x;
    int c0 = t, c1 = t + 256;
    const float* xr = x + (size_t)r*DD;
    float a = (xr[c0]-g_stats[c0])*g_stats[512+c0]*gamma[c0] + beta[c0];
    float b = (xr[c1]-g_stats[c1])*g_stats[512+c1]*gamma[c1] + beta[c1];
    g_xn[(size_t)r*DD+c0] = a; g_xn[(size_t)r*DD+c1] = b;
    g_h [(size_t)r*DD+c0] = a; g_h [(size_t)r*DD+c1] = b;
    float s = a*a + b*b;
    #pragma unroll
    for (int o=16;o;o>>=1) s += __shfl_xor_sync(~0u, s, o);
    if ((t&31)==0) red[t>>5]=s;
    __syncthreads();
    float tot = 0;
    #pragma unroll
    for (int i=0;i<8;i++) tot += red[i];
    float rs = rsqrtf(tot*(1.0f/DD) + EPS_RMS);
    float y0 = a*rs*w[c0], y1 = b*rs*w[c1];
    g_yh[(size_t)r*DD+c0] = __float2half(y0);
    g_yh[(size_t)r*DD+c1] = __float2half(y1);
    ys[c0] = y0; ys[c1] = y1;
    __syncthreads();
    gates_tail(ys, r, Wi, bi, Wf, bf, t>>5, t&31);
}

// rmsnorm -> fp16 y, optional fused gates (Wi!=null)
__global__ void rmsnorm_h_kernel(const float* __restrict__ x, const float* __restrict__ w,
                                 __half* __restrict__ y,
                                 const float* __restrict__ Wi, const float* __restrict__ bi,
                                 const float* __restrict__ Wf, const float* __restrict__ bf){
    __shared__ float red[8];
    __shared__ float ys[512];
    int r = blockIdx.x, t = threadIdx.x;
    const float* xr = x + (size_t)r*DD;
    float a = xr[t], b = xr[t+256];
    float s = a*a + b*b;
    #pragma unroll
    for (int o=16;o;o>>=1) s += __shfl_xor_sync(~0u, s, o);
    if ((t&31)==0) red[t>>5]=s;
    __syncthreads();
    float tot = 0;
    #pragma unroll
    for (int i=0;i<8;i++) tot += red[i];
    float rs = rsqrtf(tot*(1.0f/DD) + EPS_RMS);
    float y0 = a*rs*w[t], y1 = b*rs*w[t+256];
    __half* yr = y + (size_t)r*DD;
    yr[t]     = __float2half(y0);
    yr[t+256] = __float2half(y1);
    if (Wi){
        ys[t] = y0; ys[t+256] = y1;
        __syncthreads();
        gates_tail(ys, r, Wi, bi, Wf, bf, t>>5, t&31);
    }
}
__global__ void rmsnorm_f_kernel(const float* __restrict__ x, const float* __restrict__ w,
                                 float* __restrict__ y, long xs){
    __shared__ float red[8];
    int r = blockIdx.x, t = threadIdx.x;
    const float* xr = x + (size_t)r*xs;
    float a = xr[t], b = xr[t+256];
    float s = a*a + b*b;
    #pragma unroll
    for (int o=16;o;o>>=1) s += __shfl_xor_sync(~0u, s, o);
    if ((t&31)==0) red[t>>5]=s;
    __syncthreads();
    float tot = 0;
    #pragma unroll
    for (int i=0;i<8;i++) tot += red[i];
    float rs = rsqrtf(tot*(1.0f/DD) + EPS_RMS);
    float* yr = y + (size_t)r*DD;
    yr[t]     = a*rs*w[t];
    yr[t+256] = b*rs*w[t+256];
}

// ---------------- fp16 tensor-core GEMM, BM=64 x BN=128 ----------------
#define AP 40
#define BP 136
#define AS_SZ (64*AP)    // 2560 halves
#define BS_SZ (32*BP)    // 4352 halves
#define NSTG 3
#define HG_SMEM (NSTG*(AS_SZ+BS_SZ)*2)   // 41472 B
#define GU_SMEM (NSTG*(AS_SZ+2*BS_SZ)*2) // 67584 B

#define GEMM_PRE()                                                             \
    const int tid = threadIdx.x;                                               \
    const int lane = tid & 31;                                                 \
    const int wid = tid >> 5;                                                  \
    const int g = lane >> 2, t = lane & 3;                                     \
    const int mw = (wid >> 1) * 32;                                            \
    const int nw = (wid & 1) * 64;                                             \
    const int lrow = (lane & 7) + ((lane >> 3) & 1) * 8;                       \
    const int lcol = ((lane >> 3) & 2) * 4;

#define LOAD_A(kt, buf) do {                                                   \
    __half* Ad = As + (buf)*AS_SZ;                                             \
    _Pragma("unroll")                                                          \
    for (int ii=0; ii<2; ii++){                                                \
        int idx = tid + ii*128;                                                \
        int m = idx >> 2, c = idx & 3;                                         \
        cp16(Ad + m*AP + c*8, Ab + (size_t)m*K + (kt)*32 + c*8);               \
    }                                                                          \
} while(0)

#define LOAD_B(kt, buf, Bsb, Bb, N) do {                                       \
    __half* Bd = (Bsb) + (buf)*BS_SZ;                                          \
    _Pragma("unroll")                                                          \
    for (int ii=0; ii<4; ii++){                                                \
        int idx = tid + ii*128;                                                \
        int kr = idx >> 4, c = idx & 15;                                       \
        cp16(Bd + kr*BP + c*8, (Bb) + (size_t)((kt)*32+kr)*(N) + c*8);         \
    }                                                                          \
} while(0)

#define COMPUTE_TILE(buf, accA, smAbase, smBbase)                              \
    {                                                                          \
        unsigned baseA = (smAbase) + (buf)*AS_SZ*2;                            \
        unsigned baseB = (smBbase) + (buf)*BS_SZ*2;                            \
        _Pragma("unroll")                                                      \
        for (int ks=0; ks<2; ks++){                                            \
            int k0 = ks*16;                                                    \
            unsigned af[2][4], bf[4][4];                                       \
            _Pragma("unroll")                                                  \
            for (int i=0;i<2;i++){                                             \
                int m0 = mw + i*16;                                            \
                ldsm4(af[i][0], af[i][1], af[i][2], af[i][3],                  \
                      baseA + ((unsigned)(m0 + lrow)*AP + (k0 + lcol))*2);     \
            }                                                                  \
            _Pragma("unroll")                                                  \
            for (int j2=0;j2<4;j2++){                                          \
                int n0 = nw + j2*16;                                           \
                ldsm4t(bf[j2][0], bf[j2][1], bf[j2][2], bf[j2][3],             \
                       baseB + ((unsigned)(k0 + lrow)*BP + (n0 + lcol))*2);    \
            }                                                                  \
            _Pragma("unroll")                                                  \
            for (int i=0;i<2;i++){                                             \
                _Pragma("unroll")                                              \
                for (int j=0;j<8;j++){                                         \
                    unsigned b2[2];                                            \
                    b2[0] = bf[j>>1][(j&1)*2+0];                               \
                    b2[1] = bf[j>>1][(j&1)*2+1];                               \
                    mma_f16(accA[i][j], af[i], b2);                            \
                }                                                              \
            }                                                                  \
        }                                                                      \
    }

// merged projection GEMM: x-tile 0-1:q, 2-3:k, 4-7:v (fp16 out), 8-11:og (sigmoid fp32)
__global__ __launch_bounds__(128) void proj_gemm_kernel(
        const __half* __restrict__ A,
        const __half* __restrict__ Wq_h, const __half* __restrict__ Wk_h,
        const __half* __restrict__ Wv_h, const __half* __restrict__ Wog_h){
    extern __shared__ __half sm[];
    __half* As = sm;
    __half* Bs = sm + NSTG*AS_SZ;
    const int K = DD;
    int xt = blockIdx.x;
    const __half* Bsrc; __half* CH = nullptr; float* CF = nullptr; int NC, xl, epi;
    if (xt < 2)      { Bsrc = Wq_h;  CH = g_qh; NC = QKD; xl = xt;   epi = 0; }
    else if (xt < 4) { Bsrc = Wk_h;  CH = g_kh; NC = QKD; xl = xt-2; epi = 0; }
    else if (xt < 8) { Bsrc = Wv_h;  CH = g_vh; NC = VV;  xl = xt-4; epi = 0; }
    else             { Bsrc = Wog_h; CF = g_og; NC = VV;  xl = xt-8; epi = 2; }
    GEMM_PRE();
    const __half* Ab = A + (size_t)blockIdx.y * 64 * K;
    const __half* Bb = Bsrc + (size_t)xl * 128;
    const unsigned smA = (unsigned)__cvta_generic_to_shared(As);
    const unsigned smB = (unsigned)__cvta_generic_to_shared(Bs);

    float acc[2][8][4];
    #pragma unroll
    for (int i=0;i<2;i++)
        #pragma unroll
        for (int j=0;j<8;j++)
            #pragma unroll
            for (int c=0;c<4;c++) acc[i][j][c]=0.f;

    const int KT = K/32;
    LOAD_A(0,0); LOAD_B(0,0,Bs,Bb,NC); cp_commit();
    LOAD_A(1,1); LOAD_B(1,1,Bs,Bb,NC); cp_commit();
    for (int kt=0; kt<KT; kt++){
        if (kt+1 < KT) cp_wait<1>(); else cp_wait<0>();
        __syncthreads();
        if (kt+2 < KT){
            int nb = (kt+2)%NSTG;
            LOAD_A(kt+2, nb); LOAD_B(kt+2, nb, Bs, Bb, NC); cp_commit();
        }
        COMPUTE_TILE(kt%NSTG, acc, smA, smB);
        __syncthreads();
    }
    #pragma unroll
    for (int i=0;i<2;i++){
        #pragma unroll
        for (int j=0;j<8;j++){
            size_t row = (size_t)blockIdx.y*64 + mw + i*16 + g;
            size_t col = (size_t)xl*128 + nw + j*8 + t*2;
            #pragma unroll
            for (int h2=0; h2<2; h2++){
                size_t rr = row + h2*8;
                float v0 = acc[i][j][h2*2+0];
                float v1 = acc[i][j][h2*2+1];
                if (epi==0){
                    *reinterpret_cast<__half2*>(CH + rr*NC + col) = __floats2half2_rn(v0, v1);
                } else {
                    float* p = CF + rr*NC + col;
                    p[0]=1.0f/(1.0f+expf(-v0)); p[1]=1.0f/(1.0f+expf(-v1));
                }
            }
        }
    }
}

// generic GEMM: EPI 0 store fp32, 1 C+=
template<int EPI>
__global__ __launch_bounds__(128) void hgemm64_kernel(
        const __half* __restrict__ A,
        const __half* __restrict__ B, float* __restrict__ C,
        int N, int K){
    extern __shared__ __half sm[];
    __half* As = sm;
    __half* Bs = sm + NSTG*AS_SZ;
    GEMM_PRE();
    const __half* Ab = A + (size_t)blockIdx.y * 64 * K;
    const __half* Bb = B + (size_t)blockIdx.x * 128;
    const unsigned smA = (unsigned)__cvta_generic_to_shared(As);
    const unsigned smB = (unsigned)__cvta_generic_to_shared(Bs);

    float acc[2][8][4];
    #pragma unroll
    for (int i=0;i<2;i++)
        #pragma unroll
        for (int j=0;j<8;j++)
            #pragma unroll
            for (int c=0;c<4;c++) acc[i][j][c]=0.f;

    const int KT = K/32;
    LOAD_A(0,0); LOAD_B(0,0,Bs,Bb,N); cp_commit();
    LOAD_A(1,1); LOAD_B(1,1,Bs,Bb,N); cp_commit();
    for (int kt=0; kt<KT; kt++){
        if (kt+1 < KT) cp_wait<1>(); else cp_wait<0>();
        __syncthreads();
        if (kt+2 < KT){
            int nb = (kt+2)%NSTG;
            LOAD_A(kt+2, nb); LOAD_B(kt+2, nb, Bs, Bb, N); cp_commit();
        }
        COMPUTE_TILE(kt%NSTG, acc, smA, smB);
        __syncthreads();
    }
    #pragma unroll
    for (int i=0;i<2;i++){
        #pragma unroll
        for (int j=0;j<8;j++){
            size_t row = (size_t)blockIdx.y*64 + mw + i*16 + g;
            size_t col = (size_t)blockIdx.x*128 + nw + j*8 + t*2;
            #pragma unroll
            for (int h2=0; h2<2; h2++){
                size_t rr = row + h2*8;
                float v0 = acc[i][j][h2*2+0];
                float v1 = acc[i][j][h2*2+1];
                float* p = C + rr*N + col;
                if (EPI==0){ p[0]=v0; p[1]=v1; }
                else { p[0]+=v0; p[1]+=v1; }
            }
        }
    }
}

// fused G+U GEMM: out = silu(y@Wg) * (y@Wu), fp16 out
__global__ __launch_bounds__(128) void hgemm_gu_kernel(
        const __half* __restrict__ A,
        const __half* __restrict__ Bg, const __half* __restrict__ Bu,
        __half* __restrict__ CH, int N, int K){
    extern __shared__ __half sm[];
    __half* As  = sm;
    __half* Bgs = sm + NSTG*AS_SZ;
    __half* Bus = Bgs + NSTG*BS_SZ;
    GEMM_PRE();
    const __half* Ab  = A + (size_t)blockIdx.y * 64 * K;
    const __half* Bgb = Bg + (size_t)blockIdx.x * 128;
    const __half* Bub = Bu + (size_t)blockIdx.x * 128;
    const unsigned smA = (unsigned)__cvta_generic_to_shared(As);
    const unsigned smG = (unsigned)__cvta_generic_to_shared(Bgs);
    const unsigned smU = (unsigned)__cvta_generic_to_shared(Bus);

    float accg[2][8][4], accu[2][8][4];
    #pragma unroll
    for (int i=0;i<2;i++)
        #pragma unroll
        for (int j=0;j<8;j++)
            #pragma unroll
            for (int c=0;c<4;c++){ accg[i][j][c]=0.f; accu[i][j][c]=0.f; }

    const int KT = K/32;
    LOAD_A(0,0); LOAD_B(0,0,Bgs,Bgb,N); LOAD_B(0,0,Bus,Bub,N); cp_commit();
    LOAD_A(1,1); LOAD_B(1,1,Bgs,Bgb,N); LOAD_B(1,1,Bus,Bub,N); cp_commit();
    for (int kt=0; kt<KT; kt++){
        if (kt+1 < KT) cp_wait<1>(); else cp_wait<0>();
        __syncthreads();
        if (kt+2 < KT){
            int nb = (kt+2)%NSTG;
            LOAD_A(kt+2, nb);
            LOAD_B(kt+2, nb, Bgs, Bgb, N);
            LOAD_B(kt+2, nb, Bus, Bub, N);
            cp_commit();
        }
        COMPUTE_TILE(kt%NSTG, accg, smA, smG);
        COMPUTE_TILE(kt%NSTG, accu, smA, smU);
        __syncthreads();
    }
    #pragma unroll
    for (int i=0;i<2;i++){
        #pragma unroll
        for (int j=0;j<8;j++){
            size_t row = (size_t)blockIdx.y*64 + mw + i*16 + g;
            size_t col = (size_t)blockIdx.x*128 + nw + j*8 + t*2;
            #pragma unroll
            for (int h2=0; h2<2; h2++){
                size_t rr = row + h2*8;
                float g0 = accg[i][j][h2*2+0], g1v = accg[i][j][h2*2+1];
                float u0 = accu[i][j][h2*2+0], u1 = accu[i][j][h2*2+1];
                __half* q = CH + rr*N + col;
                q[0] = __float2half(g0*(1.0f/(1.0f+expf(-g0)))*u0);
                q[1] = __float2half(g1v*(1.0f/(1.0f+expf(-g1v)))*u1);
            }
        }
    }
}

// ---------------- per-(b,h) prefix scan (warp-parallel) ----------------
__global__ void scan_kernel(){
    int bh = blockIdx.x;
    int lane = threadIdx.x;
    const float* ig = g_ig + bh*SS;
    const float* fg = g_fg + bh*SS;
    float bcv[16];
    float carry = 0.f;
    #pragma unroll
    for (int c=0;c<16;c++){
        int s = c*32 + lane;
        float lf = logsigf(fg[s]);
        #pragma unroll
        for (int o=1;o<32;o<<=1){
            float n = __shfl_up_sync(~0u, lf, o);
            if (lane >= o) lf += n;
        }
        float bc = carry + lf;
        bcv[c] = bc;
        g_bc[bh*SS+s] = bc;
        carry = __shfl_sync(~0u, bc, 31);
    }
    float carrym = -1e30f;
    #pragma unroll
    for (int c=0;c<16;c++){
        int s = c*32 + lane;
        float cv = ig[s] - bcv[c];
        #pragma unroll
        for (int o=1;o<32;o<<=1){
            float n = __shfl_up_sync(~0u, cv, o);
            if (lane >= o) cv = fmaxf(cv, n);
        }
        float cm = fmaxf(carrym, cv);
        g_mv[bh*SS+s] = bcv[c] + cm;
        carrym = __shfl_sync(~0u, cm, 31);
    }
}

// ---------------- tensor-core mLSTM attention + fused headnorm ----------------
// double-buffered K/V pipeline; heavy t-tiles launched first.
#define QKP 40   // Q/K smem pitch (halves)
#define VVP 72   // V smem pitch (halves)
__global__ __launch_bounds__(128) void attn_kernel(const float* __restrict__ mhn){
    __shared__ __half Qs[64*QKP];
    __shared__ __half Ks[2][64*QKP];
    __shared__ __half Vs[2][64*VVP];
    __shared__ float bs_s[2][64], ig_s[2][64];
    int bh = blockIdx.y; int b = bh >> 3; int h = bh & 7;
    int tt = gridDim.x - 1 - blockIdx.x;   // heavy tiles first
    int tid = threadIdx.x, lane = tid & 31, wid = tid >> 5;
    int g = lane >> 2, t = lane & 3;
    int mw = wid * 16;
    const int lrow = (lane & 7) + ((lane >> 3) & 1) * 8;
    const int lcol = ((lane >> 3) & 2) * 4;
    const unsigned sQ = (unsigned)__cvta_generic_to_shared(Qs);
    const unsigned sK = (unsigned)__cvta_generic_to_shared(Ks);
    const unsigned sV = (unsigned)__cvta_generic_to_shared(Vs);
    const float scale = 0.17677669529663687f;  // 1/sqrt(32)

    #define LOADKV(st, buf) do {                                               \
        int s0_ = (st)*64;                                                     \
        _Pragma("unroll")                                                      \
        for (int ii=0; ii<2; ii++){                                            \
            int idx = tid + ii*128;                                            \
            int r = idx >> 2, c = (idx & 3) * 8;                               \
            cp16(Ks[buf] + r*QKP + c,                                          \
                 g_kh + ((size_t)(b*SS) + s0_ + r)*QKD + h*DQK + c);           \
        }                                                                      \
        _Pragma("unroll")                                                      \
        for (int ii=0; ii<4; ii++){                                            \
            int idx = tid + ii*128;                                            \
            int r = idx >> 3, c = (idx & 7) * 8;                               \
            cp16(Vs[buf] + r*VVP + c,                                          \
                 g_vh + ((size_t)(b*SS) + s0_ + r)*VV + h*DV + c);             \
        }                                                                      \
        if (tid < 64){                                                         \
            bs_s[buf][tid] = g_bc[bh*SS + s0_ + tid];                          \
            ig_s[buf][tid] = g_ig[bh*SS + s0_ + tid];                          \
        }                                                                      \
    } while(0)

    // prologue: Q + tile0 as group0, tile1 (if any) as group1
    #pragma unroll
    for (int ii=0; ii<2; ii++){
        int idx = tid + ii*128;
        int r = idx >> 2, c = (idx & 3) * 8;
        cp16(Qs + r*QKP + c, g_qh + ((size_t)(b*SS) + tt*64 + r)*QKD + h*DQK + c);
    }
    LOADKV(0, 0);
    cp_commit();
    if (tt >= 1){ LOADKV(1, 1); cp_commit(); }

    int r0 = tt*64 + mw + g, r1 = r0 + 8;
    float bt0 = g_bc[bh*SS + r0], bt1 = g_bc[bh*SS + r1];
    float mt0 = g_mv[bh*SS + r0], mt1 = g_mv[bh*SS + r1];

    float co[8][4];
    #pragma unroll
    for (int j=0;j<8;j++)
        #pragma unroll
        for (int c=0;c<4;c++) co[j][c]=0.f;
    float ssum0 = 0.f, ssum1 = 0.f;

    if (tt >= 1) cp_wait<1>(); else cp_wait<0>();
    __syncthreads();
    unsigned aq[2][4];
    #pragma unroll
    for (int ks=0; ks<2; ks++)
        ldsm4(aq[ks][0], aq[ks][1], aq[ks][2], aq[ks][3],
              sQ + ((unsigned)(mw + lrow)*QKP + ks*16 + lcol)*2);

    for (int st=0; st<=tt; st++){
        int s0 = st*64;
        int buf = st & 1;
        unsigned kbase = sK + (unsigned)buf*64*QKP*2;
        unsigned vbase = sV + (unsigned)buf*64*VVP*2;

        // S = Q K^T  (m16 x n64, k32)
        float cs[8][4];
        #pragma unroll
        for (int j=0;j<8;j++)
            #pragma unroll
            for (int c=0;c<4;c++) cs[j][c]=0.f;
        #pragma unroll
        for (int ks=0; ks<2; ks++){
            unsigned bk[4][4];
            #pragma unroll
            for (int j2=0;j2<4;j2++)
                ldsm4(bk[j2][0], bk[j2][1], bk[j2][2], bk[j2][3],
                      kbase + ((unsigned)(j2*16 + lrow)*QKP + ks*16 + lcol)*2);
            #pragma unroll
            for (int j=0;j<8;j++){
                unsigned b2[2];
                b2[0] = bk[j>>1][(j&1)];
                b2[1] = bk[j>>1][(j&1)+2];
                mma_f16(cs[j], aq[ks], b2);
            }
        }
        // decay, mask, ssum
        bool full = (st < tt);
        #pragma unroll
        for (int j=0;j<8;j++){
            int c0 = j*8 + 2*t, c1 = c0 + 1;
            float a0 = bs_s[buf][c0] - ig_s[buf][c0];
            float a1 = bs_s[buf][c1] - ig_s[buf][c1];
            float e00 = (full || (s0+c0 <= r0)) ? __expf(bt0 - a0 - mt0) : 0.f;
            float e10 = (full || (s0+c1 <= r0)) ? __expf(bt0 - a1 - mt0) : 0.f;
            float e01 = (full || (s0+c0 <= r1)) ? __expf(bt1 - a0 - mt1) : 0.f;
            float e11 = (full || (s0+c1 <= r1)) ? __expf(bt1 - a1 - mt1) : 0.f;
            cs[j][0] = cs[j][0]*scale*e00;  ssum0 += cs[j][0];
            cs[j][1] = cs[j][1]*scale*e10;  ssum0 += cs[j][1];
            cs[j][2] = cs[j][2]*scale*e01;  ssum1 += cs[j][2];
            cs[j][3] = cs[j][3]*scale*e11;  ssum1 += cs[j][3];
        }
        // O += P V
        #pragma unroll
        for (int kk=0; kk<4; kk++){
            unsigned ap[4];
            ap[0] = f22h(cs[2*kk][0],   cs[2*kk][1]);
            ap[1] = f22h(cs[2*kk][2],   cs[2*kk][3]);
            ap[2] = f22h(cs[2*kk+1][0], cs[2*kk+1][1]);
            ap[3] = f22h(cs[2*kk+1][2], cs[2*kk+1][3]);
            unsigned bv[4][4];
            #pragma unroll
            for (int j2=0;j2<4;j2++)
                ldsm4t(bv[j2][0], bv[j2][1], bv[j2][2], bv[j2][3],
                       vbase + ((unsigned)(kk*16 + lrow)*VVP + j2*16 + lcol)*2);
            #pragma unroll
            for (int j=0;j<8;j++){
                unsigned b2[2];
                b2[0] = bv[j>>1][(j&1)*2+0];
                b2[1] = bv[j>>1][(j&1)*2+1];
                mma_f16(co[j], ap, b2);
            }
        }
        __syncthreads();                 // done reading buf
        if (st+2 <= tt){ LOADKV(st+2, buf); cp_commit(); }
        if (st+1 <= tt){
            if (st+2 <= tt) cp_wait<1>(); else cp_wait<0>();
            __syncthreads();
        }
    }
    #undef LOADKV

    // row norms: reduce ssum across quad
    ssum0 += __shfl_xor_sync(~0u, ssum0, 1); ssum0 += __shfl_xor_sync(~0u, ssum0, 2);
    ssum1 += __shfl_xor_sync(~0u, ssum1, 1); ssum1 += __shfl_xor_sync(~0u, ssum1, 2);
    float inv0 = 1.0f/(fmaxf(fabsf(ssum0), __expf(-mt0)) + EPS_RMS);
    float inv1 = 1.0f/(fmaxf(fabsf(ssum1), __expf(-mt1)) + EPS_RMS);

    float mu0=0.f, mu1=0.f;
    #pragma unroll
    for (int j=0;j<8;j++){ mu0 += co[j][0]+co[j][1]; mu1 += co[j][2]+co[j][3]; }
    mu0 += __shfl_xor_sync(~0u, mu0, 1); mu0 += __shfl_xor_sync(~0u, mu0, 2);
    mu1 += __shfl_xor_sync(~0u, mu1, 1); mu1 += __shfl_xor_sync(~0u, mu1, 2);
    mu0 *= inv0 * (1.0f/DV);
    mu1 *= inv1 * (1.0f/DV);
    float var0=0.f, var1=0.f;
    #pragma unroll
    for (int j=0;j<8;j++){
        float d0 = co[j][0]*inv0 - mu0, d1 = co[j][1]*inv0 - mu0;
        float d2 = co[j][2]*inv1 - mu1, d3 = co[j][3]*inv1 - mu1;
        var0 += d0*d0 + d1*d1; var1 += d2*d2 + d3*d3;
    }
    var0 += __shfl_xor_sync(~0u, var0, 1); var0 += __shfl_xor_sync(~0u, var0, 2);
    var1 += __shfl_xor_sync(~0u, var1, 1); var1 += __shfl_xor_sync(~0u, var1, 2);
    float rs0 = rsqrtf(var0*(1.0f/DV) + EPS_RMS);
    float rs1 = rsqrtf(var1*(1.0f/DV) + EPS_RMS);

    size_t rg0 = (size_t)(b*SS) + r0;
    size_t rg1 = (size_t)(b*SS) + r1;
    #pragma unroll
    for (int j=0;j<8;j++){
        int colh = h*DV + j*8 + 2*t;
        float2 w2 = *reinterpret_cast<const float2*>(mhn + colh);
        float2 og0 = *reinterpret_cast<const float2*>(g_og + rg0*VV + colh);
        float2 og1 = *reinterpret_cast<const float2*>(g_og + rg1*VV + colh);
        float o00 = (co[j][0]*inv0 - mu0)*rs0*w2.x*og0.x;
        float o01 = (co[j][1]*inv0 - mu0)*rs0*w2.y*og0.y;
        float o10 = (co[j][2]*inv1 - mu1)*rs1*w2.x*og1.x;
        float o11 = (co[j][3]*inv1 - mu1)*rs1*w2.y*og1.y;
        *reinterpret_cast<__half2*>(g_hth + rg0*VV + colh) = __floats2half2_rn(o00, o01);
        *reinterpret_cast<__half2*>(g_hth + rg1*VV + colh) = __floats2half2_rn(o10, o11);
    }
}

// ---------------- final heads ----------------
__global__ void bn1_kernel(const float* __restrict__ gamma, const float* __restrict__ beta){
    int c = threadIdx.x;
    float v[16]; float mu=0.f;
    #pragma unroll
    for (int b=0;b<16;b++){ v[b]=g_last[b*DD+c]; mu+=v[b]; }
    mu *= (1.0f/16.0f);
    float var=0.f;
    #pragma unroll
    for (int b=0;b<16;b++){ float d=v[b]-mu; var+=d*d; }
    var *= (1.0f/16.0f);
    float rs = rsqrtf(var + EPS_BN);
    #pragma unroll
    for (int b=0;b<16;b++) g_last[b*DD+c] = (v[b]-mu)*rs*gamma[c] + beta[c];
}
__global__ void fc1_kernel(const float* __restrict__ W, const float* __restrict__ bias){
    __shared__ float xr[512];
    int b = blockIdx.x; int j = threadIdx.x;
    xr[j]     = g_last[b*DD + j];
    xr[j+256] = g_last[b*DD + j + 256];
    __syncthreads();
    float s=0.f;
    #pragma unroll 8
    for (int k=0;k<512;k++) s += xr[k]*W[k*256+j];
    g_o1[b*256+j] = s + bias[j];
}
__global__ void bn2gelu_kernel(const float* __restrict__ gamma, const float* __restrict__ beta){
    int j = threadIdx.x;
    float v[16]; float mu=0.f;
    #pragma unroll
    for (int b=0;b<16;b++){ v[b]=g_o1[b*256+j]; mu+=v[b]; }
    mu *= (1.0f/16.0f);
    float var=0.f;
    #pragma unroll
    for (int b=0;b<16;b++){ float d=v[b]-mu; var+=d*d; }
    var *= (1.0f/16.0f);
    float rs = rsqrtf(var + EPS_BN);
    #pragma unroll
    for (int b=0;b<16;b++){
        float t = (v[b]-mu)*rs*gamma[j] + beta[j];
        g_o1[b*256+j] = 0.5f*t*(1.0f + erff(t*0.7071067811865475f));
    }
}
__global__ void fc2_kernel(const float* __restrict__ W, const float* __restrict__ bias){
    __shared__ float red[256];
    int b = blockIdx.x; int j = threadIdx.x;
    red[j] = g_o1[b*256+j]*W[j];
    __syncthreads();
    for (int o=128;o;o>>=1){ if(j<o) red[j]+=red[j+o]; __syncthreads(); }
    if (j==0) g_o2[b] = red[0] + bias[0];
}
__global__ void res_out_kernel(const float* __restrict__ resW, const float* __restrict__ resb,
                               float* __restrict__ out){
    int warp = (blockIdx.x*blockDim.x + threadIdx.x) >> 5;
    int lane = threadIdx.x & 31;
    if (warp >= RR) return;
    const float* xr = g_xn + (size_t)warp*DD;
    float s=0.f;
    for (int d=lane; d<DD; d+=32) s += xr[d]*resW[d];
    #pragma unroll
    for (int o=16;o;o>>=1) s += __shfl_xor_sync(~0u,s,o);
    if (lane==0){
        float v = s + resb[0] + g_o2[warp>>9];
        out[warp] = fmaxf(v, 0.f);
    }
}

// ---------------- host driver ----------------
extern "C" void kernel_launch(void* const* d_in, const int* in_sizes, int n_in,
                              void* d_out, int out_size){
    const float* x        = (const float*)d_in[0];
    const float* bng      = (const float*)d_in[1];
    const float* bnb      = (const float*)d_in[2];
    const float* norm1_w  = (const float*)d_in[3];
    const float* norm2_w  = (const float*)d_in[4];
    const float* Wq       = (const float*)d_in[5];
    const float* Wk       = (const float*)d_in[6];
    const float* Wv       = (const float*)d_in[7];
    const float* Wog      = (const float*)d_in[8];
    const float* Wi       = (const float*)d_in[9];
    const float* bi       = (const float*)d_in[10];
    const float* Wf       = (const float*)d_in[11];
    const float* bf       = (const float*)d_in[12];
    const float* mhn_w    = (const float*)d_in[13];
    const float* Wout     = (const float*)d_in[14];
    const float* Wg       = (const float*)d_in[15];
    const float* Wu       = (const float*)d_in[16];
    const float* Wd       = (const float*)d_in[17];
    const float* fnorm_w  = (const float*)d_in[18];
    const float* bn1_g    = (const float*)d_in[19];
    const float* bn1_b    = (const float*)d_in[20];
    const float* fc1_W    = (const float*)d_in[21];
    const float* fc1_b    = (const float*)d_in[22];
    const float* bn2_g    = (const float*)d_in[23];
    const float* bn2_b    = (const float*)d_in[24];
    const float* fc2_W    = (const float*)d_in[25];
    const float* fc2_b    = (const float*)d_in[26];
    const float* res_W    = (const float*)d_in[27];
    const float* res_b    = (const float*)d_in[28];
    float* out = (float*)d_out;

    float *p_h,*p_last;
    __half *p_wh,*p_yh,*p_hth,*p_g1h;
    cudaGetSymbolAddress((void**)&p_h,  g_h);
    cudaGetSymbolAddress((void**)&p_last, g_last);
    cudaGetSymbolAddress((void**)&p_wh,  g_wh);
    cudaGetSymbolAddress((void**)&p_yh,  g_yh);
    cudaGetSymbolAddress((void**)&p_hth, g_hth);
    cudaGetSymbolAddress((void**)&p_g1h, g_g1h);

    cudaFuncSetAttribute((const void*)proj_gemm_kernel,  cudaFuncAttributeMaxDynamicSharedMemorySize, HG_SMEM);
    cudaFuncSetAttribute((const void*)hgemm64_kernel<1>, cudaFuncAttributeMaxDynamicSharedMemorySize, HG_SMEM);
    cudaFuncSetAttribute((const void*)hgemm_gu_kernel,   cudaFuncAttributeMaxDynamicSharedMemorySize, GU_SMEM);

    bnpart_conv_kernel<<<64 + (int)((TOTW + 1023)/1024), 256>>>(x, Wq, Wk, Wv, Wog, Wout, Wg, Wu, Wd);
    bn_final_kernel<<<1,512>>>();
    bnapply_rms_kernel<<<RR,256>>>(x, bng, bnb, norm1_w,
                                   Wi, bi, Wf, bf);   // layer-0 gates fused

    for (int l=0;l<LL;l++){
        const __half* Wq_h  = p_wh + OFF_WQ  + (size_t)l*DD*QKD;
        const __half* Wk_h  = p_wh + OFF_WK  + (size_t)l*DD*QKD;
        const __half* Wv_h  = p_wh + OFF_WV  + (size_t)l*DD*VV;
        const __half* Wog_h = p_wh + OFF_WOG + (size_t)l*DD*VV;
        const __half* Wout_h= p_wh + OFF_WOUT+ (size_t)l*VV*DD;
        const __half* Wg_h  = p_wh + OFF_WG  + (size_t)l*DD*FF;
        const __half* Wu_h  = p_wh + OFF_WU  + (size_t)l*DD*FF;
        const __half* Wd_h  = p_wh + OFF_WD  + (size_t)l*FF*DD;
        const float* Wi_l = Wi + (size_t)l*DD*HH;
        const float* Wf_l = Wf + (size_t)l*DD*HH;

        if (l > 0)
            rmsnorm_h_kernel<<<RR,256>>>(p_h, norm1_w + l*DD, p_yh,
                                         Wi_l, bi + l*HH, Wf_l, bf + l*HH);

        proj_gemm_kernel<<<dim3(12, RR/64), 128, HG_SMEM>>>(p_yh, Wq_h, Wk_h, Wv_h, Wog_h);
        scan_kernel<<<BB*HH,32>>>();

        attn_kernel<<<dim3(SS/64, BB*HH),128>>>(mhn_w + l*VV);

        hgemm64_kernel<1><<<dim3(DD/128, RR/64), 128, HG_SMEM>>>(p_hth, Wout_h, p_h, DD, VV);

        rmsnorm_h_kernel<<<RR,256>>>(p_h, norm2_w + l*DD, p_yh,
                                     nullptr, nullptr, nullptr, nullptr);
        hgemm_gu_kernel<<<dim3(FF/128, RR/64), 128, GU_SMEM>>>(p_yh, Wg_h, Wu_h, p_g1h, FF, DD);
        hgemm64_kernel<1><<<dim3(DD/128, RR/64), 128, HG_SMEM>>>(p_g1h, Wd_h, p_h, DD, FF);
    }

    rmsnorm_f_kernel<<<BB,256>>>(p_h + (size_t)(SS-1)*DD, fnorm_w, p_last, (long)SS*DD);

    bn1_kernel<<<1,512>>>(bn1_g, bn1_b);
    fc1_kernel<<<BB,256>>>(fc1_W, fc1_b);
    bn2gelu_kernel<<<1,256>>>(bn2_g, bn2_b);
    fc2_kernel<<<BB,256>>>(fc2_W, fc2_b);
    res_out_kernel<<<RR/8,256>>>(res_W, res_b, out);
    (void)in_sizes; (void)n_in; (void)out_size;
}

// round 11
// speedup vs baseline: 1.8280x; 1.0135x over previous
#include <cuda_runtime.h>
#include <cuda_fp16.h>
#include <math.h>

// ---------------- problem constants ----------------
#define BB   16
#define SS   512
#define DD   512
#define LL   4
#define HH   8
#define QKD  256      // D/2
#define VV   512
#define FF   1408
#define RR   (BB*SS)      // 8192 rows
#define DQK  32
#define DV   64
#define EPS_RMS 1e-6f
#define EPS_BN  1e-5f
#define CAPV 15.0f

// weight half-buffer offsets (element counts, all layers concatenated)
#define OFF_WQ   0L
#define OFF_WK   524288L
#define OFF_WV   1048576L
#define OFF_WOG  2097152L
#define OFF_WOUT 3145728L
#define OFF_WG   4194304L
#define OFF_WU   7077888L
#define OFF_WD   9961472L
#define TOTW     12845056L

// ---------------- device scratch ----------------
__device__ float g_xn [RR*DD];
__device__ float g_h  [RR*DD];
__device__ float g_ig [BB*HH*SS];
__device__ float g_fg [BB*HH*SS];
__device__ float g_bc [BB*HH*SS];
__device__ float g_mv [BB*HH*SS];
__device__ float g_part[64*1024];
__device__ float g_stats[1024];
__device__ float g_last[BB*DD];
__device__ float g_o1 [BB*256];
__device__ float g_o2 [BB];

__device__ __half g_wh  [TOTW];      // fp16 weights
__device__ __half g_yh  [RR*DD];     // fp16 rms-normed activations
__device__ __half g_hth [RR*VV];     // fp16 headnorm output
__device__ __half g_g1h [RR*FF];     // fp16 silu(g)*u
__device__ __half g_qh  [RR*QKD];
__device__ __half g_kh  [RR*QKD];
__device__ __half g_vh  [RR*VV];
__device__ __half g_ogh [RR*VV];     // fp16 sigmoid(og)

__device__ __forceinline__ float softcapf(float x){ return CAPV * tanhf(x * (1.0f/CAPV)); }
__device__ __forceinline__ float logsigf(float x){ return fminf(x,0.f) - log1pf(expf(-fabsf(x))); }

__device__ __forceinline__ void cp16(void* smem_dst, const void* gsrc){
    unsigned s = (unsigned)__cvta_generic_to_shared(smem_dst);
    asm volatile("cp.async.cg.shared.global [%0], [%1], 16;" :: "r"(s), "l"(gsrc));
}
__device__ __forceinline__ void cp_commit(){ asm volatile("cp.async.commit_group;" ::: "memory"); }
template<int NN> __device__ __forceinline__ void cp_wait(){ asm volatile("cp.async.wait_group %0;" :: "n"(NN) : "memory"); }

__device__ __forceinline__ void mma_f16(float* c, const unsigned* a, const unsigned* b){
    asm volatile("mma.sync.aligned.m16n8k16.row.col.f32.f16.f16.f32 "
        "{%0,%1,%2,%3}, {%4,%5,%6,%7}, {%8,%9}, {%0,%1,%2,%3};"
        : "+f"(c[0]), "+f"(c[1]), "+f"(c[2]), "+f"(c[3])
        : "r"(a[0]), "r"(a[1]), "r"(a[2]), "r"(a[3]), "r"(b[0]), "r"(b[1]));
}
__device__ __forceinline__ void ldsm4(unsigned& r0, unsigned& r1, unsigned& r2, unsigned& r3, unsigned addr){
    asm volatile("ldmatrix.sync.aligned.m8n8.x4.shared.b16 {%0,%1,%2,%3}, [%4];"
        : "=r"(r0), "=r"(r1), "=r"(r2), "=r"(r3) : "r"(addr));
}
__device__ __forceinline__ void ldsm4t(unsigned& r0, unsigned& r1, unsigned& r2, unsigned& r3, unsigned addr){
    asm volatile("ldmatrix.sync.aligned.m8n8.x4.trans.shared.b16 {%0,%1,%2,%3}, [%4];"
        : "=r"(r0), "=r"(r1), "=r"(r2), "=r"(r3) : "r"(addr));
}
__device__ __forceinline__ unsigned f22h(float a, float b){
    __half2 h = __floats2half2_rn(a, b);
    return *reinterpret_cast<unsigned*>(&h);
}

// ---------------- bn partial + weight fp32->fp16 conversion (fused launch) ----
__global__ void bnpart_conv_kernel(const float* __restrict__ x,
        const float* __restrict__ Wq, const float* __restrict__ Wk,
        const float* __restrict__ Wv, const float* __restrict__ Wog,
        const float* __restrict__ Wout, const float* __restrict__ Wg,
        const float* __restrict__ Wu, const float* __restrict__ Wd){
    if (blockIdx.x < 64){
        int c0 = threadIdx.x, c1 = threadIdx.x + 256;
        float s0=0,s1=0,q0=0,q1=0;
        const float* base = x + (size_t)blockIdx.x * 128 * DD;
        for (int r=0;r<128;r++){
            float v0 = base[(size_t)r*DD + c0];
            float v1 = base[(size_t)r*DD + c1];
            s0+=v0; q0+=v0*v0; s1+=v1; q1+=v1*v1;
        }
        float* p = g_part + blockIdx.x*1024;
        p[c0]=s0; p[c1]=s1; p[512+c0]=q0; p[512+c1]=q1;
    } else {
        long e = (long)(blockIdx.x - 64)*1024 + (long)threadIdx.x*4;
        if (e >= TOTW) return;
        const float* src; long base;
        if      (e < OFF_WK)   { src = Wq;   base = OFF_WQ;  }
        else if (e < OFF_WV)   { src = Wk;   base = OFF_WK;  }
        else if (e < OFF_WOG)  { src = Wv;   base = OFF_WV;  }
        else if (e < OFF_WOUT) { src = Wog;  base = OFF_WOG; }
        else if (e < OFF_WG)   { src = Wout; base = OFF_WOUT;}
        else if (e < OFF_WU)   { src = Wg;   base = OFF_WG;  }
        else if (e < OFF_WD)   { src = Wu;   base = OFF_WU;  }
        else                   { src = Wd;   base = OFF_WD;  }
        float4 v = *reinterpret_cast<const float4*>(src + (e - base));
        __half2* d = reinterpret_cast<__half2*>(g_wh + e);
        d[0] = __floats2half2_rn(v.x, v.y);
        d[1] = __floats2half2_rn(v.z, v.w);
    }
}
__global__ void bn_final_kernel(){
    int c = threadIdx.x; // 512
    float s=0,q=0;
    for (int i=0;i<64;i++){ s += g_part[i*1024+c]; q += g_part[i*1024+512+c]; }
    float mu = s * (1.0f/RR);
    float var = q * (1.0f/RR) - mu*mu;
    g_stats[c] = mu;
    g_stats[512+c] = rsqrtf(var + EPS_BN);
}

// ---------------- gates tail (shared by rms kernels) ----------------
__device__ __forceinline__ void gates_tail(const float* ys, int r,
        const float* __restrict__ Wi, const float* __restrict__ bi,
        const float* __restrict__ Wf, const float* __restrict__ bf,
        int wid, int lane){
    float ai = 0.f, af = 0.f;
    int h = wid;
    #pragma unroll
    for (int k=0;k<16;k++){
        int d = lane + k*32;
        float yv = ys[d];
        ai += yv * Wi[d*HH + h];
        af += yv * Wf[d*HH + h];
    }
    #pragma unroll
    for (int o=16;o;o>>=1){
        ai += __shfl_xor_sync(~0u, ai, o);
        af += __shfl_xor_sync(~0u, af, o);
    }
    if (lane == 0){
        int b = r >> 9, s = r & 511;
        g_ig[((b*HH+h)*SS)+s] = softcapf(ai + bi[h]);
        g_fg[((b*HH+h)*SS)+s] = softcapf(af + bf[h]);
    }
}

// bn apply + rmsnorm(norm1_w[0]) + gates fused
__global__ void bnapply_rms_kernel(const float* __restrict__ x,
                                   const float* __restrict__ gamma,
                                   const float* __restrict__ beta,
                                   const float* __restrict__ w,
                                   const float* __restrict__ Wi, const float* __restrict__ bi,
                                   const float* __restrict__ Wf, const float* __restrict__ bf){
    __shared__ float red[8];
    __shared__ float ys[512];
    int r = blockIdx.x, t = threadIdx.x;
    int c0 = t, c1 = t + 256;
    const float* xr = x + (size_t)r*DD;
    float a = (xr[c0]-g_stats[c0])*g_stats[512+c0]*gamma[c0] + beta[c0];
    float b = (xr[c1]-g_stats[c1])*g_stats[512+c1]*gamma[c1] + beta[c1];
    g_xn[(size_t)r*DD+c0] = a; g_xn[(size_t)r*DD+c1] = b;
    g_h [(size_t)r*DD+c0] = a; g_h [(size_t)r*DD+c1] = b;
    float s = a*a + b*b;
    #pragma unroll
    for (int o=16;o;o>>=1) s += __shfl_xor_sync(~0u, s, o);
    if ((t&31)==0) red[t>>5]=s;
    __syncthreads();
    float tot = 0;
    #pragma unroll
    for (int i=0;i<8;i++) tot += red[i];
    float rs = rsqrtf(tot*(1.0f/DD) + EPS_RMS);
    float y0 = a*rs*w[c0], y1 = b*rs*w[c1];
    g_yh[(size_t)r*DD+c0] = __float2half(y0);
    g_yh[(size_t)r*DD+c1] = __float2half(y1);
    ys[c0] = y0; ys[c1] = y1;
    __syncthreads();
    gates_tail(ys, r, Wi, bi, Wf, bf, t>>5, t&31);
}

// rmsnorm -> fp16 y, optional fused gates (Wi!=null)
__global__ void rmsnorm_h_kernel(const float* __restrict__ x, const float* __restrict__ w,
                                 __half* __restrict__ y,
                                 const float* __restrict__ Wi, const float* __restrict__ bi,
                                 const float* __restrict__ Wf, const float* __restrict__ bf){
    __shared__ float red[8];
    __shared__ float ys[512];
    int r = blockIdx.x, t = threadIdx.x;
    const float* xr = x + (size_t)r*DD;
    float a = xr[t], b = xr[t+256];
    float s = a*a + b*b;
    #pragma unroll
    for (int o=16;o;o>>=1) s += __shfl_xor_sync(~0u, s, o);
    if ((t&31)==0) red[t>>5]=s;
    __syncthreads();
    float tot = 0;
    #pragma unroll
    for (int i=0;i<8;i++) tot += red[i];
    float rs = rsqrtf(tot*(1.0f/DD) + EPS_RMS);
    float y0 = a*rs*w[t], y1 = b*rs*w[t+256];
    __half* yr = y + (size_t)r*DD;
    yr[t]     = __float2half(y0);
    yr[t+256] = __float2half(y1);
    if (Wi){
        ys[t] = y0; ys[t+256] = y1;
        __syncthreads();
        gates_tail(ys, r, Wi, bi, Wf, bf, t>>5, t&31);
    }
}
__global__ void rmsnorm_f_kernel(const float* __restrict__ x, const float* __restrict__ w,
                                 float* __restrict__ y, long xs){
    __shared__ float red[8];
    int r = blockIdx.x, t = threadIdx.x;
    const float* xr = x + (size_t)r*xs;
    float a = xr[t], b = xr[t+256];
    float s = a*a + b*b;
    #pragma unroll
    for (int o=16;o;o>>=1) s += __shfl_xor_sync(~0u, s, o);
    if ((t&31)==0) red[t>>5]=s;
    __syncthreads();
    float tot = 0;
    #pragma unroll
    for (int i=0;i<8;i++) tot += red[i];
    float rs = rsqrtf(tot*(1.0f/DD) + EPS_RMS);
    float* yr = y + (size_t)r*DD;
    yr[t]     = a*rs*w[t];
    yr[t+256] = b*rs*w[t+256];
}

// ---------------- fp16 tensor-core GEMM, BM=64 x BN=128 ----------------
#define AP 40
#define BP 136
#define AS_SZ (64*AP)    // 2560 halves
#define BS_SZ (32*BP)    // 4352 halves
#define NSTG 3
#define HG_SMEM (NSTG*(AS_SZ+BS_SZ)*2)   // 41472 B
#define GU_SMEM (NSTG*(AS_SZ+2*BS_SZ)*2) // 67584 B

#define GEMM_PRE()                                                             \
    const int tid = threadIdx.x;                                               \
    const int lane = tid & 31;                                                 \
    const int wid = tid >> 5;                                                  \
    const int g = lane >> 2, t = lane & 3;                                     \
    const int mw = (wid >> 1) * 32;                                            \
    const int nw = (wid & 1) * 64;                                             \
    const int lrow = (lane & 7) + ((lane >> 3) & 1) * 8;                       \
    const int lcol = ((lane >> 3) & 2) * 4;

#define LOAD_A(kt, buf) do {                                                   \
    __half* Ad = As + (buf)*AS_SZ;                                             \
    _Pragma("unroll")                                                          \
    for (int ii=0; ii<2; ii++){                                                \
        int idx = tid + ii*128;                                                \
        int m = idx >> 2, c = idx & 3;                                         \
        cp16(Ad + m*AP + c*8, Ab + (size_t)m*K + (kt)*32 + c*8);               \
    }                                                                          \
} while(0)

#define LOAD_B(kt, buf, Bsb, Bb, N) do {                                       \
    __half* Bd = (Bsb) + (buf)*BS_SZ;                                          \
    _Pragma("unroll")                                                          \
    for (int ii=0; ii<4; ii++){                                                \
        int idx = tid + ii*128;                                                \
        int kr = idx >> 4, c = idx & 15;                                       \
        cp16(Bd + kr*BP + c*8, (Bb) + (size_t)((kt)*32+kr)*(N) + c*8);         \
    }                                                                          \
} while(0)

#define COMPUTE_TILE(buf, accA, smAbase, smBbase)                              \
    {                                                                          \
        unsigned baseA = (smAbase) + (buf)*AS_SZ*2;                            \
        unsigned baseB = (smBbase) + (buf)*BS_SZ*2;                            \
        _Pragma("unroll")                                                      \
        for (int ks=0; ks<2; ks++){                                            \
            int k0 = ks*16;                                                    \
            unsigned af[2][4], bf[4][4];                                       \
            _Pragma("unroll")                                                  \
            for (int i=0;i<2;i++){                                             \
                int m0 = mw + i*16;                                            \
                ldsm4(af[i][0], af[i][1], af[i][2], af[i][3],                  \
                      baseA + ((unsigned)(m0 + lrow)*AP + (k0 + lcol))*2);     \
            }                                                                  \
            _Pragma("unroll")                                                  \
            for (int j2=0;j2<4;j2++){                                          \
                int n0 = nw + j2*16;                                           \
                ldsm4t(bf[j2][0], bf[j2][1], bf[j2][2], bf[j2][3],             \
                       baseB + ((unsigned)(k0 + lrow)*BP + (n0 + lcol))*2);    \
            }                                                                  \
            _Pragma("unroll")                                                  \
            for (int i=0;i<2;i++){                                             \
                _Pragma("unroll")                                              \
                for (int j=0;j<8;j++){                                         \
                    unsigned b2[2];                                            \
                    b2[0] = bf[j>>1][(j&1)*2+0];                               \
                    b2[1] = bf[j>>1][(j&1)*2+1];                               \
                    mma_f16(accA[i][j], af[i], b2);                            \
                }                                                              \
            }                                                                  \
        }                                                                      \
    }

// merged projection GEMM: x-tile 0-1:q, 2-3:k, 4-7:v, 8-11:og (sigmoid fp16)
__global__ __launch_bounds__(128) void proj_gemm_kernel(
        const __half* __restrict__ A,
        const __half* __restrict__ Wq_h, const __half* __restrict__ Wk_h,
        const __half* __restrict__ Wv_h, const __half* __restrict__ Wog_h){
    extern __shared__ __half sm[];
    __half* As = sm;
    __half* Bs = sm + NSTG*AS_SZ;
    const int K = DD;
    int xt = blockIdx.x;
    const __half* Bsrc; __half* CH; int NC, xl, epi;
    if (xt < 2)      { Bsrc = Wq_h;  CH = g_qh;  NC = QKD; xl = xt;   epi = 0; }
    else if (xt < 4) { Bsrc = Wk_h;  CH = g_kh;  NC = QKD; xl = xt-2; epi = 0; }
    else if (xt < 8) { Bsrc = Wv_h;  CH = g_vh;  NC = VV;  xl = xt-4; epi = 0; }
    else             { Bsrc = Wog_h; CH = g_ogh; NC = VV;  xl = xt-8; epi = 2; }
    GEMM_PRE();
    const __half* Ab = A + (size_t)blockIdx.y * 64 * K;
    const __half* Bb = Bsrc + (size_t)xl * 128;
    const unsigned smA = (unsigned)__cvta_generic_to_shared(As);
    const unsigned smB = (unsigned)__cvta_generic_to_shared(Bs);

    float acc[2][8][4];
    #pragma unroll
    for (int i=0;i<2;i++)
        #pragma unroll
        for (int j=0;j<8;j++)
            #pragma unroll
            for (int c=0;c<4;c++) acc[i][j][c]=0.f;

    const int KT = K/32;
    LOAD_A(0,0); LOAD_B(0,0,Bs,Bb,NC); cp_commit();
    LOAD_A(1,1); LOAD_B(1,1,Bs,Bb,NC); cp_commit();
    for (int kt=0; kt<KT; kt++){
        if (kt+1 < KT) cp_wait<1>(); else cp_wait<0>();
        __syncthreads();
        if (kt+2 < KT){
            int nb = (kt+2)%NSTG;
            LOAD_A(kt+2, nb); LOAD_B(kt+2, nb, Bs, Bb, NC); cp_commit();
        }
        COMPUTE_TILE(kt%NSTG, acc, smA, smB);
        __syncthreads();
    }
    #pragma unroll
    for (int i=0;i<2;i++){
        #pragma unroll
        for (int j=0;j<8;j++){
            size_t row = (size_t)blockIdx.y*64 + mw + i*16 + g;
            size_t col = (size_t)xl*128 + nw + j*8 + t*2;
            #pragma unroll
            for (int h2=0; h2<2; h2++){
                size_t rr = row + h2*8;
                float v0 = acc[i][j][h2*2+0];
                float v1 = acc[i][j][h2*2+1];
                if (epi==2){
                    v0 = 1.0f/(1.0f+expf(-v0));
                    v1 = 1.0f/(1.0f+expf(-v1));
                }
                *reinterpret_cast<__half2*>(CH + rr*NC + col) = __floats2half2_rn(v0, v1);
            }
        }
    }
}

// generic GEMM: EPI 0 store fp32, 1 C+=
template<int EPI>
__global__ __launch_bounds__(128) void hgemm64_kernel(
        const __half* __restrict__ A,
        const __half* __restrict__ B, float* __restrict__ C,
        int N, int K){
    extern __shared__ __half sm[];
    __half* As = sm;
    __half* Bs = sm + NSTG*AS_SZ;
    GEMM_PRE();
    const __half* Ab = A + (size_t)blockIdx.y * 64 * K;
    const __half* Bb = B + (size_t)blockIdx.x * 128;
    const unsigned smA = (unsigned)__cvta_generic_to_shared(As);
    const unsigned smB = (unsigned)__cvta_generic_to_shared(Bs);

    float acc[2][8][4];
    #pragma unroll
    for (int i=0;i<2;i++)
        #pragma unroll
        for (int j=0;j<8;j++)
            #pragma unroll
            for (int c=0;c<4;c++) acc[i][j][c]=0.f;

    const int KT = K/32;
    LOAD_A(0,0); LOAD_B(0,0,Bs,Bb,N); cp_commit();
    LOAD_A(1,1); LOAD_B(1,1,Bs,Bb,N); cp_commit();
    for (int kt=0; kt<KT; kt++){
        if (kt+1 < KT) cp_wait<1>(); else cp_wait<0>();
        __syncthreads();
        if (kt+2 < KT){
            int nb = (kt+2)%NSTG;
            LOAD_A(kt+2, nb); LOAD_B(kt+2, nb, Bs, Bb, N); cp_commit();
        }
        COMPUTE_TILE(kt%NSTG, acc, smA, smB);
        __syncthreads();
    }
    #pragma unroll
    for (int i=0;i<2;i++){
        #pragma unroll
        for (int j=0;j<8;j++){
            size_t row = (size_t)blockIdx.y*64 + mw + i*16 + g;
            size_t col = (size_t)blockIdx.x*128 + nw + j*8 + t*2;
            #pragma unroll
            for (int h2=0; h2<2; h2++){
                size_t rr = row + h2*8;
                float v0 = acc[i][j][h2*2+0];
                float v1 = acc[i][j][h2*2+1];
                float* p = C + rr*N + col;
                if (EPI==0){ p[0]=v0; p[1]=v1; }
                else { p[0]+=v0; p[1]+=v1; }
            }
        }
    }
}

// fused G+U GEMM: out = silu(y@Wg) * (y@Wu), fp16 out
__global__ __launch_bounds__(128) void hgemm_gu_kernel(
        const __half* __restrict__ A,
        const __half* __restrict__ Bg, const __half* __restrict__ Bu,
        __half* __restrict__ CH, int N, int K){
    extern __shared__ __half sm[];
    __half* As  = sm;
    __half* Bgs = sm + NSTG*AS_SZ;
    __half* Bus = Bgs + NSTG*BS_SZ;
    GEMM_PRE();
    const __half* Ab  = A + (size_t)blockIdx.y * 64 * K;
    const __half* Bgb = Bg + (size_t)blockIdx.x * 128;
    const __half* Bub = Bu + (size_t)blockIdx.x * 128;
    const unsigned smA = (unsigned)__cvta_generic_to_shared(As);
    const unsigned smG = (unsigned)__cvta_generic_to_shared(Bgs);
    const unsigned smU = (unsigned)__cvta_generic_to_shared(Bus);

    float accg[2][8][4], accu[2][8][4];
    #pragma unroll
    for (int i=0;i<2;i++)
        #pragma unroll
        for (int j=0;j<8;j++)
            #pragma unroll
            for (int c=0;c<4;c++){ accg[i][j][c]=0.f; accu[i][j][c]=0.f; }

    const int KT = K/32;
    LOAD_A(0,0); LOAD_B(0,0,Bgs,Bgb,N); LOAD_B(0,0,Bus,Bub,N); cp_commit();
    LOAD_A(1,1); LOAD_B(1,1,Bgs,Bgb,N); LOAD_B(1,1,Bus,Bub,N); cp_commit();
    for (int kt=0; kt<KT; kt++){
        if (kt+1 < KT) cp_wait<1>(); else cp_wait<0>();
        __syncthreads();
        if (kt+2 < KT){
            int nb = (kt+2)%NSTG;
            LOAD_A(kt+2, nb);
            LOAD_B(kt+2, nb, Bgs, Bgb, N);
            LOAD_B(kt+2, nb, Bus, Bub, N);
            cp_commit();
        }
        COMPUTE_TILE(kt%NSTG, accg, smA, smG);
        COMPUTE_TILE(kt%NSTG, accu, smA, smU);
        __syncthreads();
    }
    #pragma unroll
    for (int i=0;i<2;i++){
        #pragma unroll
        for (int j=0;j<8;j++){
            size_t row = (size_t)blockIdx.y*64 + mw + i*16 + g;
            size_t col = (size_t)blockIdx.x*128 + nw + j*8 + t*2;
            #pragma unroll
            for (int h2=0; h2<2; h2++){
                size_t rr = row + h2*8;
                float g0 = accg[i][j][h2*2+0], g1v = accg[i][j][h2*2+1];
                float u0 = accu[i][j][h2*2+0], u1 = accu[i][j][h2*2+1];
                __half* q = CH + rr*N + col;
                q[0] = __float2half(g0*(1.0f/(1.0f+expf(-g0)))*u0);
                q[1] = __float2half(g1v*(1.0f/(1.0f+expf(-g1v)))*u1);
            }
        }
    }
}

// ---------------- per-(b,h) prefix scan (warp-parallel) ----------------
__global__ void scan_kernel(){
    int bh = blockIdx.x;
    int lane = threadIdx.x;
    const float* ig = g_ig + bh*SS;
    const float* fg = g_fg + bh*SS;
    float bcv[16];
    float carry = 0.f;
    #pragma unroll
    for (int c=0;c<16;c++){
        int s = c*32 + lane;
        float lf = logsigf(fg[s]);
        #pragma unroll
        for (int o=1;o<32;o<<=1){
            float n = __shfl_up_sync(~0u, lf, o);
            if (lane >= o) lf += n;
        }
        float bc = carry + lf;
        bcv[c] = bc;
        g_bc[bh*SS+s] = bc;
        carry = __shfl_sync(~0u, bc, 31);
    }
    float carrym = -1e30f;
    #pragma unroll
    for (int c=0;c<16;c++){
        int s = c*32 + lane;
        float cv = ig[s] - bcv[c];
        #pragma unroll
        for (int o=1;o<32;o<<=1){
            float n = __shfl_up_sync(~0u, cv, o);
            if (lane >= o) cv = fmaxf(cv, n);
        }
        float cm = fmaxf(carrym, cv);
        g_mv[bh*SS+s] = bcv[c] + cm;
        carrym = __shfl_sync(~0u, cm, 31);
    }
}

// ---------------- tensor-core mLSTM attention + fused headnorm ----------------
#define QKP 40
#define VVP 72
__global__ __launch_bounds__(128) void attn_kernel(const float* __restrict__ mhn){
    __shared__ __half Qs[64*QKP];
    __shared__ __half Ks[2][64*QKP];
    __shared__ __half Vs[2][64*VVP];
    __shared__ float bs_s[2][64], ig_s[2][64];
    int bh = blockIdx.y; int b = bh >> 3; int h = bh & 7;
    int tt = gridDim.x - 1 - blockIdx.x;   // heavy tiles first
    int tid = threadIdx.x, lane = tid & 31, wid = tid >> 5;
    int g = lane >> 2, t = lane & 3;
    int mw = wid * 16;
    const int lrow = (lane & 7) + ((lane >> 3) & 1) * 8;
    const int lcol = ((lane >> 3) & 2) * 4;
    const unsigned sQ = (unsigned)__cvta_generic_to_shared(Qs);
    const unsigned sK = (unsigned)__cvta_generic_to_shared(Ks);
    const unsigned sV = (unsigned)__cvta_generic_to_shared(Vs);
    const float scale = 0.17677669529663687f;  // 1/sqrt(32)

    #define LOADKV(st, buf) do {                                               \
        int s0_ = (st)*64;                                                     \
        _Pragma("unroll")                                                      \
        for (int ii=0; ii<2; ii++){                                            \
            int idx = tid + ii*128;                                            \
            int r = idx >> 2, c = (idx & 3) * 8;                               \
            cp16(Ks[buf] + r*QKP + c,                                          \
                 g_kh + ((size_t)(b*SS) + s0_ + r)*QKD + h*DQK + c);           \
        }                                                                      \
        _Pragma("unroll")                                                      \
        for (int ii=0; ii<4; ii++){                                            \
            int idx = tid + ii*128;                                            \
            int r = idx >> 3, c = (idx & 7) * 8;                               \
            cp16(Vs[buf] + r*VVP + c,                                          \
                 g_vh + ((size_t)(b*SS) + s0_ + r)*VV + h*DV + c);             \
        }                                                                      \
        if (tid < 64){                                                         \
            bs_s[buf][tid] = g_bc[bh*SS + s0_ + tid];                          \
            ig_s[buf][tid] = g_ig[bh*SS + s0_ + tid];                          \
        }                                                                      \
    } while(0)

    #pragma unroll
    for (int ii=0; ii<2; ii++){
        int idx = tid + ii*128;
        int r = idx >> 2, c = (idx & 3) * 8;
        cp16(Qs + r*QKP + c, g_qh + ((size_t)(b*SS) + tt*64 + r)*QKD + h*DQK + c);
    }
    LOADKV(0, 0);
    cp_commit();
    if (tt >= 1){ LOADKV(1, 1); cp_commit(); }

    int r0 = tt*64 + mw + g, r1 = r0 + 8;
    float bt0 = g_bc[bh*SS + r0], bt1 = g_bc[bh*SS + r1];
    float mt0 = g_mv[bh*SS + r0], mt1 = g_mv[bh*SS + r1];

    float co[8][4];
    #pragma unroll
    for (int j=0;j<8;j++)
        #pragma unroll
        for (int c=0;c<4;c++) co[j][c]=0.f;
    float ssum0 = 0.f, ssum1 = 0.f;

    if (tt >= 1) cp_wait<1>(); else cp_wait<0>();
    __syncthreads();
    unsigned aq[2][4];
    #pragma unroll
    for (int ks=0; ks<2; ks++)
        ldsm4(aq[ks][0], aq[ks][1], aq[ks][2], aq[ks][3],
              sQ + ((unsigned)(mw + lrow)*QKP + ks*16 + lcol)*2);

    for (int st=0; st<=tt; st++){
        int s0 = st*64;
        int buf = st & 1;
        unsigned kbase = sK + (unsigned)buf*64*QKP*2;
        unsigned vbase = sV + (unsigned)buf*64*VVP*2;

        float cs[8][4];
        #pragma unroll
        for (int j=0;j<8;j++)
            #pragma unroll
            for (int c=0;c<4;c++) cs[j][c]=0.f;
        #pragma unroll
        for (int ks=0; ks<2; ks++){
            unsigned bk[4][4];
            #pragma unroll
            for (int j2=0;j2<4;j2++)
                ldsm4(bk[j2][0], bk[j2][1], bk[j2][2], bk[j2][3],
                      kbase + ((unsigned)(j2*16 + lrow)*QKP + ks*16 + lcol)*2);
            #pragma unroll
            for (int j=0;j<8;j++){
                unsigned b2[2];
                b2[0] = bk[j>>1][(j&1)];
                b2[1] = bk[j>>1][(j&1)+2];
                mma_f16(cs[j], aq[ks], b2);
            }
        }
        bool full = (st < tt);
        #pragma unroll
        for (int j=0;j<8;j++){
            int c0 = j*8 + 2*t, c1 = c0 + 1;
            float a0 = bs_s[buf][c0] - ig_s[buf][c0];
            float a1 = bs_s[buf][c1] - ig_s[buf][c1];
            float e00 = (full || (s0+c0 <= r0)) ? __expf(bt0 - a0 - mt0) : 0.f;
            float e10 = (full || (s0+c1 <= r0)) ? __expf(bt0 - a1 - mt0) : 0.f;
            float e01 = (full || (s0+c0 <= r1)) ? __expf(bt1 - a0 - mt1) : 0.f;
            float e11 = (full || (s0+c1 <= r1)) ? __expf(bt1 - a1 - mt1) : 0.f;
            cs[j][0] = cs[j][0]*scale*e00;  ssum0 += cs[j][0];
            cs[j][1] = cs[j][1]*scale*e10;  ssum0 += cs[j][1];
            cs[j][2] = cs[j][2]*scale*e01;  ssum1 += cs[j][2];
            cs[j][3] = cs[j][3]*scale*e11;  ssum1 += cs[j][3];
        }
        #pragma unroll
        for (int kk=0; kk<4; kk++){
            unsigned ap[4];
            ap[0] = f22h(cs[2*kk][0],   cs[2*kk][1]);
            ap[1] = f22h(cs[2*kk][2],   cs[2*kk][3]);
            ap[2] = f22h(cs[2*kk+1][0], cs[2*kk+1][1]);
            ap[3] = f22h(cs[2*kk+1][2], cs[2*kk+1][3]);
            unsigned bv[4][4];
            #pragma unroll
            for (int j2=0;j2<4;j2++)
                ldsm4t(bv[j2][0], bv[j2][1], bv[j2][2], bv[j2][3],
                       vbase + ((unsigned)(kk*16 + lrow)*VVP + j2*16 + lcol)*2);
            #pragma unroll
            for (int j=0;j<8;j++){
                unsigned b2[2];
                b2[0] = bv[j>>1][(j&1)*2+0];
                b2[1] = bv[j>>1][(j&1)*2+1];
                mma_f16(co[j], ap, b2);
            }
        }
        __syncthreads();
        if (st+2 <= tt){ LOADKV(st+2, buf); cp_commit(); }
        if (st+1 <= tt){
            if (st+2 <= tt) cp_wait<1>(); else cp_wait<0>();
            __syncthreads();
        }
    }
    #undef LOADKV

    ssum0 += __shfl_xor_sync(~0u, ssum0, 1); ssum0 += __shfl_xor_sync(~0u, ssum0, 2);
    ssum1 += __shfl_xor_sync(~0u, ssum1, 1); ssum1 += __shfl_xor_sync(~0u, ssum1, 2);
    float inv0 = 1.0f/(fmaxf(fabsf(ssum0), __expf(-mt0)) + EPS_RMS);
    float inv1 = 1.0f/(fmaxf(fabsf(ssum1), __expf(-mt1)) + EPS_RMS);

    float mu0=0.f, mu1=0.f;
    #pragma unroll
    for (int j=0;j<8;j++){ mu0 += co[j][0]+co[j][1]; mu1 += co[j][2]+co[j][3]; }
    mu0 += __shfl_xor_sync(~0u, mu0, 1); mu0 += __shfl_xor_sync(~0u, mu0, 2);
    mu1 += __shfl_xor_sync(~0u, mu1, 1); mu1 += __shfl_xor_sync(~0u, mu1, 2);
    mu0 *= inv0 * (1.0f/DV);
    mu1 *= inv1 * (1.0f/DV);
    float var0=0.f, var1=0.f;
    #pragma unroll
    for (int j=0;j<8;j++){
        float d0 = co[j][0]*inv0 - mu0, d1 = co[j][1]*inv0 - mu0;
        float d2 = co[j][2]*inv1 - mu1, d3 = co[j][3]*inv1 - mu1;
        var0 += d0*d0 + d1*d1; var1 += d2*d2 + d3*d3;
    }
    var0 += __shfl_xor_sync(~0u, var0, 1); var0 += __shfl_xor_sync(~0u, var0, 2);
    var1 += __shfl_xor_sync(~0u, var1, 1); var1 += __shfl_xor_sync(~0u, var1, 2);
    float rs0 = rsqrtf(var0*(1.0f/DV) + EPS_RMS);
    float rs1 = rsqrtf(var1*(1.0f/DV) + EPS_RMS);

    size_t rg0 = (size_t)(b*SS) + r0;
    size_t rg1 = (size_t)(b*SS) + r1;
    #pragma unroll
    for (int j=0;j<8;j++){
        int colh = h*DV + j*8 + 2*t;
        float2 w2 = *reinterpret_cast<const float2*>(mhn + colh);
        __half2 og0h = *reinterpret_cast<const __half2*>(g_ogh + rg0*VV + colh);
        __half2 og1h = *reinterpret_cast<const __half2*>(g_ogh + rg1*VV + colh);
        float2 og0 = __half22float2(og0h);
        float2 og1 = __half22float2(og1h);
        float o00 = (co[j][0]*inv0 - mu0)*rs0*w2.x*og0.x;
        float o01 = (co[j][1]*inv0 - mu0)*rs0*w2.y*og0.y;
        float o10 = (co[j][2]*inv1 - mu1)*rs1*w2.x*og1.x;
        float o11 = (co[j][3]*inv1 - mu1)*rs1*w2.y*og1.y;
        *reinterpret_cast<__half2*>(g_hth + rg0*VV + colh) = __floats2half2_rn(o00, o01);
        *reinterpret_cast<__half2*>(g_hth + rg1*VV + colh) = __floats2half2_rn(o10, o11);
    }
}

// ---------------- final heads ----------------
__global__ void bn1_kernel(const float* __restrict__ gamma, const float* __restrict__ beta){
    int c = threadIdx.x;
    float v[16]; float mu=0.f;
    #pragma unroll
    for (int b=0;b<16;b++){ v[b]=g_last[b*DD+c]; mu+=v[b]; }
    mu *= (1.0f/16.0f);
    float var=0.f;
    #pragma unroll
    for (int b=0;b<16;b++){ float d=v[b]-mu; var+=d*d; }
    var *= (1.0f/16.0f);
    float rs = rsqrtf(var + EPS_BN);
    #pragma unroll
    for (int b=0;b<16;b++) g_last[b*DD+c] = (v[b]-mu)*rs*gamma[c] + beta[c];
}
__global__ void fc1_kernel(const float* __restrict__ W, const float* __restrict__ bias){
    __shared__ float xr[512];
    int b = blockIdx.x; int j = threadIdx.x;
    xr[j]     = g_last[b*DD + j];
    xr[j+256] = g_last[b*DD + j + 256];
    __syncthreads();
    float s=0.f;
    #pragma unroll 8
    for (int k=0;k<512;k++) s += xr[k]*W[k*256+j];
    g_o1[b*256+j] = s + bias[j];
}
__global__ void bn2gelu_kernel(const float* __restrict__ gamma, const float* __restrict__ beta){
    int j = threadIdx.x;
    float v[16]; float mu=0.f;
    #pragma unroll
    for (int b=0;b<16;b++){ v[b]=g_o1[b*256+j]; mu+=v[b]; }
    mu *= (1.0f/16.0f);
    float var=0.f;
    #pragma unroll
    for (int b=0;b<16;b++){ float d=v[b]-mu; var+=d*d; }
    var *= (1.0f/16.0f);
    float rs = rsqrtf(var + EPS_BN);
    #pragma unroll
    for (int b=0;b<16;b++){
        float t = (v[b]-mu)*rs*gamma[j] + beta[j];
        g_o1[b*256+j] = 0.5f*t*(1.0f + erff(t*0.7071067811865475f));
    }
}
__global__ void fc2_kernel(const float* __restrict__ W, const float* __restrict__ bias){
    __shared__ float red[256];
    int b = blockIdx.x; int j = threadIdx.x;
    red[j] = g_o1[b*256+j]*W[j];
    __syncthreads();
    for (int o=128;o;o>>=1){ if(j<o) red[j]+=red[j+o]; __syncthreads(); }
    if (j==0) g_o2[b] = red[0] + bias[0];
}
__global__ void res_out_kernel(const float* __restrict__ resW, const float* __restrict__ resb,
                               float* __restrict__ out){
    int warp = (blockIdx.x*blockDim.x + threadIdx.x) >> 5;
    int lane = threadIdx.x & 31;
    if (warp >= RR) return;
    const float* xr = g_xn + (size_t)warp*DD;
    float s=0.f;
    for (int d=lane; d<DD; d+=32) s += xr[d]*resW[d];
    #pragma unroll
    for (int o=16;o;o>>=1) s += __shfl_xor_sync(~0u,s,o);
    if (lane==0){
        float v = s + resb[0] + g_o2[warp>>9];
        out[warp] = fmaxf(v, 0.f);
    }
}

// ---------------- host driver ----------------
extern "C" void kernel_launch(void* const* d_in, const int* in_sizes, int n_in,
                              void* d_out, int out_size){
    const float* x        = (const float*)d_in[0];
    const float* bng      = (const float*)d_in[1];
    const float* bnb      = (const float*)d_in[2];
    const float* norm1_w  = (const float*)d_in[3];
    const float* norm2_w  = (const float*)d_in[4];
    const float* Wq       = (const float*)d_in[5];
    const float* Wk       = (const float*)d_in[6];
    const float* Wv       = (const float*)d_in[7];
    const float* Wog      = (const float*)d_in[8];
    const float* Wi       = (const float*)d_in[9];
    const float* bi       = (const float*)d_in[10];
    const float* Wf       = (const float*)d_in[11];
    const float* bf       = (const float*)d_in[12];
    const float* mhn_w    = (const float*)d_in[13];
    const float* Wout     = (const float*)d_in[14];
    const float* Wg       = (const float*)d_in[15];
    const float* Wu       = (const float*)d_in[16];
    const float* Wd       = (const float*)d_in[17];
    const float* fnorm_w  = (const float*)d_in[18];
    const float* bn1_g    = (const float*)d_in[19];
    const float* bn1_b    = (const float*)d_in[20];
    const float* fc1_W    = (const float*)d_in[21];
    const float* fc1_b    = (const float*)d_in[22];
    const float* bn2_g    = (const float*)d_in[23];
    const float* bn2_b    = (const float*)d_in[24];
    const float* fc2_W    = (const float*)d_in[25];
    const float* fc2_b    = (const float*)d_in[26];
    const float* res_W    = (const float*)d_in[27];
    const float* res_b    = (const float*)d_in[28];
    float* out = (float*)d_out;

    float *p_h,*p_last;
    __half *p_wh,*p_yh,*p_hth,*p_g1h;
    cudaGetSymbolAddress((void**)&p_h,  g_h);
    cudaGetSymbolAddress((void**)&p_last, g_last);
    cudaGetSymbolAddress((void**)&p_wh,  g_wh);
    cudaGetSymbolAddress((void**)&p_yh,  g_yh);
    cudaGetSymbolAddress((void**)&p_hth, g_hth);
    cudaGetSymbolAddress((void**)&p_g1h, g_g1h);

    cudaFuncSetAttribute((const void*)proj_gemm_kernel,  cudaFuncAttributeMaxDynamicSharedMemorySize, HG_SMEM);
    cudaFuncSetAttribute((const void*)hgemm64_kernel<1>, cudaFuncAttributeMaxDynamicSharedMemorySize, HG_SMEM);
    cudaFuncSetAttribute((const void*)hgemm_gu_kernel,   cudaFuncAttributeMaxDynamicSharedMemorySize, GU_SMEM);

    bnpart_conv_kernel<<<64 + (int)((TOTW + 1023)/1024), 256>>>(x, Wq, Wk, Wv, Wog, Wout, Wg, Wu, Wd);
    bn_final_kernel<<<1,512>>>();
    bnapply_rms_kernel<<<RR,256>>>(x, bng, bnb, norm1_w,
                                   Wi, bi, Wf, bf);   // layer-0 gates fused

    for (int l=0;l<LL;l++){
        const __half* Wq_h  = p_wh + OFF_WQ  + (size_t)l*DD*QKD;
        const __half* Wk_h  = p_wh + OFF_WK  + (size_t)l*DD*QKD;
        const __half* Wv_h  = p_wh + OFF_WV  + (size_t)l*DD*VV;
        const __half* Wog_h = p_wh + OFF_WOG + (size_t)l*DD*VV;
        const __half* Wout_h= p_wh + OFF_WOUT+ (size_t)l*VV*DD;
        const __half* Wg_h  = p_wh + OFF_WG  + (size_t)l*DD*FF;
        const __half* Wu_h  = p_wh + OFF_WU  + (size_t)l*DD*FF;
        const __half* Wd_h  = p_wh + OFF_WD  + (size_t)l*FF*DD;
        const float* Wi_l = Wi + (size_t)l*DD*HH;
        const float* Wf_l = Wf + (size_t)l*DD*HH;

        if (l > 0)
            rmsnorm_h_kernel<<<RR,256>>>(p_h, norm1_w + l*DD, p_yh,
                                         Wi_l, bi + l*HH, Wf_l, bf + l*HH);

        proj_gemm_kernel<<<dim3(12, RR/64), 128, HG_SMEM>>>(p_yh, Wq_h, Wk_h, Wv_h, Wog_h);
        scan_kernel<<<BB*HH,32>>>();

        attn_kernel<<<dim3(SS/64, BB*HH),128>>>(mhn_w + l*VV);

        hgemm64_kernel<1><<<dim3(DD/128, RR/64), 128, HG_SMEM>>>(p_hth, Wout_h, p_h, DD, VV);

        rmsnorm_h_kernel<<<RR,256>>>(p_h, norm2_w + l*DD, p_yh,
                                     nullptr, nullptr, nullptr, nullptr);
        hgemm_gu_kernel<<<dim3(FF/128, RR/64), 128, GU_SMEM>>>(p_yh, Wg_h, Wu_h, p_g1h, FF, DD);
        hgemm64_kernel<1><<<dim3(DD/128, RR/64), 128, HG_SMEM>>>(p_g1h, Wd_h, p_h, DD, FF);
    }

    rmsnorm_f_kernel<<<BB,256>>>(p_h + (size_t)(SS-1)*DD, fnorm_w, p_last, (long)SS*DD);

    bn1_kernel<<<1,512>>>(bn1_g, bn1_b);
    fc1_kernel<<<BB,256>>>(fc1_W, fc1_b);
    bn2gelu_kernel<<<1,256>>>(bn2_g, bn2_b);
    fc2_kernel<<<BB,256>>>(fc2_W, fc2_b);
    res_out_kernel<<<RR/8,256>>>(res_W, res_b, out);
    (void)in_sizes; (void)n_in; (void)out_size;
}